// round 9
// baseline (speedup 1.0000x reference)
#include <cuda_runtime.h>
#include <cuda_bf16.h>
#include <cuda_fp16.h>
#include <cstdint>
#include <math.h>

#define BATCH   2
#define SEQLEN  4096
#define DMODEL  2048
#define DINNER  4096
#define NHEADS  32
#define HEADDIM 128
#define DSTATE  64
#define NCHUNK  16
#define CHUNKT  256
#define CONVDIM 4224
#define DINPROJ 8352
#define NROWS   (BATCH*SEQLEN)
#define LN_EPS  1e-5f

// ---------------- scratch (device globals; no allocations allowed) ----------------
__device__ float g_zxbcdt[(size_t)NROWS * DINPROJ];
__device__ float g_Bv   [NROWS * DSTATE];
__device__ float g_Cv   [NROWS * DSTATE];
__device__ float g_dt   [NROWS * NHEADS];
__device__ float g_dA   [NROWS * NHEADS];
__device__ float g_Acum [BATCH * NHEADS * SEQLEN];
__device__ float g_G    [(size_t)BATCH * NCHUNK * CHUNKT * CHUNKT];
__device__ float g_states[(size_t)BATCH * NCHUNK * NHEADS * HEADDIM * DSTATE];
__device__ float g_prefix[(size_t)BATCH * NCHUNK * NHEADS * HEADDIM * DSTATE];
__device__ float g_y    [(size_t)NROWS * DINNER];

// fp16 buffers (activations exact hi/lo, weights rounded)
__device__ __half g_uh [(size_t)NROWS * DMODEL];
__device__ __half g_ul [(size_t)NROWS * DMODEL];
__device__ __half g_w1h[(size_t)DINPROJ * DMODEL];
__device__ __half g_ynh[(size_t)NROWS * DINNER];
__device__ __half g_ynl[(size_t)NROWS * DINNER];
__device__ __half g_w2h[(size_t)DMODEL * DINNER];
__device__ __half g_xf16[(size_t)NROWS * DINNER];   // rounded fp16 of xdt

__device__ __forceinline__ float siluf(float x) { return x / (1.f + __expf(-x)); }

__device__ __forceinline__ uint32_t smem_u32(const void* p) {
    uint32_t a;
    asm("{ .reg .u64 t; cvta.to.shared.u64 t, %1; cvt.u32.u64 %0, t; }" : "=r"(a) : "l"(p));
    return a;
}

// pack two floats into fp16x2 hi; return hi, write lo (exact 2-term split)
__device__ __forceinline__ uint32_t pack2h(float a, float b, uint32_t& lo) {
    __half ha = __float2half_rn(a), hb = __float2half_rn(b);
    __half la = __float2half_rn(a - __half2float(ha));
    __half lb = __float2half_rn(b - __half2float(hb));
    lo = (uint32_t)__half_as_ushort(la) | ((uint32_t)__half_as_ushort(lb) << 16);
    return (uint32_t)__half_as_ushort(ha) | ((uint32_t)__half_as_ushort(hb) << 16);
}
__device__ __forceinline__ uint32_t rnd2h(float a, float b) {
    return (uint32_t)__half_as_ushort(__float2half_rn(a)) |
           ((uint32_t)__half_as_ushort(__float2half_rn(b)) << 16);
}

// ================= split kernels =================
__global__ void split_f16(const float* __restrict__ src,
                          __half* __restrict__ hi, __half* __restrict__ lo, long n)
{
    long i = (long)blockIdx.x * blockDim.x + threadIdx.x;
    if (i >= n) return;
    float x = src[i];
    __half h = __float2half_rn(x);
    hi[i] = h;
    lo[i] = __float2half_rn(x - __half2float(h));
}
__global__ void round_f16(const float* __restrict__ src, __half* __restrict__ dst, long n)
{
    long i = (long)blockIdx.x * blockDim.x + threadIdx.x;
    if (i >= n) return;
    dst[i] = __float2half_rn(src[i]);
}

// ================= tensor-core primitives =================
__device__ __forceinline__ void mma16816h(float* c, const uint32_t* a, uint32_t b0, uint32_t b1)
{
    asm volatile(
        "mma.sync.aligned.m16n8k16.row.col.f32.f16.f16.f32 "
        "{%0,%1,%2,%3}, {%4,%5,%6,%7}, {%8,%9}, {%0,%1,%2,%3};"
        : "+f"(c[0]), "+f"(c[1]), "+f"(c[2]), "+f"(c[3])
        : "r"(a[0]), "r"(a[1]), "r"(a[2]), "r"(a[3]), "r"(b0), "r"(b1));
}
#define LDSM_X4(r0, r1, r2, r3, addr) \
    asm volatile("ldmatrix.sync.aligned.m8n8.x4.shared.b16 {%0,%1,%2,%3}, [%4];" \
                 : "=r"(r0), "=r"(r1), "=r"(r2), "=r"(r3) : "r"(addr))
#define LDSM_X4_T(r0, r1, r2, r3, addr) \
    asm volatile("ldmatrix.sync.aligned.m8n8.x4.trans.shared.b16 {%0,%1,%2,%3}, [%4];" \
                 : "=r"(r0), "=r"(r1), "=r"(r2), "=r"(r3) : "r"(addr))
#define CP16(dst, src, sz) \
    asm volatile("cp.async.cg.shared.global [%0], [%1], 16, %2;" \
                 :: "r"(dst), "l"(src), "r"(sz))
#define CP_COMMIT() asm volatile("cp.async.commit_group;" ::: "memory")
#define CP_WAIT1()  asm volatile("cp.async.wait_group 1;" ::: "memory")
#define CP_WAIT0()  asm volatile("cp.async.wait_group 0;" ::: "memory")

// ================= fp16 2-MMA GEMM: C = (Ah+Al)*Bh^T + bias =================
// BM=128, BN=128, BK=64, 256 threads (8 warps, 32x64 warp tiles), 2-stage
// cp.async pipeline, 48KB/stage -> 96KB/CTA -> 2 CTAs per SM.
#define GST 49152
__global__ void __launch_bounds__(256, 2)
mma_gemm_nt(const __half* __restrict__ Ah, const __half* __restrict__ Al,
            const __half* __restrict__ Bh,
            const float* __restrict__ bias, float* __restrict__ C, int N, int K)
{
    extern __shared__ char smem[];
    const uint32_t sb = smem_u32(smem);
    const int tid = threadIdx.x, lane = tid & 31, wid = tid >> 5;
    const int wr = wid >> 1, wc = wid & 1;        // 4x2 warps, each 32(m) x 64(n)
    const int mbase = blockIdx.y * 128;
    const int nbase = blockIdx.x * 128;

    // loaders: 2 thr/row, 4 x 16B units each (tile 128 rows x 128B)
    const int r = tid >> 1, u0 = (tid & 1) * 4;
    const bool bval = (nbase + r) < N;
    const uint32_t bsz = bval ? 16u : 0u;
    const __half* gAh = Ah + (size_t)(mbase + r) * K + u0 * 8;
    const __half* gAl = Al + (size_t)(mbase + r) * K + u0 * 8;
    const __half* gBh = Bh + (size_t)(bval ? nbase + r : 0) * K + u0 * 8;
    uint32_t dst[4];
#pragma unroll
    for (int j = 0; j < 4; j++) dst[j] = r * 128 + (((u0 + j) ^ (r & 7)) * 16);

    auto issue = [&](int st, int kt) {
        uint32_t s0 = sb + st * GST;
#pragma unroll
        for (int j = 0; j < 4; j++) {
            CP16(s0 + dst[j],         gAh + kt + j * 8, 16);
            CP16(s0 + 16384 + dst[j], gAl + kt + j * 8, 16);
            CP16(s0 + 32768 + dst[j], gBh + kt + j * 8, bsz);
        }
        CP_COMMIT();
    };

    float acc[2][8][4];
#pragma unroll
    for (int mt = 0; mt < 2; mt++)
#pragma unroll
        for (int nt = 0; nt < 8; nt++)
#pragma unroll
            for (int i = 0; i < 4; i++) acc[mt][nt][i] = 0.f;

    const int nk = K >> 6;
    issue(0, 0);
    issue(1, 64);

    const int g = lane >> 3, li = lane & 7;
    const int arow_lo = (g & 1) * 8 + li;
    const int ahalf   = g >> 1;
    const int brow_lo = (g >> 1) * 8 + li;
    const int bhalf   = g & 1;

    int stage = 0;
    for (int c = 0; c < nk; c++) {
        if (c + 1 < nk) CP_WAIT1(); else CP_WAIT0();
        __syncthreads();
        const uint32_t s0 = sb + stage * GST;
#pragma unroll
        for (int s = 0; s < 4; s++) {
            uint32_t afh[2][4], afl[2][4];
#pragma unroll
            for (int mt = 0; mt < 2; mt++) {
                int row = wr * 32 + mt * 16 + arow_lo;
                uint32_t off = row * 128 + (((2 * s + ahalf) ^ (row & 7)) * 16);
                LDSM_X4(afh[mt][0], afh[mt][1], afh[mt][2], afh[mt][3], s0 + off);
                LDSM_X4(afl[mt][0], afl[mt][1], afl[mt][2], afl[mt][3], s0 + 16384 + off);
            }
#pragma unroll
            for (int ntp = 0; ntp < 4; ntp++) {
                int row = wc * 64 + ntp * 16 + brow_lo;
                uint32_t off = row * 128 + (((2 * s + bhalf) ^ (row & 7)) * 16);
                uint32_t b0, b1, b2, b3;
                LDSM_X4(b0, b1, b2, b3, s0 + 32768 + off);
#pragma unroll
                for (int mt = 0; mt < 2; mt++) {
                    mma16816h(acc[mt][2*ntp+0], afh[mt], b0, b1);
                    mma16816h(acc[mt][2*ntp+0], afl[mt], b0, b1);
                    mma16816h(acc[mt][2*ntp+1], afh[mt], b2, b3);
                    mma16816h(acc[mt][2*ntp+1], afl[mt], b2, b3);
                }
            }
        }
        __syncthreads();
        if (c + 2 < nk) issue(stage, (c + 2) * 64);
        stage ^= 1;
    }

#pragma unroll
    for (int mt = 0; mt < 2; mt++) {
        int r0 = mbase + wr * 32 + mt * 16 + (lane >> 2);
#pragma unroll
        for (int nt = 0; nt < 8; nt++) {
            int col = nbase + wc * 64 + nt * 8 + (lane & 3) * 2;
            if (col < N) {
                float b0 = bias ? bias[col] : 0.f;
                float b1 = bias ? bias[col + 1] : 0.f;
                float2 v0 = make_float2(acc[mt][nt][0] + b0, acc[mt][nt][1] + b1);
                float2 v1 = make_float2(acc[mt][nt][2] + b0, acc[mt][nt][3] + b1);
                *(float2*)(C + (size_t)r0 * N + col)       = v0;
                *(float2*)(C + (size_t)(r0 + 8) * N + col) = v1;
            }
        }
    }
}

// ---------------- small fp32 NT GEMM (G = C @ B^T) ----------------
__global__ void __launch_bounds__(256)
sgemm_nt(const float* __restrict__ A, const float* __restrict__ B,
         const float* __restrict__ bias, float* __restrict__ C,
         int N, int K, long sA, long sB, long sC)
{
    __shared__ float As[16][128];
    __shared__ float Bs[16][128];
    const int tid  = threadIdx.x;
    const int tcol = tid & 15;
    const int trow = tid >> 4;
    const float* Ab = A + (size_t)blockIdx.z * sA + (size_t)blockIdx.y * 128 * K;
    const float* Bb = B + (size_t)blockIdx.z * sB + (size_t)blockIdx.x * 128 * K;
    const int nbase = blockIdx.x * 128;

    float acc[8][8];
#pragma unroll
    for (int m = 0; m < 8; m++)
#pragma unroll
        for (int n = 0; n < 8; n++) acc[m][n] = 0.f;

    const int lrow = tid >> 2;
    const int lcol = (tid & 3) * 4;

    for (int kt = 0; kt < K; kt += 16) {
#pragma unroll
        for (int it = 0; it < 2; it++) {
            int r = lrow + it * 64;
            float4 va = *(const float4*)(Ab + (size_t)r * K + kt + lcol);
            As[lcol+0][r] = va.x; As[lcol+1][r] = va.y;
            As[lcol+2][r] = va.z; As[lcol+3][r] = va.w;
            float4 vb;
            if (nbase + r < N) vb = *(const float4*)(Bb + (size_t)r * K + kt + lcol);
            else               vb = make_float4(0.f, 0.f, 0.f, 0.f);
            Bs[lcol+0][r] = vb.x; Bs[lcol+1][r] = vb.y;
            Bs[lcol+2][r] = vb.z; Bs[lcol+3][r] = vb.w;
        }
        __syncthreads();
#pragma unroll
        for (int k = 0; k < 16; k++) {
            float ra[8], rb[8];
#pragma unroll
            for (int m = 0; m < 8; m++) ra[m] = As[k][trow * 8 + m];
#pragma unroll
            for (int n = 0; n < 8; n++) rb[n] = Bs[k][tcol * 8 + n];
#pragma unroll
            for (int m = 0; m < 8; m++)
#pragma unroll
                for (int n = 0; n < 8; n++) acc[m][n] = fmaf(ra[m], rb[n], acc[m][n]);
        }
        __syncthreads();
    }
#pragma unroll
    for (int m = 0; m < 8; m++) {
        int row = blockIdx.y * 128 + trow * 8 + m;
#pragma unroll
        for (int n = 0; n < 8; n++) {
            int col = nbase + tcol * 8 + n;
            if (col < N) {
                float bv = bias ? bias[col] : 0.f;
                C[(size_t)blockIdx.z * sC + (size_t)row * N + col] = acc[m][n] + bv;
            }
        }
    }
}

// ---------------- dt: softplus(dt_raw + bias), dA = -exp(A_log)*dt ----------------
__global__ void dt_kernel(const float* __restrict__ dt_bias, const float* __restrict__ A_log)
{
    int idx = blockIdx.x * blockDim.x + threadIdx.x;
    if (idx >= NROWS * NHEADS) return;
    int h = idx & (NHEADS - 1);
    int r = idx >> 5;
    float v = g_zxbcdt[(size_t)r * DINPROJ + DINNER + CONVDIM + h] + dt_bias[h];
    float dt = (v > 20.f) ? v : log1pf(__expf(v));
    g_dt[idx] = dt;
    g_dA[idx] = -__expf(A_log[h]) * dt;
}

// ---------------- causal depthwise conv + SiLU; split x*dt / B / C ----------------
__global__ void conv_kernel(const float* __restrict__ w, const float* __restrict__ cb)
{
    long idx = (long)blockIdx.x * blockDim.x + threadIdx.x;
    if (idx >= (long)NROWS * CONVDIM) return;
    int c = (int)(idx % CONVDIM);
    int r = (int)(idx / CONVDIM);
    int l = r & (SEQLEN - 1);
    float acc = cb[c];
#pragma unroll
    for (int k = 0; k < 4; k++) {
        int lp = l - 3 + k;
        if (lp >= 0)
            acc = fmaf(w[c * 4 + k], g_zxbcdt[(size_t)(r - 3 + k) * DINPROJ + DINNER + c], acc);
    }
    float out = siluf(acc);
    if (c < DINNER) {
        float v = out * g_dt[r * NHEADS + (c >> 7)];
        g_xf16[(size_t)r * DINNER + c] = __float2half_rn(v);
    } else if (c < DINNER + DSTATE) {
        g_Bv[r * DSTATE + (c - DINNER)] = out;
    } else {
        g_Cv[r * DSTATE + (c - DINNER - DSTATE)] = out;
    }
}

// ---------------- per-chunk inclusive cumsum of dA ----------------
__global__ void cumsum_kernel()
{
    int c = blockIdx.x, h = blockIdx.y, b = blockIdx.z;
    int t = threadIdx.x;
    __shared__ float s[CHUNKT];
    int row = b * SEQLEN + c * CHUNKT + t;
    s[t] = g_dA[row * NHEADS + h];
    __syncthreads();
#pragma unroll
    for (int off = 1; off < CHUNKT; off <<= 1) {
        float x = (t >= off) ? s[t - off] : 0.f;
        __syncthreads();
        s[t] += x;
        __syncthreads();
    }
    g_Acum[(b * NHEADS + h) * SEQLEN + c * CHUNKT + t] = s[t];
}

// ---------------- chunk-local states (FFMA; X from fp16) ----------------
__global__ void __launch_bounds__(256) states_kernel()
{
    int h = blockIdx.x, c = blockIdx.y, b = blockIdx.z;
    __shared__ float Xs[16][128];
    __shared__ float Bsc[16][64];
    __shared__ float Ac[CHUNKT];
    int tid = threadIdx.x;
    Ac[tid] = g_Acum[(b * NHEADS + h) * SEQLEN + c * CHUNKT + tid];
    __syncthreads();
    float Atot = Ac[CHUNKT - 1];
    int brow = b * SEQLEN + c * CHUNKT;
    int tp = tid >> 3, tn = tid & 7;
    float acc[4][8];
#pragma unroll
    for (int m = 0; m < 4; m++)
#pragma unroll
        for (int n = 0; n < 8; n++) acc[m][n] = 0.f;

    for (int lt = 0; lt < CHUNKT; lt += 16) {
#pragma unroll
        for (int q = 0; q < 8; q++) {
            int idx = tid + q * 256;
            int ll = idx >> 7, p = idx & 127;
            Xs[ll][p] = __half2float(g_xf16[(size_t)(brow + lt + ll) * DINNER + h * HEADDIM + p]);
        }
#pragma unroll
        for (int q = 0; q < 4; q++) {
            int idx = tid + q * 256;
            int ll = idx >> 6, n = idx & 63;
            Bsc[ll][n] = g_Bv[(brow + lt + ll) * DSTATE + n] * __expf(Atot - Ac[lt + ll]);
        }
        __syncthreads();
#pragma unroll
        for (int l = 0; l < 16; l++) {
            float ra[4], rb[8];
#pragma unroll
            for (int m = 0; m < 4; m++) ra[m] = Xs[l][tp * 4 + m];
#pragma unroll
            for (int n = 0; n < 8; n++) rb[n] = Bsc[l][tn * 8 + n];
#pragma unroll
            for (int m = 0; m < 4; m++)
#pragma unroll
                for (int n = 0; n < 8; n++) acc[m][n] = fmaf(ra[m], rb[n], acc[m][n]);
        }
        __syncthreads();
    }
    size_t base = ((size_t)((b * NCHUNK + c) * NHEADS + h)) * HEADDIM * DSTATE;
#pragma unroll
    for (int m = 0; m < 4; m++)
#pragma unroll
        for (int n = 0; n < 8; n++)
            g_states[base + (size_t)(tp * 4 + m) * DSTATE + tn * 8 + n] = acc[m][n];
}

// ---------------- inter-chunk state scan ----------------
__global__ void scan_kernel()
{
    int bh = blockIdx.x;
    int b = bh >> 5, h = bh & 31;
    int t = threadIdx.x;
    float S[32];
#pragma unroll
    for (int i = 0; i < 32; i++) S[i] = 0.f;
    for (int c = 0; c < NCHUNK; c++) {
        size_t base = ((size_t)((b * NCHUNK + c) * NHEADS + h)) * (HEADDIM * DSTATE) + (size_t)t * 32;
#pragma unroll
        for (int i = 0; i < 32; i++) g_prefix[base + i] = S[i];
        float f = __expf(g_Acum[(b * NHEADS + h) * SEQLEN + c * CHUNKT + CHUNKT - 1]);
#pragma unroll
        for (int i = 0; i < 32; i++) S[i] = S[i] * f + g_states[base + i];
    }
}

// ================= fused Y on tensor cores (fp16 2-term) =================
// smem: WH 0 (32K) | WL 32768 (32K) | X/S 65536 (16K) | Ac 81920 | eAc 82944
#define YSMEM 84992
__global__ void __launch_bounds__(512, 1) yfused_mma()
{
    extern __shared__ char ysm[];
    const uint32_t sb = smem_u32(ysm);
    float* Ac  = (float*)(ysm + 81920);
    float* eAc = (float*)(ysm + 82944);
    const int h = blockIdx.x, c = blockIdx.y, b = blockIdx.z;
    const int tid = threadIdx.x, lane = tid & 31, wid = tid >> 5;
    const int wr = wid >> 2, wc = wid & 3;     // warp tile 64(i) x 32(p)
    const int brow = b * SEQLEN + c * CHUNKT;
    const size_t gbase = (size_t)(b * NCHUNK + c) * CHUNKT * CHUNKT;
    const size_t sbase = ((size_t)((b * NCHUNK + c) * NHEADS + h)) * (HEADDIM * DSTATE);

    if (tid < CHUNKT) {
        float a = g_Acum[(b * NHEADS + h) * SEQLEN + c * CHUNKT + tid];
        Ac[tid] = a;
        eAc[tid] = __expf(a);
    }

    float acc[4][4][4];
#pragma unroll
    for (int mt = 0; mt < 4; mt++)
#pragma unroll
        for (int nt = 0; nt < 4; nt++)
#pragma unroll
            for (int i = 0; i < 4; i++) acc[mt][nt][i] = 0.f;

    const int g = lane >> 3, li = lane & 7;
    const int arow  = (g & 1) * 8 + li;
    const int ahalf = g >> 1;
    const int bkt   = (g & 1) * 8 + li;
    const int bnt   = (g >> 1) * 8;
    const int brw2  = (g >> 1) * 8 + li;
    const int bhf2  = g & 1;

    // ---- part 1: W @ X over 4 j-tiles of 64 ----
    for (int jt = 0; jt < CHUNKT; jt += 64) {
        __syncthreads();
        for (int idx = tid; idx < 256 * 16; idx += 512) {
            int i = idx >> 4, u4 = idx & 15;
            float4 gv = *(const float4*)&g_G[gbase + (size_t)i * 256 + jt + u4 * 4];
            float ai = Ac[i];
            int j0 = jt + u4 * 4;
            float v0 = (j0 + 0 <= i) ? __expf(ai - Ac[j0 + 0]) * gv.x : 0.f;
            float v1 = (j0 + 1 <= i) ? __expf(ai - Ac[j0 + 1]) * gv.y : 0.f;
            float v2 = (j0 + 2 <= i) ? __expf(ai - Ac[j0 + 2]) * gv.z : 0.f;
            float v3 = (j0 + 3 <= i) ? __expf(ai - Ac[j0 + 3]) * gv.w : 0.f;
            uint32_t lo01, lo23;
            uint32_t hi01 = pack2h(v0, v1, lo01);
            uint32_t hi23 = pack2h(v2, v3, lo23);
            uint32_t base = i * 128 + (((u4 >> 1) ^ (i & 7)) * 16) + (u4 & 1) * 8;
            *(uint2*)(ysm + base)         = make_uint2(hi01, hi23);
            *(uint2*)(ysm + 32768 + base) = make_uint2(lo01, lo23);
        }
        for (int idx = tid; idx < 64 * 16; idx += 512) {
            int l = idx >> 4, u = idx & 15;
            size_t src = (size_t)(brow + jt + l) * DINNER + h * HEADDIM + u * 8;
            uint32_t dst = l * 256 + ((u ^ (l & 7)) * 16);
            *(uint4*)(ysm + 65536 + dst) = *(const uint4*)(g_xf16 + src);
        }
        __syncthreads();
        if (wr * 64 + 63 >= jt) {
#pragma unroll
            for (int s = 0; s < 4; s++) {
                uint32_t afh[4][4], afl[4][4];
#pragma unroll
                for (int mt = 0; mt < 4; mt++) {
                    int row = wr * 64 + mt * 16 + arow;
                    uint32_t off = row * 128 + (((2 * s + ahalf) ^ (row & 7)) * 16);
                    LDSM_X4(afh[mt][0], afh[mt][1], afh[mt][2], afh[mt][3], sb + off);
                    LDSM_X4(afl[mt][0], afl[mt][1], afl[mt][2], afl[mt][3], sb + 32768 + off);
                }
#pragma unroll
                for (int ntp = 0; ntp < 2; ntp++) {
                    int krow = s * 16 + bkt;
                    int p = wc * 32 + ntp * 16 + bnt;
                    uint32_t off = krow * 256 + (((p >> 3) ^ (krow & 7)) * 16);
                    uint32_t b0, b1, b2, b3;
                    LDSM_X4_T(b0, b1, b2, b3, sb + 65536 + off);
#pragma unroll
                    for (int mt = 0; mt < 4; mt++) {
                        mma16816h(acc[mt][2*ntp+0], afh[mt], b0, b1);
                        mma16816h(acc[mt][2*ntp+0], afl[mt], b0, b1);
                        mma16816h(acc[mt][2*ntp+1], afh[mt], b2, b3);
                        mma16816h(acc[mt][2*ntp+1], afl[mt], b2, b3);
                    }
                }
            }
        }
    }

    // ---- part 2: Ce @ S^T (K = 64) ----
    __syncthreads();
    for (int idx = tid; idx < 256 * 16; idx += 512) {
        int i = idx >> 4, u4 = idx & 15;
        float4 cv = *(const float4*)&g_Cv[(size_t)(brow + i) * 64 + u4 * 4];
        float e = eAc[i];
        uint32_t lo01, lo23;
        uint32_t hi01 = pack2h(cv.x * e, cv.y * e, lo01);
        uint32_t hi23 = pack2h(cv.z * e, cv.w * e, lo23);
        uint32_t base = i * 128 + (((u4 >> 1) ^ (i & 7)) * 16) + (u4 & 1) * 8;
        *(uint2*)(ysm + base)         = make_uint2(hi01, hi23);
        *(uint2*)(ysm + 32768 + base) = make_uint2(lo01, lo23);
    }
    for (int idx = tid; idx < 128 * 16; idx += 512) {
        int p = idx >> 4, u4 = idx & 15;
        float4 sv = *(const float4*)&g_prefix[sbase + (size_t)p * 64 + u4 * 4];
        uint32_t h01 = rnd2h(sv.x, sv.y);
        uint32_t h23 = rnd2h(sv.z, sv.w);
        uint32_t base = p * 128 + (((u4 >> 1) ^ (p & 7)) * 16) + (u4 & 1) * 8;
        *(uint2*)(ysm + 65536 + base) = make_uint2(h01, h23);
    }
    __syncthreads();
#pragma unroll
    for (int s = 0; s < 4; s++) {
        uint32_t afh[4][4], afl[4][4];
#pragma unroll
        for (int mt = 0; mt < 4; mt++) {
            int row = wr * 64 + mt * 16 + arow;
            uint32_t off = row * 128 + (((2 * s + ahalf) ^ (row & 7)) * 16);
            LDSM_X4(afh[mt][0], afh[mt][1], afh[mt][2], afh[mt][3], sb + off);
            LDSM_X4(afl[mt][0], afl[mt][1], afl[mt][2], afl[mt][3], sb + 32768 + off);
        }
#pragma unroll
        for (int ntp = 0; ntp < 2; ntp++) {
            int row = wc * 32 + ntp * 16 + brw2;
            uint32_t off = row * 128 + (((2 * s + bhf2) ^ (row & 7)) * 16);
            uint32_t b0, b1, b2, b3;
            LDSM_X4(b0, b1, b2, b3, sb + 65536 + off);
#pragma unroll
            for (int mt = 0; mt < 4; mt++) {
                mma16816h(acc[mt][2*ntp+0], afh[mt], b0, b1);
                mma16816h(acc[mt][2*ntp+0], afl[mt], b0, b1);
                mma16816h(acc[mt][2*ntp+1], afh[mt], b2, b3);
                mma16816h(acc[mt][2*ntp+1], afl[mt], b2, b3);
            }
        }
    }

    // ---- epilogue ----
#pragma unroll
    for (int mt = 0; mt < 4; mt++) {
        int i0 = wr * 64 + mt * 16 + (lane >> 2);
#pragma unroll
        for (int nt = 0; nt < 4; nt++) {
            int col = h * HEADDIM + wc * 32 + nt * 8 + (lane & 3) * 2;
            *(float2*)(g_y + (size_t)(brow + i0) * DINNER + col) =
                make_float2(acc[mt][nt][0], acc[mt][nt][1]);
            *(float2*)(g_y + (size_t)(brow + i0 + 8) * DINNER + col) =
                make_float2(acc[mt][nt][2], acc[mt][nt][3]);
        }
    }
}

// ---------------- gating (y * silu(z)) + LayerNorm; emits fp16 hi/lo ----------------
__global__ void __launch_bounds__(256) ln_kernel(const float* __restrict__ lnw, const float* __restrict__ lnb)
{
    int row = blockIdx.x;
    int tid = threadIdx.x;
    float g[16];
    float s = 0.f, s2 = 0.f;
#pragma unroll
    for (int q = 0; q < 16; q++) {
        int i = tid + q * 256;
        float y = g_y[(size_t)row * DINNER + i];
        float z = g_zxbcdt[(size_t)row * DINPROJ + i];
        float v = y * siluf(z);
        g[q] = v; s += v; s2 = fmaf(v, v, s2);
    }
    __shared__ float red[2][8];
#pragma unroll
    for (int off = 16; off > 0; off >>= 1) {
        s  += __shfl_xor_sync(0xffffffffu, s, off);
        s2 += __shfl_xor_sync(0xffffffffu, s2, off);
    }
    if ((tid & 31) == 0) { red[0][tid >> 5] = s; red[1][tid >> 5] = s2; }
    __syncthreads();
    if (tid == 0) {
        float a = 0.f, a2 = 0.f;
#pragma unroll
        for (int w = 0; w < 8; w++) { a += red[0][w]; a2 += red[1][w]; }
        red[0][0] = a; red[1][0] = a2;
    }
    __syncthreads();
    float mu  = red[0][0] * (1.f / DINNER);
    float var = red[1][0] * (1.f / DINNER) - mu * mu;
    float rstd = rsqrtf(var + LN_EPS);
#pragma unroll
    for (int q = 0; q < 16; q++) {
        int i = tid + q * 256;
        float v = (g[q] - mu) * rstd * lnw[i] + lnb[i];
        __half hh = __float2half_rn(v);
        g_ynh[(size_t)row * DINNER + i] = hh;
        g_ynl[(size_t)row * DINNER + i] = __float2half_rn(v - __half2float(hh));
    }
}

// ---------------- launch ----------------
extern "C" void kernel_launch(void* const* d_in, const int* in_sizes, int n_in,
                              void* d_out, int out_size)
{
    const float* u          = (const float*)d_in[0];
    const float* in_proj_w  = (const float*)d_in[1];
    const float* in_proj_b  = (const float*)d_in[2];
    const float* conv_w     = (const float*)d_in[3];
    const float* conv_b     = (const float*)d_in[4];
    const float* dt_bias    = (const float*)d_in[5];
    const float* A_log      = (const float*)d_in[6];
    const float* ln_w       = (const float*)d_in[7];
    const float* ln_b       = (const float*)d_in[8];
    const float* out_proj_w = (const float*)d_in[9];
    const float* out_proj_b = (const float*)d_in[10];
    float* out = (float*)d_out;

    float *zx, *gB, *gC, *gG;
    __half *uh, *ul, *w1h, *ynh, *ynl, *w2h;
    cudaGetSymbolAddress((void**)&zx,  g_zxbcdt);
    cudaGetSymbolAddress((void**)&gB,  g_Bv);
    cudaGetSymbolAddress((void**)&gC,  g_Cv);
    cudaGetSymbolAddress((void**)&gG,  g_G);
    cudaGetSymbolAddress((void**)&uh,  g_uh);
    cudaGetSymbolAddress((void**)&ul,  g_ul);
    cudaGetSymbolAddress((void**)&w1h, g_w1h);
    cudaGetSymbolAddress((void**)&ynh, g_ynh);
    cudaGetSymbolAddress((void**)&ynl, g_ynl);
    cudaGetSymbolAddress((void**)&w2h, g_w2h);

    cudaFuncSetAttribute(mma_gemm_nt, cudaFuncAttributeMaxDynamicSharedMemorySize, 2 * GST);
    cudaFuncSetAttribute(yfused_mma, cudaFuncAttributeMaxDynamicSharedMemorySize, YSMEM);

    // 0) fp32 -> fp16 conversions
    {
        long n1 = (long)NROWS * DMODEL;
        split_f16<<<(unsigned)((n1 + 255) / 256), 256>>>(u, uh, ul, n1);
        long n2 = (long)DINPROJ * DMODEL;
        round_f16<<<(unsigned)((n2 + 255) / 256), 256>>>(in_proj_w, w1h, n2);
        long n3 = (long)DMODEL * DINNER;
        round_f16<<<(unsigned)((n3 + 255) / 256), 256>>>(out_proj_w, w2h, n3);
    }

    // 1) in_proj: M=8192, N=8352, K=2048
    mma_gemm_nt<<<dim3((DINPROJ + 127) / 128, NROWS / 128), 256, 2 * GST>>>(
        uh, ul, w1h, in_proj_b, zx, DINPROJ, DMODEL);

    // 2) dt softplus + dA
    dt_kernel<<<(NROWS * NHEADS) / 256, 256>>>(dt_bias, A_log);

    // 3) causal conv + silu + split
    {
        long total = (long)NROWS * CONVDIM;
        conv_kernel<<<(unsigned)((total + 255) / 256), 256>>>(conv_w, conv_b);
    }

    // 4) per-chunk cumsum of dA
    cumsum_kernel<<<dim3(NCHUNK, NHEADS, BATCH), CHUNKT>>>();

    // 5) G = C @ B^T per (b,chunk)
    sgemm_nt<<<dim3(2, 2, BATCH * NCHUNK), 256>>>(
        gC, gB, nullptr, gG, CHUNKT, DSTATE,
        (long)CHUNKT * DSTATE, (long)CHUNKT * DSTATE, (long)CHUNKT * CHUNKT);

    // 6) chunk-local states
    states_kernel<<<dim3(NHEADS, NCHUNK, BATCH), 256>>>();

    // 7) inter-chunk scan
    scan_kernel<<<BATCH * NHEADS, 256>>>();

    // 8) fused Y on tensor cores
    yfused_mma<<<dim3(NHEADS, NCHUNK, BATCH), 512, YSMEM>>>();

    // 9) gate + layernorm (+ fp16 split of yn)
    ln_kernel<<<NROWS, 256>>>(ln_w, ln_b);

    // 10) out_proj: M=8192, N=2048, K=4096
    mma_gemm_nt<<<dim3(DMODEL / 128, NROWS / 128), 256, 2 * GST>>>(
        ynh, ynl, w2h, out_proj_b, out, DMODEL, DINNER);
}

// round 10
// speedup vs baseline: 1.0051x; 1.0051x over previous
#include <cuda_runtime.h>
#include <cuda_bf16.h>
#include <cuda_fp16.h>
#include <cstdint>
#include <math.h>

#define BATCH   2
#define SEQLEN  4096
#define DMODEL  2048
#define DINNER  4096
#define NHEADS  32
#define HEADDIM 128
#define DSTATE  64
#define NCHUNK  16
#define CHUNKT  256
#define CONVDIM 4224
#define DINPROJ 8352
#define NROWS   (BATCH*SEQLEN)
#define LN_EPS  1e-5f

// ---------------- scratch (device globals; no allocations allowed) ----------------
__device__ float g_zxbcdt[(size_t)NROWS * DINPROJ];
__device__ float g_Bv   [NROWS * DSTATE];
__device__ float g_Cv   [NROWS * DSTATE];
__device__ float g_dt   [NROWS * NHEADS];
__device__ float g_dA   [NROWS * NHEADS];
__device__ float g_Acum [BATCH * NHEADS * SEQLEN];
__device__ float g_G    [(size_t)BATCH * NCHUNK * CHUNKT * CHUNKT];
__device__ float g_states[(size_t)BATCH * NCHUNK * NHEADS * HEADDIM * DSTATE];
__device__ float g_prefix[(size_t)BATCH * NCHUNK * NHEADS * HEADDIM * DSTATE];
__device__ float g_y    [(size_t)NROWS * DINNER];

// fp16 buffers (activations exact hi/lo, weights rounded)
__device__ __half g_uh [(size_t)NROWS * DMODEL];
__device__ __half g_ul [(size_t)NROWS * DMODEL];
__device__ __half g_w1h[(size_t)DINPROJ * DMODEL];
__device__ __half g_ynh[(size_t)NROWS * DINNER];
__device__ __half g_ynl[(size_t)NROWS * DINNER];
__device__ __half g_w2h[(size_t)DMODEL * DINNER];
__device__ __half g_xf16[(size_t)NROWS * DINNER];   // rounded fp16 of xdt

__device__ __forceinline__ float siluf(float x) { return x / (1.f + __expf(-x)); }

__device__ __forceinline__ uint32_t smem_u32(const void* p) {
    uint32_t a;
    asm("{ .reg .u64 t; cvta.to.shared.u64 t, %1; cvt.u32.u64 %0, t; }" : "=r"(a) : "l"(p));
    return a;
}

// pack two floats into fp16x2 hi; return hi, write lo (exact 2-term split)
__device__ __forceinline__ uint32_t pack2h(float a, float b, uint32_t& lo) {
    __half ha = __float2half_rn(a), hb = __float2half_rn(b);
    __half la = __float2half_rn(a - __half2float(ha));
    __half lb = __float2half_rn(b - __half2float(hb));
    lo = (uint32_t)__half_as_ushort(la) | ((uint32_t)__half_as_ushort(lb) << 16);
    return (uint32_t)__half_as_ushort(ha) | ((uint32_t)__half_as_ushort(hb) << 16);
}
__device__ __forceinline__ uint32_t rnd2h(float a, float b) {
    return (uint32_t)__half_as_ushort(__float2half_rn(a)) |
           ((uint32_t)__half_as_ushort(__float2half_rn(b)) << 16);
}

// ================= split kernels =================
__global__ void split_f16(const float* __restrict__ src,
                          __half* __restrict__ hi, __half* __restrict__ lo, long n)
{
    long i = (long)blockIdx.x * blockDim.x + threadIdx.x;
    if (i >= n) return;
    float x = src[i];
    __half h = __float2half_rn(x);
    hi[i] = h;
    lo[i] = __float2half_rn(x - __half2float(h));
}
__global__ void round_f16(const float* __restrict__ src, __half* __restrict__ dst, long n)
{
    long i = (long)blockIdx.x * blockDim.x + threadIdx.x;
    if (i >= n) return;
    dst[i] = __float2half_rn(src[i]);
}

// ================= tensor-core primitives =================
__device__ __forceinline__ void mma16816h(float* c, const uint32_t* a, uint32_t b0, uint32_t b1)
{
    asm volatile(
        "mma.sync.aligned.m16n8k16.row.col.f32.f16.f16.f32 "
        "{%0,%1,%2,%3}, {%4,%5,%6,%7}, {%8,%9}, {%0,%1,%2,%3};"
        : "+f"(c[0]), "+f"(c[1]), "+f"(c[2]), "+f"(c[3])
        : "r"(a[0]), "r"(a[1]), "r"(a[2]), "r"(a[3]), "r"(b0), "r"(b1));
}
#define LDSM_X4(r0, r1, r2, r3, addr) \
    asm volatile("ldmatrix.sync.aligned.m8n8.x4.shared.b16 {%0,%1,%2,%3}, [%4];" \
                 : "=r"(r0), "=r"(r1), "=r"(r2), "=r"(r3) : "r"(addr))
#define LDSM_X4_T(r0, r1, r2, r3, addr) \
    asm volatile("ldmatrix.sync.aligned.m8n8.x4.trans.shared.b16 {%0,%1,%2,%3}, [%4];" \
                 : "=r"(r0), "=r"(r1), "=r"(r2), "=r"(r3) : "r"(addr))
#define CP16(dst, src, sz) \
    asm volatile("cp.async.cg.shared.global [%0], [%1], 16, %2;" \
                 :: "r"(dst), "l"(src), "r"(sz))
#define CP_COMMIT() asm volatile("cp.async.commit_group;" ::: "memory")
#define CP_WAIT1()  asm volatile("cp.async.wait_group 1;" ::: "memory")
#define CP_WAIT0()  asm volatile("cp.async.wait_group 0;" ::: "memory")

// ================= fp16 2-MMA GEMM: C = (Ah+Al)*Bh^T + bias =================
// BM=128, BN=256, BK=64, 512 threads (16 warps, 32x64 warp tiles).
// 3-stage cp.async pipeline. A exact fp16 hi/lo (M mult of 128); B rounded fp16.
#define GST 65536
__global__ void __launch_bounds__(512, 1)
mma_gemm_nt(const __half* __restrict__ Ah, const __half* __restrict__ Al,
            const __half* __restrict__ Bh,
            const float* __restrict__ bias, float* __restrict__ C, int N, int K)
{
    extern __shared__ char smem[];
    const uint32_t sb = smem_u32(smem);
    const int tid = threadIdx.x, lane = tid & 31, wid = tid >> 5;
    const int wr = wid >> 2, wc = wid & 3;        // 4x4 warps, each 32(m) x 64(n)
    const int mbase = blockIdx.y * 128;
    const int nbase = blockIdx.x * 256;

    // A loader: 4 thr/row, 2 units; B loader: 2 thr/row, 4 units
    const int ra = tid >> 2, ua0 = (tid & 3) * 2;
    const int rb = tid >> 1, ub0 = (tid & 1) * 4;
    const bool bval = (nbase + rb) < N;
    const uint32_t bsz = bval ? 16u : 0u;
    const __half* gAh = Ah + (size_t)(mbase + ra) * K + ua0 * 8;
    const __half* gAl = Al + (size_t)(mbase + ra) * K + ua0 * 8;
    const __half* gBh = Bh + (size_t)(bval ? nbase + rb : 0) * K + ub0 * 8;
    const uint32_t dA0 = ra * 128 + (( ua0      ^ (ra & 7)) * 16);
    const uint32_t dA1 = ra * 128 + (((ua0 + 1) ^ (ra & 7)) * 16);
    uint32_t dB[4];
#pragma unroll
    for (int j = 0; j < 4; j++) dB[j] = rb * 128 + (((ub0 + j) ^ (rb & 7)) * 16);

    auto issue = [&](int st, int kt) {
        uint32_t s0 = sb + st * GST;
        CP16(s0 + dA0,         gAh + kt,     16);
        CP16(s0 + dA1,         gAh + kt + 8, 16);
        CP16(s0 + 16384 + dA0, gAl + kt,     16);
        CP16(s0 + 16384 + dA1, gAl + kt + 8, 16);
#pragma unroll
        for (int j = 0; j < 4; j++)
            CP16(s0 + 32768 + dB[j], gBh + kt + j * 8, bsz);
        CP_COMMIT();
    };

    float acc[2][8][4];
#pragma unroll
    for (int mt = 0; mt < 2; mt++)
#pragma unroll
        for (int nt = 0; nt < 8; nt++)
#pragma unroll
            for (int i = 0; i < 4; i++) acc[mt][nt][i] = 0.f;

    const int nk = K >> 6;
    issue(0, 0);
    issue(1, 64);

    const int g = lane >> 3, li = lane & 7;
    const int arow_lo = (g & 1) * 8 + li;
    const int ahalf   = g >> 1;
    const int brow_lo = (g >> 1) * 8 + li;
    const int bhalf   = g & 1;

    int stage = 0;
    for (int c = 0; c < nk; c++) {
        if (c + 1 < nk) CP_WAIT1(); else CP_WAIT0();
        __syncthreads();
        if (c + 2 < nk) {
            int st = stage + 2; if (st >= 3) st -= 3;
            issue(st, (c + 2) * 64);
        }
        const uint32_t s0 = sb + stage * GST;
#pragma unroll
        for (int s = 0; s < 4; s++) {
            uint32_t afh[2][4], afl[2][4];
#pragma unroll
            for (int mt = 0; mt < 2; mt++) {
                int row = wr * 32 + mt * 16 + arow_lo;
                uint32_t off = row * 128 + (((2 * s + ahalf) ^ (row & 7)) * 16);
                LDSM_X4(afh[mt][0], afh[mt][1], afh[mt][2], afh[mt][3], s0 + off);
                LDSM_X4(afl[mt][0], afl[mt][1], afl[mt][2], afl[mt][3], s0 + 16384 + off);
            }
#pragma unroll
            for (int ntp = 0; ntp < 4; ntp++) {
                int row = wc * 64 + ntp * 16 + brow_lo;
                uint32_t off = row * 128 + (((2 * s + bhalf) ^ (row & 7)) * 16);
                uint32_t b0, b1, b2, b3;
                LDSM_X4(b0, b1, b2, b3, s0 + 32768 + off);
#pragma unroll
                for (int mt = 0; mt < 2; mt++) {
                    mma16816h(acc[mt][2*ntp+0], afh[mt], b0, b1);
                    mma16816h(acc[mt][2*ntp+0], afl[mt], b0, b1);
                    mma16816h(acc[mt][2*ntp+1], afh[mt], b2, b3);
                    mma16816h(acc[mt][2*ntp+1], afl[mt], b2, b3);
                }
            }
        }
        stage++; if (stage >= 3) stage -= 3;
    }

#pragma unroll
    for (int mt = 0; mt < 2; mt++) {
        int r0 = mbase + wr * 32 + mt * 16 + (lane >> 2);
#pragma unroll
        for (int nt = 0; nt < 8; nt++) {
            int col = nbase + wc * 64 + nt * 8 + (lane & 3) * 2;
            if (col < N) {
                float b0 = bias ? bias[col] : 0.f;
                float b1 = bias ? bias[col + 1] : 0.f;
                float2 v0 = make_float2(acc[mt][nt][0] + b0, acc[mt][nt][1] + b1);
                float2 v1 = make_float2(acc[mt][nt][2] + b0, acc[mt][nt][3] + b1);
                *(float2*)(C + (size_t)r0 * N + col)       = v0;
                *(float2*)(C + (size_t)(r0 + 8) * N + col) = v1;
            }
        }
    }
}

// ---------------- small fp32 NT GEMM (G = C @ B^T) ----------------
__global__ void __launch_bounds__(256)
sgemm_nt(const float* __restrict__ A, const float* __restrict__ B,
         const float* __restrict__ bias, float* __restrict__ C,
         int N, int K, long sA, long sB, long sC)
{
    __shared__ float As[16][128];
    __shared__ float Bs[16][128];
    const int tid  = threadIdx.x;
    const int tcol = tid & 15;
    const int trow = tid >> 4;
    const float* Ab = A + (size_t)blockIdx.z * sA + (size_t)blockIdx.y * 128 * K;
    const float* Bb = B + (size_t)blockIdx.z * sB + (size_t)blockIdx.x * 128 * K;
    const int nbase = blockIdx.x * 128;

    float acc[8][8];
#pragma unroll
    for (int m = 0; m < 8; m++)
#pragma unroll
        for (int n = 0; n < 8; n++) acc[m][n] = 0.f;

    const int lrow = tid >> 2;
    const int lcol = (tid & 3) * 4;

    for (int kt = 0; kt < K; kt += 16) {
#pragma unroll
        for (int it = 0; it < 2; it++) {
            int r = lrow + it * 64;
            float4 va = *(const float4*)(Ab + (size_t)r * K + kt + lcol);
            As[lcol+0][r] = va.x; As[lcol+1][r] = va.y;
            As[lcol+2][r] = va.z; As[lcol+3][r] = va.w;
            float4 vb;
            if (nbase + r < N) vb = *(const float4*)(Bb + (size_t)r * K + kt + lcol);
            else               vb = make_float4(0.f, 0.f, 0.f, 0.f);
            Bs[lcol+0][r] = vb.x; Bs[lcol+1][r] = vb.y;
            Bs[lcol+2][r] = vb.z; Bs[lcol+3][r] = vb.w;
        }
        __syncthreads();
#pragma unroll
        for (int k = 0; k < 16; k++) {
            float ra[8], rb[8];
#pragma unroll
            for (int m = 0; m < 8; m++) ra[m] = As[k][trow * 8 + m];
#pragma unroll
            for (int n = 0; n < 8; n++) rb[n] = Bs[k][tcol * 8 + n];
#pragma unroll
            for (int m = 0; m < 8; m++)
#pragma unroll
                for (int n = 0; n < 8; n++) acc[m][n] = fmaf(ra[m], rb[n], acc[m][n]);
        }
        __syncthreads();
    }
#pragma unroll
    for (int m = 0; m < 8; m++) {
        int row = blockIdx.y * 128 + trow * 8 + m;
#pragma unroll
        for (int n = 0; n < 8; n++) {
            int col = nbase + tcol * 8 + n;
            if (col < N) {
                float bv = bias ? bias[col] : 0.f;
                C[(size_t)blockIdx.z * sC + (size_t)row * N + col] = acc[m][n] + bv;
            }
        }
    }
}

// ---------------- dt: softplus(dt_raw + bias), dA = -exp(A_log)*dt ----------------
__global__ void dt_kernel(const float* __restrict__ dt_bias, const float* __restrict__ A_log)
{
    int idx = blockIdx.x * blockDim.x + threadIdx.x;
    if (idx >= NROWS * NHEADS) return;
    int h = idx & (NHEADS - 1);
    int r = idx >> 5;
    float v = g_zxbcdt[(size_t)r * DINPROJ + DINNER + CONVDIM + h] + dt_bias[h];
    float dt = (v > 20.f) ? v : log1pf(__expf(v));
    g_dt[idx] = dt;
    g_dA[idx] = -__expf(A_log[h]) * dt;
}

// ---------------- causal depthwise conv + SiLU; split x*dt / B / C ----------------
__global__ void conv_kernel(const float* __restrict__ w, const float* __restrict__ cb)
{
    long idx = (long)blockIdx.x * blockDim.x + threadIdx.x;
    if (idx >= (long)NROWS * CONVDIM) return;
    int c = (int)(idx % CONVDIM);
    int r = (int)(idx / CONVDIM);
    int l = r & (SEQLEN - 1);
    float acc = cb[c];
#pragma unroll
    for (int k = 0; k < 4; k++) {
        int lp = l - 3 + k;
        if (lp >= 0)
            acc = fmaf(w[c * 4 + k], g_zxbcdt[(size_t)(r - 3 + k) * DINPROJ + DINNER + c], acc);
    }
    float out = siluf(acc);
    if (c < DINNER) {
        float v = out * g_dt[r * NHEADS + (c >> 7)];
        g_xf16[(size_t)r * DINNER + c] = __float2half_rn(v);
    } else if (c < DINNER + DSTATE) {
        g_Bv[r * DSTATE + (c - DINNER)] = out;
    } else {
        g_Cv[r * DSTATE + (c - DINNER - DSTATE)] = out;
    }
}

// ---------------- per-chunk inclusive cumsum of dA ----------------
__global__ void cumsum_kernel()
{
    int c = blockIdx.x, h = blockIdx.y, b = blockIdx.z;
    int t = threadIdx.x;
    __shared__ float s[CHUNKT];
    int row = b * SEQLEN + c * CHUNKT + t;
    s[t] = g_dA[row * NHEADS + h];
    __syncthreads();
#pragma unroll
    for (int off = 1; off < CHUNKT; off <<= 1) {
        float x = (t >= off) ? s[t - off] : 0.f;
        __syncthreads();
        s[t] += x;
        __syncthreads();
    }
    g_Acum[(b * NHEADS + h) * SEQLEN + c * CHUNKT + t] = s[t];
}

// ---------------- chunk-local states (FFMA; X from fp16) ----------------
__global__ void __launch_bounds__(256) states_kernel()
{
    int h = blockIdx.x, c = blockIdx.y, b = blockIdx.z;
    __shared__ float Xs[16][128];
    __shared__ float Bsc[16][64];
    __shared__ float Ac[CHUNKT];
    int tid = threadIdx.x;
    Ac[tid] = g_Acum[(b * NHEADS + h) * SEQLEN + c * CHUNKT + tid];
    __syncthreads();
    float Atot = Ac[CHUNKT - 1];
    int brow = b * SEQLEN + c * CHUNKT;
    int tp = tid >> 3, tn = tid & 7;
    float acc[4][8];
#pragma unroll
    for (int m = 0; m < 4; m++)
#pragma unroll
        for (int n = 0; n < 8; n++) acc[m][n] = 0.f;

    for (int lt = 0; lt < CHUNKT; lt += 16) {
#pragma unroll
        for (int q = 0; q < 8; q++) {
            int idx = tid + q * 256;
            int ll = idx >> 7, p = idx & 127;
            Xs[ll][p] = __half2float(g_xf16[(size_t)(brow + lt + ll) * DINNER + h * HEADDIM + p]);
        }
#pragma unroll
        for (int q = 0; q < 4; q++) {
            int idx = tid + q * 256;
            int ll = idx >> 6, n = idx & 63;
            Bsc[ll][n] = g_Bv[(brow + lt + ll) * DSTATE + n] * __expf(Atot - Ac[lt + ll]);
        }
        __syncthreads();
#pragma unroll
        for (int l = 0; l < 16; l++) {
            float ra[4], rb[8];
#pragma unroll
            for (int m = 0; m < 4; m++) ra[m] = Xs[l][tp * 4 + m];
#pragma unroll
            for (int n = 0; n < 8; n++) rb[n] = Bsc[l][tn * 8 + n];
#pragma unroll
            for (int m = 0; m < 4; m++)
#pragma unroll
                for (int n = 0; n < 8; n++) acc[m][n] = fmaf(ra[m], rb[n], acc[m][n]);
        }
        __syncthreads();
    }
    size_t base = ((size_t)((b * NCHUNK + c) * NHEADS + h)) * HEADDIM * DSTATE;
#pragma unroll
    for (int m = 0; m < 4; m++)
#pragma unroll
        for (int n = 0; n < 8; n++)
            g_states[base + (size_t)(tp * 4 + m) * DSTATE + tn * 8 + n] = acc[m][n];
}

// ---------------- inter-chunk state scan ----------------
__global__ void scan_kernel()
{
    int bh = blockIdx.x;
    int b = bh >> 5, h = bh & 31;
    int t = threadIdx.x;
    float S[32];
#pragma unroll
    for (int i = 0; i < 32; i++) S[i] = 0.f;
    for (int c = 0; c < NCHUNK; c++) {
        size_t base = ((size_t)((b * NCHUNK + c) * NHEADS + h)) * (HEADDIM * DSTATE) + (size_t)t * 32;
#pragma unroll
        for (int i = 0; i < 32; i++) g_prefix[base + i] = S[i];
        float f = __expf(g_Acum[(b * NHEADS + h) * SEQLEN + c * CHUNKT + CHUNKT - 1]);
#pragma unroll
        for (int i = 0; i < 32; i++) S[i] = S[i] * f + g_states[base + i];
    }
}

// ================= fused Y on tensor cores (fp16 2-term) =================
// smem: WH 0 (32K) | WL 32768 (32K) | X/S 65536 (16K) | Ac 81920 | eAc 82944
#define YSMEM 84992
__global__ void __launch_bounds__(512, 1) yfused_mma()
{
    extern __shared__ char ysm[];
    const uint32_t sb = smem_u32(ysm);
    float* Ac  = (float*)(ysm + 81920);
    float* eAc = (float*)(ysm + 82944);
    const int h = blockIdx.x, c = blockIdx.y, b = blockIdx.z;
    const int tid = threadIdx.x, lane = tid & 31, wid = tid >> 5;
    const int wr = wid >> 2, wc = wid & 3;     // warp tile 64(i) x 32(p)
    const int brow = b * SEQLEN + c * CHUNKT;
    const size_t gbase = (size_t)(b * NCHUNK + c) * CHUNKT * CHUNKT;
    const size_t sbase = ((size_t)((b * NCHUNK + c) * NHEADS + h)) * (HEADDIM * DSTATE);

    if (tid < CHUNKT) {
        float a = g_Acum[(b * NHEADS + h) * SEQLEN + c * CHUNKT + tid];
        Ac[tid] = a;
        eAc[tid] = __expf(a);
    }

    float acc[4][4][4];
#pragma unroll
    for (int mt = 0; mt < 4; mt++)
#pragma unroll
        for (int nt = 0; nt < 4; nt++)
#pragma unroll
            for (int i = 0; i < 4; i++) acc[mt][nt][i] = 0.f;

    const int g = lane >> 3, li = lane & 7;
    const int arow  = (g & 1) * 8 + li;
    const int ahalf = g >> 1;
    const int bkt   = (g & 1) * 8 + li;
    const int bnt   = (g >> 1) * 8;
    const int brw2  = (g >> 1) * 8 + li;
    const int bhf2  = g & 1;

    // ---- part 1: W @ X over 4 j-tiles of 64 ----
    for (int jt = 0; jt < CHUNKT; jt += 64) {
        __syncthreads();
        for (int idx = tid; idx < 256 * 16; idx += 512) {
            int i = idx >> 4, u4 = idx & 15;
            float4 gv = *(const float4*)&g_G[gbase + (size_t)i * 256 + jt + u4 * 4];
            float ai = Ac[i];
            int j0 = jt + u4 * 4;
            float v0 = (j0 + 0 <= i) ? __expf(ai - Ac[j0 + 0]) * gv.x : 0.f;
            float v1 = (j0 + 1 <= i) ? __expf(ai - Ac[j0 + 1]) * gv.y : 0.f;
            float v2 = (j0 + 2 <= i) ? __expf(ai - Ac[j0 + 2]) * gv.z : 0.f;
            float v3 = (j0 + 3 <= i) ? __expf(ai - Ac[j0 + 3]) * gv.w : 0.f;
            uint32_t lo01, lo23;
            uint32_t hi01 = pack2h(v0, v1, lo01);
            uint32_t hi23 = pack2h(v2, v3, lo23);
            uint32_t base = i * 128 + (((u4 >> 1) ^ (i & 7)) * 16) + (u4 & 1) * 8;
            *(uint2*)(ysm + base)         = make_uint2(hi01, hi23);
            *(uint2*)(ysm + 32768 + base) = make_uint2(lo01, lo23);
        }
        for (int idx = tid; idx < 64 * 16; idx += 512) {
            int l = idx >> 4, u = idx & 15;
            size_t src = (size_t)(brow + jt + l) * DINNER + h * HEADDIM + u * 8;
            uint32_t dst = l * 256 + ((u ^ (l & 7)) * 16);
            *(uint4*)(ysm + 65536 + dst) = *(const uint4*)(g_xf16 + src);
        }
        __syncthreads();
        if (wr * 64 + 63 >= jt) {
#pragma unroll
            for (int s = 0; s < 4; s++) {
                uint32_t afh[4][4], afl[4][4];
#pragma unroll
                for (int mt = 0; mt < 4; mt++) {
                    int row = wr * 64 + mt * 16 + arow;
                    uint32_t off = row * 128 + (((2 * s + ahalf) ^ (row & 7)) * 16);
                    LDSM_X4(afh[mt][0], afh[mt][1], afh[mt][2], afh[mt][3], sb + off);
                    LDSM_X4(afl[mt][0], afl[mt][1], afl[mt][2], afl[mt][3], sb + 32768 + off);
                }
#pragma unroll
                for (int ntp = 0; ntp < 2; ntp++) {
                    int krow = s * 16 + bkt;
                    int p = wc * 32 + ntp * 16 + bnt;
                    uint32_t off = krow * 256 + (((p >> 3) ^ (krow & 7)) * 16);
                    uint32_t b0, b1, b2, b3;
                    LDSM_X4_T(b0, b1, b2, b3, sb + 65536 + off);
#pragma unroll
                    for (int mt = 0; mt < 4; mt++) {
                        mma16816h(acc[mt][2*ntp+0], afh[mt], b0, b1);
                        mma16816h(acc[mt][2*ntp+0], afl[mt], b0, b1);
                        mma16816h(acc[mt][2*ntp+1], afh[mt], b2, b3);
                        mma16816h(acc[mt][2*ntp+1], afl[mt], b2, b3);
                    }
                }
            }
        }
    }

    // ---- part 2: Ce @ S^T (K = 64) ----
    __syncthreads();
    for (int idx = tid; idx < 256 * 16; idx += 512) {
        int i = idx >> 4, u4 = idx & 15;
        float4 cv = *(const float4*)&g_Cv[(size_t)(brow + i) * 64 + u4 * 4];
        float e = eAc[i];
        uint32_t lo01, lo23;
        uint32_t hi01 = pack2h(cv.x * e, cv.y * e, lo01);
        uint32_t hi23 = pack2h(cv.z * e, cv.w * e, lo23);
        uint32_t base = i * 128 + (((u4 >> 1) ^ (i & 7)) * 16) + (u4 & 1) * 8;
        *(uint2*)(ysm + base)         = make_uint2(hi01, hi23);
        *(uint2*)(ysm + 32768 + base) = make_uint2(lo01, lo23);
    }
    for (int idx = tid; idx < 128 * 16; idx += 512) {
        int p = idx >> 4, u4 = idx & 15;
        float4 sv = *(const float4*)&g_prefix[sbase + (size_t)p * 64 + u4 * 4];
        uint32_t h01 = rnd2h(sv.x, sv.y);
        uint32_t h23 = rnd2h(sv.z, sv.w);
        uint32_t base = p * 128 + (((u4 >> 1) ^ (p & 7)) * 16) + (u4 & 1) * 8;
        *(uint2*)(ysm + 65536 + base) = make_uint2(h01, h23);
    }
    __syncthreads();
#pragma unroll
    for (int s = 0; s < 4; s++) {
        uint32_t afh[4][4], afl[4][4];
#pragma unroll
        for (int mt = 0; mt < 4; mt++) {
            int row = wr * 64 + mt * 16 + arow;
            uint32_t off = row * 128 + (((2 * s + ahalf) ^ (row & 7)) * 16);
            LDSM_X4(afh[mt][0], afh[mt][1], afh[mt][2], afh[mt][3], sb + off);
            LDSM_X4(afl[mt][0], afl[mt][1], afl[mt][2], afl[mt][3], sb + 32768 + off);
        }
#pragma unroll
        for (int ntp = 0; ntp < 2; ntp++) {
            int row = wc * 32 + ntp * 16 + brw2;
            uint32_t off = row * 128 + (((2 * s + bhf2) ^ (row & 7)) * 16);
            uint32_t b0, b1, b2, b3;
            LDSM_X4(b0, b1, b2, b3, sb + 65536 + off);
#pragma unroll
            for (int mt = 0; mt < 4; mt++) {
                mma16816h(acc[mt][2*ntp+0], afh[mt], b0, b1);
                mma16816h(acc[mt][2*ntp+0], afl[mt], b0, b1);
                mma16816h(acc[mt][2*ntp+1], afh[mt], b2, b3);
                mma16816h(acc[mt][2*ntp+1], afl[mt], b2, b3);
            }
        }
    }

    // ---- epilogue ----
#pragma unroll
    for (int mt = 0; mt < 4; mt++) {
        int i0 = wr * 64 + mt * 16 + (lane >> 2);
#pragma unroll
        for (int nt = 0; nt < 4; nt++) {
            int col = h * HEADDIM + wc * 32 + nt * 8 + (lane & 3) * 2;
            *(float2*)(g_y + (size_t)(brow + i0) * DINNER + col) =
                make_float2(acc[mt][nt][0], acc[mt][nt][1]);
            *(float2*)(g_y + (size_t)(brow + i0 + 8) * DINNER + col) =
                make_float2(acc[mt][nt][2], acc[mt][nt][3]);
        }
    }
}

// ---------------- gating (y * silu(z)) + LayerNorm; emits fp16 hi/lo ----------------
__global__ void __launch_bounds__(256) ln_kernel(const float* __restrict__ lnw, const float* __restrict__ lnb)
{
    int row = blockIdx.x;
    int tid = threadIdx.x;
    float g[16];
    float s = 0.f, s2 = 0.f;
#pragma unroll
    for (int q = 0; q < 16; q++) {
        int i = tid + q * 256;
        float y = g_y[(size_t)row * DINNER + i];
        float z = g_zxbcdt[(size_t)row * DINPROJ + i];
        float v = y * siluf(z);
        g[q] = v; s += v; s2 = fmaf(v, v, s2);
    }
    __shared__ float red[2][8];
#pragma unroll
    for (int off = 16; off > 0; off >>= 1) {
        s  += __shfl_xor_sync(0xffffffffu, s, off);
        s2 += __shfl_xor_sync(0xffffffffu, s2, off);
    }
    if ((tid & 31) == 0) { red[0][tid >> 5] = s; red[1][tid >> 5] = s2; }
    __syncthreads();
    if (tid == 0) {
        float a = 0.f, a2 = 0.f;
#pragma unroll
        for (int w = 0; w < 8; w++) { a += red[0][w]; a2 += red[1][w]; }
        red[0][0] = a; red[1][0] = a2;
    }
    __syncthreads();
    float mu  = red[0][0] * (1.f / DINNER);
    float var = red[1][0] * (1.f / DINNER) - mu * mu;
    float rstd = rsqrtf(var + LN_EPS);
#pragma unroll
    for (int q = 0; q < 16; q++) {
        int i = tid + q * 256;
        float v = (g[q] - mu) * rstd * lnw[i] + lnb[i];
        __half hh = __float2half_rn(v);
        g_ynh[(size_t)row * DINNER + i] = hh;
        g_ynl[(size_t)row * DINNER + i] = __float2half_rn(v - __half2float(hh));
    }
}

// ---------------- launch ----------------
extern "C" void kernel_launch(void* const* d_in, const int* in_sizes, int n_in,
                              void* d_out, int out_size)
{
    const float* u          = (const float*)d_in[0];
    const float* in_proj_w  = (const float*)d_in[1];
    const float* in_proj_b  = (const float*)d_in[2];
    const float* conv_w     = (const float*)d_in[3];
    const float* conv_b     = (const float*)d_in[4];
    const float* dt_bias    = (const float*)d_in[5];
    const float* A_log      = (const float*)d_in[6];
    const float* ln_w       = (const float*)d_in[7];
    const float* ln_b       = (const float*)d_in[8];
    const float* out_proj_w = (const float*)d_in[9];
    const float* out_proj_b = (const float*)d_in[10];
    float* out = (float*)d_out;

    float *zx, *gB, *gC, *gG;
    __half *uh, *ul, *w1h, *ynh, *ynl, *w2h;
    cudaGetSymbolAddress((void**)&zx,  g_zxbcdt);
    cudaGetSymbolAddress((void**)&gB,  g_Bv);
    cudaGetSymbolAddress((void**)&gC,  g_Cv);
    cudaGetSymbolAddress((void**)&gG,  g_G);
    cudaGetSymbolAddress((void**)&uh,  g_uh);
    cudaGetSymbolAddress((void**)&ul,  g_ul);
    cudaGetSymbolAddress((void**)&w1h, g_w1h);
    cudaGetSymbolAddress((void**)&ynh, g_ynh);
    cudaGetSymbolAddress((void**)&ynl, g_ynl);
    cudaGetSymbolAddress((void**)&w2h, g_w2h);

    cudaFuncSetAttribute(mma_gemm_nt, cudaFuncAttributeMaxDynamicSharedMemorySize, 3 * GST);
    cudaFuncSetAttribute(yfused_mma, cudaFuncAttributeMaxDynamicSharedMemorySize, YSMEM);

    // 0) fp32 -> fp16 conversions
    {
        long n1 = (long)NROWS * DMODEL;
        split_f16<<<(unsigned)((n1 + 255) / 256), 256>>>(u, uh, ul, n1);
        long n2 = (long)DINPROJ * DMODEL;
        round_f16<<<(unsigned)((n2 + 255) / 256), 256>>>(in_proj_w, w1h, n2);
        long n3 = (long)DMODEL * DINNER;
        round_f16<<<(unsigned)((n3 + 255) / 256), 256>>>(out_proj_w, w2h, n3);
    }

    // 1) in_proj: M=8192, N=8352, K=2048
    mma_gemm_nt<<<dim3((DINPROJ + 255) / 256, NROWS / 128), 512, 3 * GST>>>(
        uh, ul, w1h, in_proj_b, zx, DINPROJ, DMODEL);

    // 2) dt softplus + dA
    dt_kernel<<<(NROWS * NHEADS) / 256, 256>>>(dt_bias, A_log);

    // 3) causal conv + silu + split
    {
        long total = (long)NROWS * CONVDIM;
        conv_kernel<<<(unsigned)((total + 255) / 256), 256>>>(conv_w, conv_b);
    }

    // 4) per-chunk cumsum of dA
    cumsum_kernel<<<dim3(NCHUNK, NHEADS, BATCH), CHUNKT>>>();

    // 5) G = C @ B^T per (b,chunk)
    sgemm_nt<<<dim3(2, 2, BATCH * NCHUNK), 256>>>(
        gC, gB, nullptr, gG, CHUNKT, DSTATE,
        (long)CHUNKT * DSTATE, (long)CHUNKT * DSTATE, (long)CHUNKT * CHUNKT);

    // 6) chunk-local states
    states_kernel<<<dim3(NHEADS, NCHUNK, BATCH), 256>>>();

    // 7) inter-chunk scan
    scan_kernel<<<BATCH * NHEADS, 256>>>();

    // 8) fused Y on tensor cores
    yfused_mma<<<dim3(NHEADS, NCHUNK, BATCH), 512, YSMEM>>>();

    // 9) gate + layernorm (+ fp16 split of yn)
    ln_kernel<<<NROWS, 256>>>(ln_w, ln_b);

    // 10) out_proj: M=8192, N=2048, K=4096
    mma_gemm_nt<<<dim3(DMODEL / 256, NROWS / 128), 512, 3 * GST>>>(
        ynh, ynl, w2h, out_proj_b, out, DMODEL, DINNER);
}

// round 11
// speedup vs baseline: 1.1052x; 1.0996x over previous
#include <cuda_runtime.h>
#include <cuda_bf16.h>
#include <cuda_fp16.h>
#include <cstdint>
#include <math.h>

#define BATCH   2
#define SEQLEN  4096
#define DMODEL  2048
#define DINNER  4096
#define NHEADS  32
#define HEADDIM 128
#define DSTATE  64
#define NCHUNK  16
#define CHUNKT  256
#define CONVDIM 4224
#define DINPROJ 8352
#define NROWS   (BATCH*SEQLEN)
#define LN_EPS  1e-5f

// ---------------- scratch (device globals; no allocations allowed) ----------------
__device__ float g_zxbcdt[(size_t)NROWS * DINPROJ];
__device__ float g_Bv   [NROWS * DSTATE];
__device__ float g_Cv   [NROWS * DSTATE];
__device__ float g_dt   [NROWS * NHEADS];
__device__ float g_dA   [NROWS * NHEADS];
__device__ float g_Acum [BATCH * NHEADS * SEQLEN];
__device__ float g_G    [(size_t)BATCH * NCHUNK * CHUNKT * CHUNKT];
__device__ float g_states[(size_t)BATCH * NCHUNK * NHEADS * HEADDIM * DSTATE];
__device__ float g_prefix[(size_t)BATCH * NCHUNK * NHEADS * HEADDIM * DSTATE];
__device__ float g_y    [(size_t)NROWS * DINNER];

// fp16 buffers (activations exact hi/lo, weights rounded)
__device__ __half g_uh [(size_t)NROWS * DMODEL];
__device__ __half g_ul [(size_t)NROWS * DMODEL];
__device__ __half g_w1h[(size_t)DINPROJ * DMODEL];
__device__ __half g_ynh[(size_t)NROWS * DINNER];
__device__ __half g_ynl[(size_t)NROWS * DINNER];
__device__ __half g_w2h[(size_t)DMODEL * DINNER];
__device__ __half g_xf16[(size_t)NROWS * DINNER];   // rounded fp16 of xdt

__device__ __forceinline__ float siluf(float x) { return x / (1.f + __expf(-x)); }

__device__ __forceinline__ uint32_t smem_u32(const void* p) {
    uint32_t a;
    asm("{ .reg .u64 t; cvta.to.shared.u64 t, %1; cvt.u32.u64 %0, t; }" : "=r"(a) : "l"(p));
    return a;
}

// pack two floats into fp16x2 hi; return hi, write lo (exact 2-term split)
__device__ __forceinline__ uint32_t pack2h(float a, float b, uint32_t& lo) {
    __half ha = __float2half_rn(a), hb = __float2half_rn(b);
    __half la = __float2half_rn(a - __half2float(ha));
    __half lb = __float2half_rn(b - __half2float(hb));
    lo = (uint32_t)__half_as_ushort(la) | ((uint32_t)__half_as_ushort(lb) << 16);
    return (uint32_t)__half_as_ushort(ha) | ((uint32_t)__half_as_ushort(hb) << 16);
}
__device__ __forceinline__ uint32_t rnd2h(float a, float b) {
    return (uint32_t)__half_as_ushort(__float2half_rn(a)) |
           ((uint32_t)__half_as_ushort(__float2half_rn(b)) << 16);
}

// ================= split kernels =================
__global__ void split_f16(const float* __restrict__ src,
                          __half* __restrict__ hi, __half* __restrict__ lo, long n)
{
    long i = (long)blockIdx.x * blockDim.x + threadIdx.x;
    if (i >= n) return;
    float x = src[i];
    __half h = __float2half_rn(x);
    hi[i] = h;
    lo[i] = __float2half_rn(x - __half2float(h));
}
__global__ void round_f16(const float* __restrict__ src, __half* __restrict__ dst, long n)
{
    long i = (long)blockIdx.x * blockDim.x + threadIdx.x;
    if (i >= n) return;
    dst[i] = __float2half_rn(src[i]);
}

// ================= tensor-core primitives =================
__device__ __forceinline__ void mma16816h(float* c, const uint32_t* a, uint32_t b0, uint32_t b1)
{
    asm volatile(
        "mma.sync.aligned.m16n8k16.row.col.f32.f16.f16.f32 "
        "{%0,%1,%2,%3}, {%4,%5,%6,%7}, {%8,%9}, {%0,%1,%2,%3};"
        : "+f"(c[0]), "+f"(c[1]), "+f"(c[2]), "+f"(c[3])
        : "r"(a[0]), "r"(a[1]), "r"(a[2]), "r"(a[3]), "r"(b0), "r"(b1));
}
#define LDSM_X4(r0, r1, r2, r3, addr) \
    asm volatile("ldmatrix.sync.aligned.m8n8.x4.shared.b16 {%0,%1,%2,%3}, [%4];" \
                 : "=r"(r0), "=r"(r1), "=r"(r2), "=r"(r3) : "r"(addr))
#define LDSM_X4_T(r0, r1, r2, r3, addr) \
    asm volatile("ldmatrix.sync.aligned.m8n8.x4.trans.shared.b16 {%0,%1,%2,%3}, [%4];" \
                 : "=r"(r0), "=r"(r1), "=r"(r2), "=r"(r3) : "r"(addr))
#define CP16(dst, src, sz) \
    asm volatile("cp.async.cg.shared.global [%0], [%1], 16, %2;" \
                 :: "r"(dst), "l"(src), "r"(sz))
#define CP_COMMIT() asm volatile("cp.async.commit_group;" ::: "memory")
#define CP_WAIT1()  asm volatile("cp.async.wait_group 1;" ::: "memory")
#define CP_WAIT0()  asm volatile("cp.async.wait_group 0;" ::: "memory")

// ================= fp16 2-MMA GEMM: C = (Ah+Al)*Bh^T + bias =================
// BM=128, BN=256, BK=64, 512 threads (16 warps, 32x64 warp tiles).
// 3-stage cp.async pipeline. A exact fp16 hi/lo (M mult of 128); B rounded fp16.
#define GST 65536
__global__ void __launch_bounds__(512, 1)
mma_gemm_nt(const __half* __restrict__ Ah, const __half* __restrict__ Al,
            const __half* __restrict__ Bh,
            const float* __restrict__ bias, float* __restrict__ C, int N, int K)
{
    extern __shared__ char smem[];
    const uint32_t sb = smem_u32(smem);
    const int tid = threadIdx.x, lane = tid & 31, wid = tid >> 5;
    const int wr = wid >> 2, wc = wid & 3;        // 4x4 warps, each 32(m) x 64(n)
    const int mbase = blockIdx.y * 128;
    const int nbase = blockIdx.x * 256;

    // A loader: 4 thr/row, 2 units; B loader: 2 thr/row, 4 units
    const int ra = tid >> 2, ua0 = (tid & 3) * 2;
    const int rb = tid >> 1, ub0 = (tid & 1) * 4;
    const bool bval = (nbase + rb) < N;
    const uint32_t bsz = bval ? 16u : 0u;
    const __half* gAh = Ah + (size_t)(mbase + ra) * K + ua0 * 8;
    const __half* gAl = Al + (size_t)(mbase + ra) * K + ua0 * 8;
    const __half* gBh = Bh + (size_t)(bval ? nbase + rb : 0) * K + ub0 * 8;
    const uint32_t dA0 = ra * 128 + (( ua0      ^ (ra & 7)) * 16);
    const uint32_t dA1 = ra * 128 + (((ua0 + 1) ^ (ra & 7)) * 16);
    uint32_t dB[4];
#pragma unroll
    for (int j = 0; j < 4; j++) dB[j] = rb * 128 + (((ub0 + j) ^ (rb & 7)) * 16);

    auto issue = [&](int st, int kt) {
        uint32_t s0 = sb + st * GST;
        CP16(s0 + dA0,         gAh + kt,     16);
        CP16(s0 + dA1,         gAh + kt + 8, 16);
        CP16(s0 + 16384 + dA0, gAl + kt,     16);
        CP16(s0 + 16384 + dA1, gAl + kt + 8, 16);
#pragma unroll
        for (int j = 0; j < 4; j++)
            CP16(s0 + 32768 + dB[j], gBh + kt + j * 8, bsz);
        CP_COMMIT();
    };

    float acc[2][8][4];
#pragma unroll
    for (int mt = 0; mt < 2; mt++)
#pragma unroll
        for (int nt = 0; nt < 8; nt++)
#pragma unroll
            for (int i = 0; i < 4; i++) acc[mt][nt][i] = 0.f;

    const int nk = K >> 6;
    issue(0, 0);
    issue(1, 64);

    const int g = lane >> 3, li = lane & 7;
    const int arow_lo = (g & 1) * 8 + li;
    const int ahalf   = g >> 1;
    const int brow_lo = (g >> 1) * 8 + li;
    const int bhalf   = g & 1;

    int stage = 0;
    for (int c = 0; c < nk; c++) {
        if (c + 1 < nk) CP_WAIT1(); else CP_WAIT0();
        __syncthreads();
        if (c + 2 < nk) {
            int st = stage + 2; if (st >= 3) st -= 3;
            issue(st, (c + 2) * 64);
        }
        const uint32_t s0 = sb + stage * GST;
#pragma unroll
        for (int s = 0; s < 4; s++) {
            uint32_t afh[2][4], afl[2][4];
#pragma unroll
            for (int mt = 0; mt < 2; mt++) {
                int row = wr * 32 + mt * 16 + arow_lo;
                uint32_t off = row * 128 + (((2 * s + ahalf) ^ (row & 7)) * 16);
                LDSM_X4(afh[mt][0], afh[mt][1], afh[mt][2], afh[mt][3], s0 + off);
                LDSM_X4(afl[mt][0], afl[mt][1], afl[mt][2], afl[mt][3], s0 + 16384 + off);
            }
#pragma unroll
            for (int ntp = 0; ntp < 4; ntp++) {
                int row = wc * 64 + ntp * 16 + brow_lo;
                uint32_t off = row * 128 + (((2 * s + bhalf) ^ (row & 7)) * 16);
                uint32_t b0, b1, b2, b3;
                LDSM_X4(b0, b1, b2, b3, s0 + 32768 + off);
#pragma unroll
                for (int mt = 0; mt < 2; mt++) {
                    mma16816h(acc[mt][2*ntp+0], afh[mt], b0, b1);
                    mma16816h(acc[mt][2*ntp+0], afl[mt], b0, b1);
                    mma16816h(acc[mt][2*ntp+1], afh[mt], b2, b3);
                    mma16816h(acc[mt][2*ntp+1], afl[mt], b2, b3);
                }
            }
        }
        stage++; if (stage >= 3) stage -= 3;
    }

#pragma unroll
    for (int mt = 0; mt < 2; mt++) {
        int r0 = mbase + wr * 32 + mt * 16 + (lane >> 2);
#pragma unroll
        for (int nt = 0; nt < 8; nt++) {
            int col = nbase + wc * 64 + nt * 8 + (lane & 3) * 2;
            if (col < N) {
                float b0 = bias ? bias[col] : 0.f;
                float b1 = bias ? bias[col + 1] : 0.f;
                float2 v0 = make_float2(acc[mt][nt][0] + b0, acc[mt][nt][1] + b1);
                float2 v1 = make_float2(acc[mt][nt][2] + b0, acc[mt][nt][3] + b1);
                *(float2*)(C + (size_t)r0 * N + col)       = v0;
                *(float2*)(C + (size_t)(r0 + 8) * N + col) = v1;
            }
        }
    }
}

// ---------------- small fp32 NT GEMM (G = C @ B^T) ----------------
__global__ void __launch_bounds__(256)
sgemm_nt(const float* __restrict__ A, const float* __restrict__ B,
         const float* __restrict__ bias, float* __restrict__ C,
         int N, int K, long sA, long sB, long sC)
{
    __shared__ float As[16][128];
    __shared__ float Bs[16][128];
    const int tid  = threadIdx.x;
    const int tcol = tid & 15;
    const int trow = tid >> 4;
    const float* Ab = A + (size_t)blockIdx.z * sA + (size_t)blockIdx.y * 128 * K;
    const float* Bb = B + (size_t)blockIdx.z * sB + (size_t)blockIdx.x * 128 * K;
    const int nbase = blockIdx.x * 128;

    float acc[8][8];
#pragma unroll
    for (int m = 0; m < 8; m++)
#pragma unroll
        for (int n = 0; n < 8; n++) acc[m][n] = 0.f;

    const int lrow = tid >> 2;
    const int lcol = (tid & 3) * 4;

    for (int kt = 0; kt < K; kt += 16) {
#pragma unroll
        for (int it = 0; it < 2; it++) {
            int r = lrow + it * 64;
            float4 va = *(const float4*)(Ab + (size_t)r * K + kt + lcol);
            As[lcol+0][r] = va.x; As[lcol+1][r] = va.y;
            As[lcol+2][r] = va.z; As[lcol+3][r] = va.w;
            float4 vb;
            if (nbase + r < N) vb = *(const float4*)(Bb + (size_t)r * K + kt + lcol);
            else               vb = make_float4(0.f, 0.f, 0.f, 0.f);
            Bs[lcol+0][r] = vb.x; Bs[lcol+1][r] = vb.y;
            Bs[lcol+2][r] = vb.z; Bs[lcol+3][r] = vb.w;
        }
        __syncthreads();
#pragma unroll
        for (int k = 0; k < 16; k++) {
            float ra[8], rb[8];
#pragma unroll
            for (int m = 0; m < 8; m++) ra[m] = As[k][trow * 8 + m];
#pragma unroll
            for (int n = 0; n < 8; n++) rb[n] = Bs[k][tcol * 8 + n];
#pragma unroll
            for (int m = 0; m < 8; m++)
#pragma unroll
                for (int n = 0; n < 8; n++) acc[m][n] = fmaf(ra[m], rb[n], acc[m][n]);
        }
        __syncthreads();
    }
#pragma unroll
    for (int m = 0; m < 8; m++) {
        int row = blockIdx.y * 128 + trow * 8 + m;
#pragma unroll
        for (int n = 0; n < 8; n++) {
            int col = nbase + tcol * 8 + n;
            if (col < N) {
                float bv = bias ? bias[col] : 0.f;
                C[(size_t)blockIdx.z * sC + (size_t)row * N + col] = acc[m][n] + bv;
            }
        }
    }
}

// ---------------- dt: softplus(dt_raw + bias), dA = -exp(A_log)*dt ----------------
__global__ void dt_kernel(const float* __restrict__ dt_bias, const float* __restrict__ A_log)
{
    int idx = blockIdx.x * blockDim.x + threadIdx.x;
    if (idx >= NROWS * NHEADS) return;
    int h = idx & (NHEADS - 1);
    int r = idx >> 5;
    float v = g_zxbcdt[(size_t)r * DINPROJ + DINNER + CONVDIM + h] + dt_bias[h];
    float dt = (v > 20.f) ? v : log1pf(__expf(v));
    g_dt[idx] = dt;
    g_dA[idx] = -__expf(A_log[h]) * dt;
}

// ---------------- causal depthwise conv + SiLU; split x*dt / B / C ----------------
__global__ void conv_kernel(const float* __restrict__ w, const float* __restrict__ cb)
{
    long idx = (long)blockIdx.x * blockDim.x + threadIdx.x;
    if (idx >= (long)NROWS * CONVDIM) return;
    int c = (int)(idx % CONVDIM);
    int r = (int)(idx / CONVDIM);
    int l = r & (SEQLEN - 1);
    float acc = cb[c];
#pragma unroll
    for (int k = 0; k < 4; k++) {
        int lp = l - 3 + k;
        if (lp >= 0)
            acc = fmaf(w[c * 4 + k], g_zxbcdt[(size_t)(r - 3 + k) * DINPROJ + DINNER + c], acc);
    }
    float out = siluf(acc);
    if (c < DINNER) {
        float v = out * g_dt[r * NHEADS + (c >> 7)];
        g_xf16[(size_t)r * DINNER + c] = __float2half_rn(v);
    } else if (c < DINNER + DSTATE) {
        g_Bv[r * DSTATE + (c - DINNER)] = out;
    } else {
        g_Cv[r * DSTATE + (c - DINNER - DSTATE)] = out;
    }
}

// ---------------- per-chunk inclusive cumsum of dA ----------------
__global__ void cumsum_kernel()
{
    int c = blockIdx.x, h = blockIdx.y, b = blockIdx.z;
    int t = threadIdx.x;
    __shared__ float s[CHUNKT];
    int row = b * SEQLEN + c * CHUNKT + t;
    s[t] = g_dA[row * NHEADS + h];
    __syncthreads();
#pragma unroll
    for (int off = 1; off < CHUNKT; off <<= 1) {
        float x = (t >= off) ? s[t - off] : 0.f;
        __syncthreads();
        s[t] += x;
        __syncthreads();
    }
    g_Acum[(b * NHEADS + h) * SEQLEN + c * CHUNKT + t] = s[t];
}

// ---------------- chunk-local states on tensor cores ----------------
// S[p(128)][n(64)] = sum_l X[l][p] * (B[l][n] * exp(Atot - Ac[l])), K = 256
// A = X^T via ldmatrix.trans (X smem [l][p], 256B rows);
// B = Bsc via ldmatrix.trans (Bsc smem [l][n] fp16, 128B rows).
__global__ void __launch_bounds__(256) states_mma()
{
    __shared__ __align__(16) char sX[64 * 256];    // 16KB
    __shared__ __align__(16) char sB[64 * 128];    // 8KB
    __shared__ float Ac[CHUNKT];
    const int h = blockIdx.x, c = blockIdx.y, b = blockIdx.z;
    const int tid = threadIdx.x, lane = tid & 31, wid = tid >> 5;
    const int wr = wid >> 1, wc = wid & 1;         // 4x2 warps, 32(p) x 32(n)
    const int brow = b * SEQLEN + c * CHUNKT;
    const uint32_t sbX = smem_u32(sX), sbB = smem_u32(sB);

    Ac[tid] = g_Acum[(b * NHEADS + h) * SEQLEN + c * CHUNKT + tid];
    __syncthreads();
    const float Atot = Ac[CHUNKT - 1];

    float acc[2][4][4];
#pragma unroll
    for (int mt = 0; mt < 2; mt++)
#pragma unroll
        for (int nt = 0; nt < 4; nt++)
#pragma unroll
            for (int i = 0; i < 4; i++) acc[mt][nt][i] = 0.f;

    const int g = lane >> 3, li = lane & 7;
    // A trans: a0=(m0-7,k0-7) a1=(m8-15,k0-7) a2=(m0-7,k8-15) a3=(m8-15,k8-15)
    const int akr = (g >> 1) * 8 + li;   // k-row within 16
    const int amc = (g & 1) * 8;         // m-col half
    // B trans: b0=(k0-7,n0-7) b1=(k8-15,n0-7) b2,b3 = n8-15
    const int bkr = (g & 1) * 8 + li;
    const int bnc = (g >> 1) * 8;

    for (int lt = 0; lt < CHUNKT; lt += 64) {
        if (lt) __syncthreads();
        // stage X [64][128] fp16 (256B rows, swizzled)
        for (int idx = tid; idx < 64 * 16; idx += 256) {
            int l = idx >> 4, u = idx & 15;
            size_t src = (size_t)(brow + lt + l) * DINNER + h * HEADDIM + u * 8;
            uint32_t dst = l * 256 + ((u ^ (l & 7)) * 16);
            *(uint4*)(sX + dst) = *(const uint4*)(g_xf16 + src);
        }
        // stage Bsc [64][64] fp16 (128B rows, swizzled)
        for (int idx = tid; idx < 64 * 16; idx += 256) {
            int l = idx >> 4, u4 = idx & 15;
            float4 bv = *(const float4*)&g_Bv[(size_t)(brow + lt + l) * DSTATE + u4 * 4];
            float e = __expf(Atot - Ac[lt + l]);
            uint32_t h01 = rnd2h(bv.x * e, bv.y * e);
            uint32_t h23 = rnd2h(bv.z * e, bv.w * e);
            uint32_t dst = l * 128 + (((u4 >> 1) ^ (l & 7)) * 16) + (u4 & 1) * 8;
            *(uint2*)(sB + dst) = make_uint2(h01, h23);
        }
        __syncthreads();
#pragma unroll
        for (int s = 0; s < 4; s++) {
            uint32_t af[2][4];
#pragma unroll
            for (int mt = 0; mt < 2; mt++) {
                int kr = s * 16 + akr;
                int mc = wr * 32 + mt * 16 + amc;
                uint32_t off = kr * 256 + (((mc >> 3) ^ (kr & 7)) * 16);
                LDSM_X4_T(af[mt][0], af[mt][1], af[mt][2], af[mt][3], sbX + off);
            }
#pragma unroll
            for (int ntp = 0; ntp < 2; ntp++) {
                int kr = s * 16 + bkr;
                int nc = wc * 32 + ntp * 16 + bnc;
                uint32_t off = kr * 128 + (((nc >> 3) ^ (kr & 7)) * 16);
                uint32_t b0, b1, b2, b3;
                LDSM_X4_T(b0, b1, b2, b3, sbB + off);
#pragma unroll
                for (int mt = 0; mt < 2; mt++) {
                    mma16816h(acc[mt][2*ntp+0], af[mt], b0, b1);
                    mma16816h(acc[mt][2*ntp+1], af[mt], b2, b3);
                }
            }
        }
    }

    size_t base = ((size_t)((b * NCHUNK + c) * NHEADS + h)) * HEADDIM * DSTATE;
#pragma unroll
    for (int mt = 0; mt < 2; mt++) {
        int p0 = wr * 32 + mt * 16 + (lane >> 2);
#pragma unroll
        for (int nt = 0; nt < 4; nt++) {
            int n = wc * 32 + nt * 8 + (lane & 3) * 2;
            *(float2*)(g_states + base + (size_t)p0 * DSTATE + n) =
                make_float2(acc[mt][nt][0], acc[mt][nt][1]);
            *(float2*)(g_states + base + (size_t)(p0 + 8) * DSTATE + n) =
                make_float2(acc[mt][nt][2], acc[mt][nt][3]);
        }
    }
}

// ---------------- inter-chunk state scan (8-way split per (b,h)) ----------------
__global__ void scan_kernel()
{
    int bh = blockIdx.x >> 3, seg = blockIdx.x & 7;
    int b = bh >> 5, h = bh & 31;
    int t = threadIdx.x;
    size_t off = (size_t)seg * 1024 + (size_t)t * 4;
    float4 S = make_float4(0.f, 0.f, 0.f, 0.f);
    for (int c = 0; c < NCHUNK; c++) {
        size_t base = ((size_t)((b * NCHUNK + c) * NHEADS + h)) * (HEADDIM * DSTATE) + off;
        *(float4*)(g_prefix + base) = S;
        float f = __expf(g_Acum[(b * NHEADS + h) * SEQLEN + c * CHUNKT + CHUNKT - 1]);
        float4 st = *(const float4*)(g_states + base);
        S.x = S.x * f + st.x;
        S.y = S.y * f + st.y;
        S.z = S.z * f + st.z;
        S.w = S.w * f + st.w;
    }
}

// ================= fused Y on tensor cores (fp16 2-term) =================
// smem: WH 0 (32K) | WL 32768 (32K) | X/S 65536 (16K) | Ac 81920 | eAc 82944
#define YSMEM 84992
__global__ void __launch_bounds__(512, 1) yfused_mma()
{
    extern __shared__ char ysm[];
    const uint32_t sb = smem_u32(ysm);
    float* Ac  = (float*)(ysm + 81920);
    float* eAc = (float*)(ysm + 82944);
    const int h = blockIdx.x, c = blockIdx.y, b = blockIdx.z;
    const int tid = threadIdx.x, lane = tid & 31, wid = tid >> 5;
    const int wr = wid >> 2, wc = wid & 3;     // warp tile 64(i) x 32(p)
    const int brow = b * SEQLEN + c * CHUNKT;
    const size_t gbase = (size_t)(b * NCHUNK + c) * CHUNKT * CHUNKT;
    const size_t sbase = ((size_t)((b * NCHUNK + c) * NHEADS + h)) * (HEADDIM * DSTATE);

    if (tid < CHUNKT) {
        float a = g_Acum[(b * NHEADS + h) * SEQLEN + c * CHUNKT + tid];
        Ac[tid] = a;
        eAc[tid] = __expf(a);
    }

    float acc[4][4][4];
#pragma unroll
    for (int mt = 0; mt < 4; mt++)
#pragma unroll
        for (int nt = 0; nt < 4; nt++)
#pragma unroll
            for (int i = 0; i < 4; i++) acc[mt][nt][i] = 0.f;

    const int g = lane >> 3, li = lane & 7;
    const int arow  = (g & 1) * 8 + li;
    const int ahalf = g >> 1;
    const int bkt   = (g & 1) * 8 + li;
    const int bnt   = (g >> 1) * 8;
    const int brw2  = (g >> 1) * 8 + li;
    const int bhf2  = g & 1;

    // ---- part 1: W @ X over 4 j-tiles of 64 ----
    for (int jt = 0; jt < CHUNKT; jt += 64) {
        __syncthreads();
        for (int idx = tid; idx < 256 * 16; idx += 512) {
            int i = idx >> 4, u4 = idx & 15;
            float4 gv = *(const float4*)&g_G[gbase + (size_t)i * 256 + jt + u4 * 4];
            float ai = Ac[i];
            int j0 = jt + u4 * 4;
            float v0 = (j0 + 0 <= i) ? __expf(ai - Ac[j0 + 0]) * gv.x : 0.f;
            float v1 = (j0 + 1 <= i) ? __expf(ai - Ac[j0 + 1]) * gv.y : 0.f;
            float v2 = (j0 + 2 <= i) ? __expf(ai - Ac[j0 + 2]) * gv.z : 0.f;
            float v3 = (j0 + 3 <= i) ? __expf(ai - Ac[j0 + 3]) * gv.w : 0.f;
            uint32_t lo01, lo23;
            uint32_t hi01 = pack2h(v0, v1, lo01);
            uint32_t hi23 = pack2h(v2, v3, lo23);
            uint32_t base = i * 128 + (((u4 >> 1) ^ (i & 7)) * 16) + (u4 & 1) * 8;
            *(uint2*)(ysm + base)         = make_uint2(hi01, hi23);
            *(uint2*)(ysm + 32768 + base) = make_uint2(lo01, lo23);
        }
        for (int idx = tid; idx < 64 * 16; idx += 512) {
            int l = idx >> 4, u = idx & 15;
            size_t src = (size_t)(brow + jt + l) * DINNER + h * HEADDIM + u * 8;
            uint32_t dst = l * 256 + ((u ^ (l & 7)) * 16);
            *(uint4*)(ysm + 65536 + dst) = *(const uint4*)(g_xf16 + src);
        }
        __syncthreads();
        if (wr * 64 + 63 >= jt) {
#pragma unroll
            for (int s = 0; s < 4; s++) {
                uint32_t afh[4][4], afl[4][4];
#pragma unroll
                for (int mt = 0; mt < 4; mt++) {
                    int row = wr * 64 + mt * 16 + arow;
                    uint32_t off = row * 128 + (((2 * s + ahalf) ^ (row & 7)) * 16);
                    LDSM_X4(afh[mt][0], afh[mt][1], afh[mt][2], afh[mt][3], sb + off);
                    LDSM_X4(afl[mt][0], afl[mt][1], afl[mt][2], afl[mt][3], sb + 32768 + off);
                }
#pragma unroll
                for (int ntp = 0; ntp < 2; ntp++) {
                    int krow = s * 16 + bkt;
                    int p = wc * 32 + ntp * 16 + bnt;
                    uint32_t off = krow * 256 + (((p >> 3) ^ (krow & 7)) * 16);
                    uint32_t b0, b1, b2, b3;
                    LDSM_X4_T(b0, b1, b2, b3, sb + 65536 + off);
#pragma unroll
                    for (int mt = 0; mt < 4; mt++) {
                        mma16816h(acc[mt][2*ntp+0], afh[mt], b0, b1);
                        mma16816h(acc[mt][2*ntp+0], afl[mt], b0, b1);
                        mma16816h(acc[mt][2*ntp+1], afh[mt], b2, b3);
                        mma16816h(acc[mt][2*ntp+1], afl[mt], b2, b3);
                    }
                }
            }
        }
    }

    // ---- part 2: Ce @ S^T (K = 64) ----
    __syncthreads();
    for (int idx = tid; idx < 256 * 16; idx += 512) {
        int i = idx >> 4, u4 = idx & 15;
        float4 cv = *(const float4*)&g_Cv[(size_t)(brow + i) * 64 + u4 * 4];
        float e = eAc[i];
        uint32_t lo01, lo23;
        uint32_t hi01 = pack2h(cv.x * e, cv.y * e, lo01);
        uint32_t hi23 = pack2h(cv.z * e, cv.w * e, lo23);
        uint32_t base = i * 128 + (((u4 >> 1) ^ (i & 7)) * 16) + (u4 & 1) * 8;
        *(uint2*)(ysm + base)         = make_uint2(hi01, hi23);
        *(uint2*)(ysm + 32768 + base) = make_uint2(lo01, lo23);
    }
    for (int idx = tid; idx < 128 * 16; idx += 512) {
        int p = idx >> 4, u4 = idx & 15;
        float4 sv = *(const float4*)&g_prefix[sbase + (size_t)p * 64 + u4 * 4];
        uint32_t h01 = rnd2h(sv.x, sv.y);
        uint32_t h23 = rnd2h(sv.z, sv.w);
        uint32_t base = p * 128 + (((u4 >> 1) ^ (p & 7)) * 16) + (u4 & 1) * 8;
        *(uint2*)(ysm + 65536 + base) = make_uint2(h01, h23);
    }
    __syncthreads();
#pragma unroll
    for (int s = 0; s < 4; s++) {
        uint32_t afh[4][4], afl[4][4];
#pragma unroll
        for (int mt = 0; mt < 4; mt++) {
            int row = wr * 64 + mt * 16 + arow;
            uint32_t off = row * 128 + (((2 * s + ahalf) ^ (row & 7)) * 16);
            LDSM_X4(afh[mt][0], afh[mt][1], afh[mt][2], afh[mt][3], sb + off);
            LDSM_X4(afl[mt][0], afl[mt][1], afl[mt][2], afl[mt][3], sb + 32768 + off);
        }
#pragma unroll
        for (int ntp = 0; ntp < 2; ntp++) {
            int row = wc * 32 + ntp * 16 + brw2;
            uint32_t off = row * 128 + (((2 * s + bhf2) ^ (row & 7)) * 16);
            uint32_t b0, b1, b2, b3;
            LDSM_X4(b0, b1, b2, b3, sb + 65536 + off);
#pragma unroll
            for (int mt = 0; mt < 4; mt++) {
                mma16816h(acc[mt][2*ntp+0], afh[mt], b0, b1);
                mma16816h(acc[mt][2*ntp+0], afl[mt], b0, b1);
                mma16816h(acc[mt][2*ntp+1], afh[mt], b2, b3);
                mma16816h(acc[mt][2*ntp+1], afl[mt], b2, b3);
            }
        }
    }

    // ---- epilogue ----
#pragma unroll
    for (int mt = 0; mt < 4; mt++) {
        int i0 = wr * 64 + mt * 16 + (lane >> 2);
#pragma unroll
        for (int nt = 0; nt < 4; nt++) {
            int col = h * HEADDIM + wc * 32 + nt * 8 + (lane & 3) * 2;
            *(float2*)(g_y + (size_t)(brow + i0) * DINNER + col) =
                make_float2(acc[mt][nt][0], acc[mt][nt][1]);
            *(float2*)(g_y + (size_t)(brow + i0 + 8) * DINNER + col) =
                make_float2(acc[mt][nt][2], acc[mt][nt][3]);
        }
    }
}

// ---------------- gating (y * silu(z)) + LayerNorm; emits fp16 hi/lo ----------------
__global__ void __launch_bounds__(256) ln_kernel(const float* __restrict__ lnw, const float* __restrict__ lnb)
{
    int row = blockIdx.x;
    int tid = threadIdx.x;
    float g[16];
    float s = 0.f, s2 = 0.f;
#pragma unroll
    for (int q = 0; q < 16; q++) {
        int i = tid + q * 256;
        float y = g_y[(size_t)row * DINNER + i];
        float z = g_zxbcdt[(size_t)row * DINPROJ + i];
        float v = y * siluf(z);
        g[q] = v; s += v; s2 = fmaf(v, v, s2);
    }
    __shared__ float red[2][8];
#pragma unroll
    for (int off = 16; off > 0; off >>= 1) {
        s  += __shfl_xor_sync(0xffffffffu, s, off);
        s2 += __shfl_xor_sync(0xffffffffu, s2, off);
    }
    if ((tid & 31) == 0) { red[0][tid >> 5] = s; red[1][tid >> 5] = s2; }
    __syncthreads();
    if (tid == 0) {
        float a = 0.f, a2 = 0.f;
#pragma unroll
        for (int w = 0; w < 8; w++) { a += red[0][w]; a2 += red[1][w]; }
        red[0][0] = a; red[1][0] = a2;
    }
    __syncthreads();
    float mu  = red[0][0] * (1.f / DINNER);
    float var = red[1][0] * (1.f / DINNER) - mu * mu;
    float rstd = rsqrtf(var + LN_EPS);
#pragma unroll
    for (int q = 0; q < 16; q++) {
        int i = tid + q * 256;
        float v = (g[q] - mu) * rstd * lnw[i] + lnb[i];
        __half hh = __float2half_rn(v);
        g_ynh[(size_t)row * DINNER + i] = hh;
        g_ynl[(size_t)row * DINNER + i] = __float2half_rn(v - __half2float(hh));
    }
}

// ---------------- launch ----------------
extern "C" void kernel_launch(void* const* d_in, const int* in_sizes, int n_in,
                              void* d_out, int out_size)
{
    const float* u          = (const float*)d_in[0];
    const float* in_proj_w  = (const float*)d_in[1];
    const float* in_proj_b  = (const float*)d_in[2];
    const float* conv_w     = (const float*)d_in[3];
    const float* conv_b     = (const float*)d_in[4];
    const float* dt_bias    = (const float*)d_in[5];
    const float* A_log      = (const float*)d_in[6];
    const float* ln_w       = (const float*)d_in[7];
    const float* ln_b       = (const float*)d_in[8];
    const float* out_proj_w = (const float*)d_in[9];
    const float* out_proj_b = (const float*)d_in[10];
    float* out = (float*)d_out;

    float *zx, *gB, *gC, *gG;
    __half *uh, *ul, *w1h, *ynh, *ynl, *w2h;
    cudaGetSymbolAddress((void**)&zx,  g_zxbcdt);
    cudaGetSymbolAddress((void**)&gB,  g_Bv);
    cudaGetSymbolAddress((void**)&gC,  g_Cv);
    cudaGetSymbolAddress((void**)&gG,  g_G);
    cudaGetSymbolAddress((void**)&uh,  g_uh);
    cudaGetSymbolAddress((void**)&ul,  g_ul);
    cudaGetSymbolAddress((void**)&w1h, g_w1h);
    cudaGetSymbolAddress((void**)&ynh, g_ynh);
    cudaGetSymbolAddress((void**)&ynl, g_ynl);
    cudaGetSymbolAddress((void**)&w2h, g_w2h);

    cudaFuncSetAttribute(mma_gemm_nt, cudaFuncAttributeMaxDynamicSharedMemorySize, 3 * GST);
    cudaFuncSetAttribute(yfused_mma, cudaFuncAttributeMaxDynamicSharedMemorySize, YSMEM);

    // 0) fp32 -> fp16 conversions
    {
        long n1 = (long)NROWS * DMODEL;
        split_f16<<<(unsigned)((n1 + 255) / 256), 256>>>(u, uh, ul, n1);
        long n2 = (long)DINPROJ * DMODEL;
        round_f16<<<(unsigned)((n2 + 255) / 256), 256>>>(in_proj_w, w1h, n2);
        long n3 = (long)DMODEL * DINNER;
        round_f16<<<(unsigned)((n3 + 255) / 256), 256>>>(out_proj_w, w2h, n3);
    }

    // 1) in_proj: M=8192, N=8352, K=2048
    mma_gemm_nt<<<dim3((DINPROJ + 255) / 256, NROWS / 128), 512, 3 * GST>>>(
        uh, ul, w1h, in_proj_b, zx, DINPROJ, DMODEL);

    // 2) dt softplus + dA
    dt_kernel<<<(NROWS * NHEADS) / 256, 256>>>(dt_bias, A_log);

    // 3) causal conv + silu + split
    {
        long total = (long)NROWS * CONVDIM;
        conv_kernel<<<(unsigned)((total + 255) / 256), 256>>>(conv_w, conv_b);
    }

    // 4) per-chunk cumsum of dA
    cumsum_kernel<<<dim3(NCHUNK, NHEADS, BATCH), CHUNKT>>>();

    // 5) G = C @ B^T per (b,chunk)
    sgemm_nt<<<dim3(2, 2, BATCH * NCHUNK), 256>>>(
        gC, gB, nullptr, gG, CHUNKT, DSTATE,
        (long)CHUNKT * DSTATE, (long)CHUNKT * DSTATE, (long)CHUNKT * CHUNKT);

    // 6) chunk-local states on tensor cores
    states_mma<<<dim3(NHEADS, NCHUNK, BATCH), 256>>>();

    // 7) inter-chunk scan (8-way split)
    scan_kernel<<<BATCH * NHEADS * 8, 256>>>();

    // 8) fused Y on tensor cores
    yfused_mma<<<dim3(NHEADS, NCHUNK, BATCH), 512, YSMEM>>>();

    // 9) gate + layernorm (+ fp16 split of yn)
    ln_kernel<<<NROWS, 256>>>(ln_w, ln_b);

    // 10) out_proj: M=8192, N=2048, K=4096
    mma_gemm_nt<<<dim3(DMODEL / 256, NROWS / 128), 512, 3 * GST>>>(
        ynh, ynl, w2h, out_proj_b, out, DMODEL, DINNER);
}

// round 12
// speedup vs baseline: 1.1699x; 1.0586x over previous
#include <cuda_runtime.h>
#include <cuda_bf16.h>
#include <cuda_fp16.h>
#include <cstdint>
#include <math.h>

#define BATCH   2
#define SEQLEN  4096
#define DMODEL  2048
#define DINNER  4096
#define NHEADS  32
#define HEADDIM 128
#define DSTATE  64
#define NCHUNK  16
#define CHUNKT  256
#define CONVDIM 4224
#define DINPROJ 8352
#define NROWS   (BATCH*SEQLEN)
#define LN_EPS  1e-5f

// ---------------- scratch (device globals; no allocations allowed) ----------------
__device__ float g_zxbcdt[(size_t)NROWS * DINPROJ];
__device__ float g_Bv   [NROWS * DSTATE];
__device__ float g_Cv   [NROWS * DSTATE];
__device__ float g_dt   [NROWS * NHEADS];
__device__ float g_Acum [BATCH * NHEADS * SEQLEN];
__device__ float g_G    [(size_t)BATCH * NCHUNK * CHUNKT * CHUNKT];
__device__ float g_states[(size_t)BATCH * NCHUNK * NHEADS * HEADDIM * DSTATE];
__device__ float g_prefix[(size_t)BATCH * NCHUNK * NHEADS * HEADDIM * DSTATE];
__device__ float g_y    [(size_t)NROWS * DINNER];

// fp16 buffers (activations exact hi/lo, weights rounded)
__device__ __half g_uh [(size_t)NROWS * DMODEL];
__device__ __half g_ul [(size_t)NROWS * DMODEL];
__device__ __half g_w1h[(size_t)DINPROJ * DMODEL];
__device__ __half g_ynh[(size_t)NROWS * DINNER];
__device__ __half g_ynl[(size_t)NROWS * DINNER];
__device__ __half g_w2h[(size_t)DMODEL * DINNER];
__device__ __half g_xf16[(size_t)NROWS * DINNER];   // rounded fp16 of xdt

__device__ __forceinline__ float siluf(float x) { return x / (1.f + __expf(-x)); }

__device__ __forceinline__ uint32_t smem_u32(const void* p) {
    uint32_t a;
    asm("{ .reg .u64 t; cvta.to.shared.u64 t, %1; cvt.u32.u64 %0, t; }" : "=r"(a) : "l"(p));
    return a;
}

// pack two floats into fp16x2 hi; return hi, write lo (exact 2-term split)
__device__ __forceinline__ uint32_t pack2h(float a, float b, uint32_t& lo) {
    __half ha = __float2half_rn(a), hb = __float2half_rn(b);
    __half la = __float2half_rn(a - __half2float(ha));
    __half lb = __float2half_rn(b - __half2float(hb));
    lo = (uint32_t)__half_as_ushort(la) | ((uint32_t)__half_as_ushort(lb) << 16);
    return (uint32_t)__half_as_ushort(ha) | ((uint32_t)__half_as_ushort(hb) << 16);
}
__device__ __forceinline__ uint32_t rnd2h(float a, float b) {
    return (uint32_t)__half_as_ushort(__float2half_rn(a)) |
           ((uint32_t)__half_as_ushort(__float2half_rn(b)) << 16);
}

// ================= split kernels (float4 vectorized; n divisible by 4) =================
__global__ void split_f16(const float* __restrict__ src,
                          __half* __restrict__ hi, __half* __restrict__ lo, long n4)
{
    long i = (long)blockIdx.x * blockDim.x + threadIdx.x;
    if (i >= n4) return;
    float4 x = ((const float4*)src)[i];
    uint32_t l01, l23;
    uint32_t h01 = pack2h(x.x, x.y, l01);
    uint32_t h23 = pack2h(x.z, x.w, l23);
    ((uint2*)hi)[i] = make_uint2(h01, h23);
    ((uint2*)lo)[i] = make_uint2(l01, l23);
}
__global__ void round_f16(const float* __restrict__ src, __half* __restrict__ dst, long n4)
{
    long i = (long)blockIdx.x * blockDim.x + threadIdx.x;
    if (i >= n4) return;
    float4 x = ((const float4*)src)[i];
    ((uint2*)dst)[i] = make_uint2(rnd2h(x.x, x.y), rnd2h(x.z, x.w));
}

// ================= tensor-core primitives =================
__device__ __forceinline__ void mma16816h(float* c, const uint32_t* a, uint32_t b0, uint32_t b1)
{
    asm volatile(
        "mma.sync.aligned.m16n8k16.row.col.f32.f16.f16.f32 "
        "{%0,%1,%2,%3}, {%4,%5,%6,%7}, {%8,%9}, {%0,%1,%2,%3};"
        : "+f"(c[0]), "+f"(c[1]), "+f"(c[2]), "+f"(c[3])
        : "r"(a[0]), "r"(a[1]), "r"(a[2]), "r"(a[3]), "r"(b0), "r"(b1));
}
#define LDSM_X4(r0, r1, r2, r3, addr) \
    asm volatile("ldmatrix.sync.aligned.m8n8.x4.shared.b16 {%0,%1,%2,%3}, [%4];" \
                 : "=r"(r0), "=r"(r1), "=r"(r2), "=r"(r3) : "r"(addr))
#define LDSM_X4_T(r0, r1, r2, r3, addr) \
    asm volatile("ldmatrix.sync.aligned.m8n8.x4.trans.shared.b16 {%0,%1,%2,%3}, [%4];" \
                 : "=r"(r0), "=r"(r1), "=r"(r2), "=r"(r3) : "r"(addr))
#define CP16(dst, src, sz) \
    asm volatile("cp.async.cg.shared.global [%0], [%1], 16, %2;" \
                 :: "r"(dst), "l"(src), "r"(sz))
#define CP_COMMIT() asm volatile("cp.async.commit_group;" ::: "memory")
#define CP_WAIT1()  asm volatile("cp.async.wait_group 1;" ::: "memory")
#define CP_WAIT0()  asm volatile("cp.async.wait_group 0;" ::: "memory")

// ================= fp16 2-MMA GEMM: C = (Ah+Al)*Bh^T + bias =================
// BM=128, BN=256, BK=64, 512 threads (16 warps, 32x64 warp tiles).
// 3-stage cp.async pipeline. A exact fp16 hi/lo (M mult of 128); B rounded fp16.
#define GST 65536
__global__ void __launch_bounds__(512, 1)
mma_gemm_nt(const __half* __restrict__ Ah, const __half* __restrict__ Al,
            const __half* __restrict__ Bh,
            const float* __restrict__ bias, float* __restrict__ C, int N, int K)
{
    extern __shared__ char smem[];
    const uint32_t sb = smem_u32(smem);
    const int tid = threadIdx.x, lane = tid & 31, wid = tid >> 5;
    const int wr = wid >> 2, wc = wid & 3;        // 4x4 warps, each 32(m) x 64(n)
    const int mbase = blockIdx.y * 128;
    const int nbase = blockIdx.x * 256;

    // A loader: 4 thr/row, 2 units; B loader: 2 thr/row, 4 units
    const int ra = tid >> 2, ua0 = (tid & 3) * 2;
    const int rb = tid >> 1, ub0 = (tid & 1) * 4;
    const bool bval = (nbase + rb) < N;
    const uint32_t bsz = bval ? 16u : 0u;
    const __half* gAh = Ah + (size_t)(mbase + ra) * K + ua0 * 8;
    const __half* gAl = Al + (size_t)(mbase + ra) * K + ua0 * 8;
    const __half* gBh = Bh + (size_t)(bval ? nbase + rb : 0) * K + ub0 * 8;
    const uint32_t dA0 = ra * 128 + (( ua0      ^ (ra & 7)) * 16);
    const uint32_t dA1 = ra * 128 + (((ua0 + 1) ^ (ra & 7)) * 16);
    uint32_t dB[4];
#pragma unroll
    for (int j = 0; j < 4; j++) dB[j] = rb * 128 + (((ub0 + j) ^ (rb & 7)) * 16);

    auto issue = [&](int st, int kt) {
        uint32_t s0 = sb + st * GST;
        CP16(s0 + dA0,         gAh + kt,     16);
        CP16(s0 + dA1,         gAh + kt + 8, 16);
        CP16(s0 + 16384 + dA0, gAl + kt,     16);
        CP16(s0 + 16384 + dA1, gAl + kt + 8, 16);
#pragma unroll
        for (int j = 0; j < 4; j++)
            CP16(s0 + 32768 + dB[j], gBh + kt + j * 8, bsz);
        CP_COMMIT();
    };

    float acc[2][8][4];
#pragma unroll
    for (int mt = 0; mt < 2; mt++)
#pragma unroll
        for (int nt = 0; nt < 8; nt++)
#pragma unroll
            for (int i = 0; i < 4; i++) acc[mt][nt][i] = 0.f;

    const int nk = K >> 6;
    issue(0, 0);
    issue(1, 64);

    const int g = lane >> 3, li = lane & 7;
    const int arow_lo = (g & 1) * 8 + li;
    const int ahalf   = g >> 1;
    const int brow_lo = (g >> 1) * 8 + li;
    const int bhalf   = g & 1;

    int stage = 0;
    for (int c = 0; c < nk; c++) {
        if (c + 1 < nk) CP_WAIT1(); else CP_WAIT0();
        __syncthreads();
        if (c + 2 < nk) {
            int st = stage + 2; if (st >= 3) st -= 3;
            issue(st, (c + 2) * 64);
        }
        const uint32_t s0 = sb + stage * GST;
#pragma unroll
        for (int s = 0; s < 4; s++) {
            uint32_t afh[2][4], afl[2][4];
#pragma unroll
            for (int mt = 0; mt < 2; mt++) {
                int row = wr * 32 + mt * 16 + arow_lo;
                uint32_t off = row * 128 + (((2 * s + ahalf) ^ (row & 7)) * 16);
                LDSM_X4(afh[mt][0], afh[mt][1], afh[mt][2], afh[mt][3], s0 + off);
                LDSM_X4(afl[mt][0], afl[mt][1], afl[mt][2], afl[mt][3], s0 + 16384 + off);
            }
#pragma unroll
            for (int ntp = 0; ntp < 4; ntp++) {
                int row = wc * 64 + ntp * 16 + brow_lo;
                uint32_t off = row * 128 + (((2 * s + bhalf) ^ (row & 7)) * 16);
                uint32_t b0, b1, b2, b3;
                LDSM_X4(b0, b1, b2, b3, s0 + 32768 + off);
#pragma unroll
                for (int mt = 0; mt < 2; mt++) {
                    mma16816h(acc[mt][2*ntp+0], afh[mt], b0, b1);
                    mma16816h(acc[mt][2*ntp+0], afl[mt], b0, b1);
                    mma16816h(acc[mt][2*ntp+1], afh[mt], b2, b3);
                    mma16816h(acc[mt][2*ntp+1], afl[mt], b2, b3);
                }
            }
        }
        stage++; if (stage >= 3) stage -= 3;
    }

#pragma unroll
    for (int mt = 0; mt < 2; mt++) {
        int r0 = mbase + wr * 32 + mt * 16 + (lane >> 2);
#pragma unroll
        for (int nt = 0; nt < 8; nt++) {
            int col = nbase + wc * 64 + nt * 8 + (lane & 3) * 2;
            if (col < N) {
                float b0 = bias ? bias[col] : 0.f;
                float b1 = bias ? bias[col + 1] : 0.f;
                float2 v0 = make_float2(acc[mt][nt][0] + b0, acc[mt][nt][1] + b1);
                float2 v1 = make_float2(acc[mt][nt][2] + b0, acc[mt][nt][3] + b1);
                *(float2*)(C + (size_t)r0 * N + col)       = v0;
                *(float2*)(C + (size_t)(r0 + 8) * N + col) = v1;
            }
        }
    }
}

// ---------------- small fp32 NT GEMM (G = C @ B^T) ----------------
__global__ void __launch_bounds__(256)
sgemm_nt(const float* __restrict__ A, const float* __restrict__ B,
         const float* __restrict__ bias, float* __restrict__ C,
         int N, int K, long sA, long sB, long sC)
{
    __shared__ float As[16][128];
    __shared__ float Bs[16][128];
    const int tid  = threadIdx.x;
    const int tcol = tid & 15;
    const int trow = tid >> 4;
    const float* Ab = A + (size_t)blockIdx.z * sA + (size_t)blockIdx.y * 128 * K;
    const float* Bb = B + (size_t)blockIdx.z * sB + (size_t)blockIdx.x * 128 * K;
    const int nbase = blockIdx.x * 128;

    float acc[8][8];
#pragma unroll
    for (int m = 0; m < 8; m++)
#pragma unroll
        for (int n = 0; n < 8; n++) acc[m][n] = 0.f;

    const int lrow = tid >> 2;
    const int lcol = (tid & 3) * 4;

    for (int kt = 0; kt < K; kt += 16) {
#pragma unroll
        for (int it = 0; it < 2; it++) {
            int r = lrow + it * 64;
            float4 va = *(const float4*)(Ab + (size_t)r * K + kt + lcol);
            As[lcol+0][r] = va.x; As[lcol+1][r] = va.y;
            As[lcol+2][r] = va.z; As[lcol+3][r] = va.w;
            float4 vb;
            if (nbase + r < N) vb = *(const float4*)(Bb + (size_t)r * K + kt + lcol);
            else               vb = make_float4(0.f, 0.f, 0.f, 0.f);
            Bs[lcol+0][r] = vb.x; Bs[lcol+1][r] = vb.y;
            Bs[lcol+2][r] = vb.z; Bs[lcol+3][r] = vb.w;
        }
        __syncthreads();
#pragma unroll
        for (int k = 0; k < 16; k++) {
            float ra[8], rb[8];
#pragma unroll
            for (int m = 0; m < 8; m++) ra[m] = As[k][trow * 8 + m];
#pragma unroll
            for (int n = 0; n < 8; n++) rb[n] = Bs[k][tcol * 8 + n];
#pragma unroll
            for (int m = 0; m < 8; m++)
#pragma unroll
                for (int n = 0; n < 8; n++) acc[m][n] = fmaf(ra[m], rb[n], acc[m][n]);
        }
        __syncthreads();
    }
#pragma unroll
    for (int m = 0; m < 8; m++) {
        int row = blockIdx.y * 128 + trow * 8 + m;
#pragma unroll
        for (int n = 0; n < 8; n++) {
            int col = nbase + tcol * 8 + n;
            if (col < N) {
                float bv = bias ? bias[col] : 0.f;
                C[(size_t)blockIdx.z * sC + (size_t)row * N + col] = acc[m][n] + bv;
            }
        }
    }
}

// ---------------- fused dt softplus + per-chunk inclusive cumsum ----------------
__global__ void cumsum_kernel(const float* __restrict__ dt_bias, const float* __restrict__ A_log)
{
    int c = blockIdx.x, h = blockIdx.y, b = blockIdx.z;
    int t = threadIdx.x;
    __shared__ float s[CHUNKT];
    int row = b * SEQLEN + c * CHUNKT + t;
    float v = g_zxbcdt[(size_t)row * DINPROJ + DINNER + CONVDIM + h] + dt_bias[h];
    float dtv = (v > 20.f) ? v : log1pf(__expf(v));
    g_dt[row * NHEADS + h] = dtv;
    s[t] = -__expf(A_log[h]) * dtv;
    __syncthreads();
#pragma unroll
    for (int off = 1; off < CHUNKT; off <<= 1) {
        float x = (t >= off) ? s[t - off] : 0.f;
        __syncthreads();
        s[t] += x;
        __syncthreads();
    }
    g_Acum[(b * NHEADS + h) * SEQLEN + c * CHUNKT + t] = s[t];
}

// ---------------- causal depthwise conv + SiLU (4 outputs/thread) ----------------
__global__ void conv_kernel(const float* __restrict__ w, const float* __restrict__ cb)
{
    long idx = (long)blockIdx.x * blockDim.x + threadIdx.x;
    if (idx >= (long)(NROWS / 4) * CONVDIM) return;
    int c = (int)(idx % CONVDIM);
    int r0 = (int)(idx / CONVDIM) * 4;
    int l0 = r0 & (SEQLEN - 1);
    float v[7];
#pragma unroll
    for (int k = 0; k < 7; k++) {
        int l = l0 - 3 + k;
        v[k] = (l >= 0) ? g_zxbcdt[(size_t)(r0 - 3 + k) * DINPROJ + DINNER + c] : 0.f;
    }
    const float w0 = w[c * 4], w1 = w[c * 4 + 1], w2 = w[c * 4 + 2], w3 = w[c * 4 + 3];
    const float bias = cb[c];
#pragma unroll
    for (int j = 0; j < 4; j++) {
        float acc = bias;
        acc = fmaf(w0, v[j + 0], acc);
        acc = fmaf(w1, v[j + 1], acc);
        acc = fmaf(w2, v[j + 2], acc);
        acc = fmaf(w3, v[j + 3], acc);
        float out = siluf(acc);
        int r = r0 + j;
        if (c < DINNER) {
            float xv = out * g_dt[r * NHEADS + (c >> 7)];
            g_xf16[(size_t)r * DINNER + c] = __float2half_rn(xv);
        } else if (c < DINNER + DSTATE) {
            g_Bv[r * DSTATE + (c - DINNER)] = out;
        } else {
            g_Cv[r * DSTATE + (c - DINNER - DSTATE)] = out;
        }
    }
}

// ---------------- chunk-local states on tensor cores ----------------
__global__ void __launch_bounds__(256) states_mma()
{
    __shared__ __align__(16) char sX[64 * 256];
    __shared__ __align__(16) char sB[64 * 128];
    __shared__ float Ac[CHUNKT];
    const int h = blockIdx.x, c = blockIdx.y, b = blockIdx.z;
    const int tid = threadIdx.x, lane = tid & 31, wid = tid >> 5;
    const int wr = wid >> 1, wc = wid & 1;
    const int brow = b * SEQLEN + c * CHUNKT;
    const uint32_t sbX = smem_u32(sX), sbB = smem_u32(sB);

    Ac[tid] = g_Acum[(b * NHEADS + h) * SEQLEN + c * CHUNKT + tid];
    __syncthreads();
    const float Atot = Ac[CHUNKT - 1];

    float acc[2][4][4];
#pragma unroll
    for (int mt = 0; mt < 2; mt++)
#pragma unroll
        for (int nt = 0; nt < 4; nt++)
#pragma unroll
            for (int i = 0; i < 4; i++) acc[mt][nt][i] = 0.f;

    const int g = lane >> 3, li = lane & 7;
    const int akr = (g >> 1) * 8 + li;
    const int amc = (g & 1) * 8;
    const int bkr = (g & 1) * 8 + li;
    const int bnc = (g >> 1) * 8;

    for (int lt = 0; lt < CHUNKT; lt += 64) {
        if (lt) __syncthreads();
        for (int idx = tid; idx < 64 * 16; idx += 256) {
            int l = idx >> 4, u = idx & 15;
            size_t src = (size_t)(brow + lt + l) * DINNER + h * HEADDIM + u * 8;
            uint32_t dst = l * 256 + ((u ^ (l & 7)) * 16);
            *(uint4*)(sX + dst) = *(const uint4*)(g_xf16 + src);
        }
        for (int idx = tid; idx < 64 * 16; idx += 256) {
            int l = idx >> 4, u4 = idx & 15;
            float4 bv = *(const float4*)&g_Bv[(size_t)(brow + lt + l) * DSTATE + u4 * 4];
            float e = __expf(Atot - Ac[lt + l]);
            uint32_t h01 = rnd2h(bv.x * e, bv.y * e);
            uint32_t h23 = rnd2h(bv.z * e, bv.w * e);
            uint32_t dst = l * 128 + (((u4 >> 1) ^ (l & 7)) * 16) + (u4 & 1) * 8;
            *(uint2*)(sB + dst) = make_uint2(h01, h23);
        }
        __syncthreads();
#pragma unroll
        for (int s = 0; s < 4; s++) {
            uint32_t af[2][4];
#pragma unroll
            for (int mt = 0; mt < 2; mt++) {
                int kr = s * 16 + akr;
                int mc = wr * 32 + mt * 16 + amc;
                uint32_t off = kr * 256 + (((mc >> 3) ^ (kr & 7)) * 16);
                LDSM_X4_T(af[mt][0], af[mt][1], af[mt][2], af[mt][3], sbX + off);
            }
#pragma unroll
            for (int ntp = 0; ntp < 2; ntp++) {
                int kr = s * 16 + bkr;
                int nc = wc * 32 + ntp * 16 + bnc;
                uint32_t off = kr * 128 + (((nc >> 3) ^ (kr & 7)) * 16);
                uint32_t b0, b1, b2, b3;
                LDSM_X4_T(b0, b1, b2, b3, sbB + off);
#pragma unroll
                for (int mt = 0; mt < 2; mt++) {
                    mma16816h(acc[mt][2*ntp+0], af[mt], b0, b1);
                    mma16816h(acc[mt][2*ntp+1], af[mt], b2, b3);
                }
            }
        }
    }

    size_t base = ((size_t)((b * NCHUNK + c) * NHEADS + h)) * HEADDIM * DSTATE;
#pragma unroll
    for (int mt = 0; mt < 2; mt++) {
        int p0 = wr * 32 + mt * 16 + (lane >> 2);
#pragma unroll
        for (int nt = 0; nt < 4; nt++) {
            int n = wc * 32 + nt * 8 + (lane & 3) * 2;
            *(float2*)(g_states + base + (size_t)p0 * DSTATE + n) =
                make_float2(acc[mt][nt][0], acc[mt][nt][1]);
            *(float2*)(g_states + base + (size_t)(p0 + 8) * DSTATE + n) =
                make_float2(acc[mt][nt][2], acc[mt][nt][3]);
        }
    }
}

// ---------------- inter-chunk state scan (8-way split per (b,h)) ----------------
__global__ void scan_kernel()
{
    int bh = blockIdx.x >> 3, seg = blockIdx.x & 7;
    int b = bh >> 5, h = bh & 31;
    int t = threadIdx.x;
    size_t off = (size_t)seg * 1024 + (size_t)t * 4;
    float4 S = make_float4(0.f, 0.f, 0.f, 0.f);
    for (int c = 0; c < NCHUNK; c++) {
        size_t base = ((size_t)((b * NCHUNK + c) * NHEADS + h)) * (HEADDIM * DSTATE) + off;
        *(float4*)(g_prefix + base) = S;
        float f = __expf(g_Acum[(b * NHEADS + h) * SEQLEN + c * CHUNKT + CHUNKT - 1]);
        float4 st = *(const float4*)(g_states + base);
        S.x = S.x * f + st.x;
        S.y = S.y * f + st.y;
        S.z = S.z * f + st.z;
        S.w = S.w * f + st.w;
    }
}

// ================= fused Y on tensor cores (fp16 2-term) =================
// smem: WH 0 (32K) | WL 32768 (32K) | X/S 65536 (16K) | Ac 81920 | eAc 82944
#define YSMEM 84992
__global__ void __launch_bounds__(512, 1) yfused_mma()
{
    extern __shared__ char ysm[];
    const uint32_t sb = smem_u32(ysm);
    float* Ac  = (float*)(ysm + 81920);
    float* eAc = (float*)(ysm + 82944);
    const int h = blockIdx.x, c = blockIdx.y, b = blockIdx.z;
    const int tid = threadIdx.x, lane = tid & 31, wid = tid >> 5;
    const int wr = wid >> 2, wc = wid & 3;
    const int brow = b * SEQLEN + c * CHUNKT;
    const size_t gbase = (size_t)(b * NCHUNK + c) * CHUNKT * CHUNKT;
    const size_t sbase = ((size_t)((b * NCHUNK + c) * NHEADS + h)) * (HEADDIM * DSTATE);

    if (tid < CHUNKT) {
        float a = g_Acum[(b * NHEADS + h) * SEQLEN + c * CHUNKT + tid];
        Ac[tid] = a;
        eAc[tid] = __expf(a);
    }

    float acc[4][4][4];
#pragma unroll
    for (int mt = 0; mt < 4; mt++)
#pragma unroll
        for (int nt = 0; nt < 4; nt++)
#pragma unroll
            for (int i = 0; i < 4; i++) acc[mt][nt][i] = 0.f;

    const int g = lane >> 3, li = lane & 7;
    const int arow  = (g & 1) * 8 + li;
    const int ahalf = g >> 1;
    const int bkt   = (g & 1) * 8 + li;
    const int bnt   = (g >> 1) * 8;
    const int brw2  = (g >> 1) * 8 + li;
    const int bhf2  = g & 1;

    // ---- part 1: W @ X over 4 j-tiles of 64 ----
    for (int jt = 0; jt < CHUNKT; jt += 64) {
        __syncthreads();
        for (int idx = tid; idx < 256 * 16; idx += 512) {
            int i = idx >> 4, u4 = idx & 15;
            float4 gv = *(const float4*)&g_G[gbase + (size_t)i * 256 + jt + u4 * 4];
            float ai = Ac[i];
            int j0 = jt + u4 * 4;
            float v0 = (j0 + 0 <= i) ? __expf(ai - Ac[j0 + 0]) * gv.x : 0.f;
            float v1 = (j0 + 1 <= i) ? __expf(ai - Ac[j0 + 1]) * gv.y : 0.f;
            float v2 = (j0 + 2 <= i) ? __expf(ai - Ac[j0 + 2]) * gv.z : 0.f;
            float v3 = (j0 + 3 <= i) ? __expf(ai - Ac[j0 + 3]) * gv.w : 0.f;
            uint32_t lo01, lo23;
            uint32_t hi01 = pack2h(v0, v1, lo01);
            uint32_t hi23 = pack2h(v2, v3, lo23);
            uint32_t base = i * 128 + (((u4 >> 1) ^ (i & 7)) * 16) + (u4 & 1) * 8;
            *(uint2*)(ysm + base)         = make_uint2(hi01, hi23);
            *(uint2*)(ysm + 32768 + base) = make_uint2(lo01, lo23);
        }
        for (int idx = tid; idx < 64 * 16; idx += 512) {
            int l = idx >> 4, u = idx & 15;
            size_t src = (size_t)(brow + jt + l) * DINNER + h * HEADDIM + u * 8;
            uint32_t dst = l * 256 + ((u ^ (l & 7)) * 16);
            *(uint4*)(ysm + 65536 + dst) = *(const uint4*)(g_xf16 + src);
        }
        __syncthreads();
        if (wr * 64 + 63 >= jt) {
#pragma unroll
            for (int s = 0; s < 4; s++) {
                uint32_t afh[4][4], afl[4][4];
#pragma unroll
                for (int mt = 0; mt < 4; mt++) {
                    int row = wr * 64 + mt * 16 + arow;
                    uint32_t off = row * 128 + (((2 * s + ahalf) ^ (row & 7)) * 16);
                    LDSM_X4(afh[mt][0], afh[mt][1], afh[mt][2], afh[mt][3], sb + off);
                    LDSM_X4(afl[mt][0], afl[mt][1], afl[mt][2], afl[mt][3], sb + 32768 + off);
                }
#pragma unroll
                for (int ntp = 0; ntp < 2; ntp++) {
                    int krow = s * 16 + bkt;
                    int p = wc * 32 + ntp * 16 + bnt;
                    uint32_t off = krow * 256 + (((p >> 3) ^ (krow & 7)) * 16);
                    uint32_t b0, b1, b2, b3;
                    LDSM_X4_T(b0, b1, b2, b3, sb + 65536 + off);
#pragma unroll
                    for (int mt = 0; mt < 4; mt++) {
                        mma16816h(acc[mt][2*ntp+0], afh[mt], b0, b1);
                        mma16816h(acc[mt][2*ntp+0], afl[mt], b0, b1);
                        mma16816h(acc[mt][2*ntp+1], afh[mt], b2, b3);
                        mma16816h(acc[mt][2*ntp+1], afl[mt], b2, b3);
                    }
                }
            }
        }
    }

    // ---- part 2: Ce @ S^T (K = 64) ----
    __syncthreads();
    for (int idx = tid; idx < 256 * 16; idx += 512) {
        int i = idx >> 4, u4 = idx & 15;
        float4 cv = *(const float4*)&g_Cv[(size_t)(brow + i) * 64 + u4 * 4];
        float e = eAc[i];
        uint32_t lo01, lo23;
        uint32_t hi01 = pack2h(cv.x * e, cv.y * e, lo01);
        uint32_t hi23 = pack2h(cv.z * e, cv.w * e, lo23);
        uint32_t base = i * 128 + (((u4 >> 1) ^ (i & 7)) * 16) + (u4 & 1) * 8;
        *(uint2*)(ysm + base)         = make_uint2(hi01, hi23);
        *(uint2*)(ysm + 32768 + base) = make_uint2(lo01, lo23);
    }
    for (int idx = tid; idx < 128 * 16; idx += 512) {
        int p = idx >> 4, u4 = idx & 15;
        float4 sv = *(const float4*)&g_prefix[sbase + (size_t)p * 64 + u4 * 4];
        uint32_t h01 = rnd2h(sv.x, sv.y);
        uint32_t h23 = rnd2h(sv.z, sv.w);
        uint32_t base = p * 128 + (((u4 >> 1) ^ (p & 7)) * 16) + (u4 & 1) * 8;
        *(uint2*)(ysm + 65536 + base) = make_uint2(h01, h23);
    }
    __syncthreads();
#pragma unroll
    for (int s = 0; s < 4; s++) {
        uint32_t afh[4][4], afl[4][4];
#pragma unroll
        for (int mt = 0; mt < 4; mt++) {
            int row = wr * 64 + mt * 16 + arow;
            uint32_t off = row * 128 + (((2 * s + ahalf) ^ (row & 7)) * 16);
            LDSM_X4(afh[mt][0], afh[mt][1], afh[mt][2], afh[mt][3], sb + off);
            LDSM_X4(afl[mt][0], afl[mt][1], afl[mt][2], afl[mt][3], sb + 32768 + off);
        }
#pragma unroll
        for (int ntp = 0; ntp < 2; ntp++) {
            int row = wc * 32 + ntp * 16 + brw2;
            uint32_t off = row * 128 + (((2 * s + bhf2) ^ (row & 7)) * 16);
            uint32_t b0, b1, b2, b3;
            LDSM_X4(b0, b1, b2, b3, sb + 65536 + off);
#pragma unroll
            for (int mt = 0; mt < 4; mt++) {
                mma16816h(acc[mt][2*ntp+0], afh[mt], b0, b1);
                mma16816h(acc[mt][2*ntp+0], afl[mt], b0, b1);
                mma16816h(acc[mt][2*ntp+1], afh[mt], b2, b3);
                mma16816h(acc[mt][2*ntp+1], afl[mt], b2, b3);
            }
        }
    }

    // ---- epilogue ----
#pragma unroll
    for (int mt = 0; mt < 4; mt++) {
        int i0 = wr * 64 + mt * 16 + (lane >> 2);
#pragma unroll
        for (int nt = 0; nt < 4; nt++) {
            int col = h * HEADDIM + wc * 32 + nt * 8 + (lane & 3) * 2;
            *(float2*)(g_y + (size_t)(brow + i0) * DINNER + col) =
                make_float2(acc[mt][nt][0], acc[mt][nt][1]);
            *(float2*)(g_y + (size_t)(brow + i0 + 8) * DINNER + col) =
                make_float2(acc[mt][nt][2], acc[mt][nt][3]);
        }
    }
}

// ---------------- gating (y * silu(z)) + LayerNorm; emits fp16 hi/lo ----------------
__global__ void __launch_bounds__(256) ln_kernel(const float* __restrict__ lnw, const float* __restrict__ lnb)
{
    int row = blockIdx.x;
    int tid = threadIdx.x;
    float gv[4][4];
    float s = 0.f, s2 = 0.f;
#pragma unroll
    for (int q = 0; q < 4; q++) {
        int i = (tid + q * 256) * 4;
        float4 yv = *(const float4*)&g_y[(size_t)row * DINNER + i];
        float4 zv = *(const float4*)&g_zxbcdt[(size_t)row * DINPROJ + i];
        float v0 = yv.x * siluf(zv.x);
        float v1 = yv.y * siluf(zv.y);
        float v2 = yv.z * siluf(zv.z);
        float v3 = yv.w * siluf(zv.w);
        gv[q][0] = v0; gv[q][1] = v1; gv[q][2] = v2; gv[q][3] = v3;
        s += v0 + v1 + v2 + v3;
        s2 = fmaf(v0, v0, s2); s2 = fmaf(v1, v1, s2);
        s2 = fmaf(v2, v2, s2); s2 = fmaf(v3, v3, s2);
    }
    __shared__ float red[2][8];
#pragma unroll
    for (int off = 16; off > 0; off >>= 1) {
        s  += __shfl_xor_sync(0xffffffffu, s, off);
        s2 += __shfl_xor_sync(0xffffffffu, s2, off);
    }
    if ((tid & 31) == 0) { red[0][tid >> 5] = s; red[1][tid >> 5] = s2; }
    __syncthreads();
    if (tid == 0) {
        float a = 0.f, a2 = 0.f;
#pragma unroll
        for (int w = 0; w < 8; w++) { a += red[0][w]; a2 += red[1][w]; }
        red[0][0] = a; red[1][0] = a2;
    }
    __syncthreads();
    float mu  = red[0][0] * (1.f / DINNER);
    float var = red[1][0] * (1.f / DINNER) - mu * mu;
    float rstd = rsqrtf(var + LN_EPS);
#pragma unroll
    for (int q = 0; q < 4; q++) {
        int i = (tid + q * 256) * 4;
        float4 wv = *(const float4*)&lnw[i];
        float4 bv = *(const float4*)&lnb[i];
        float o0 = (gv[q][0] - mu) * rstd * wv.x + bv.x;
        float o1 = (gv[q][1] - mu) * rstd * wv.y + bv.y;
        float o2 = (gv[q][2] - mu) * rstd * wv.z + bv.z;
        float o3 = (gv[q][3] - mu) * rstd * wv.w + bv.w;
        uint32_t l01, l23;
        uint32_t h01 = pack2h(o0, o1, l01);
        uint32_t h23 = pack2h(o2, o3, l23);
        *(uint2*)&g_ynh[(size_t)row * DINNER + i] = make_uint2(h01, h23);
        *(uint2*)&g_ynl[(size_t)row * DINNER + i] = make_uint2(l01, l23);
    }
}

// ---------------- launch ----------------
extern "C" void kernel_launch(void* const* d_in, const int* in_sizes, int n_in,
                              void* d_out, int out_size)
{
    const float* u          = (const float*)d_in[0];
    const float* in_proj_w  = (const float*)d_in[1];
    const float* in_proj_b  = (const float*)d_in[2];
    const float* conv_w     = (const float*)d_in[3];
    const float* conv_b     = (const float*)d_in[4];
    const float* dt_bias    = (const float*)d_in[5];
    const float* A_log      = (const float*)d_in[6];
    const float* ln_w       = (const float*)d_in[7];
    const float* ln_b       = (const float*)d_in[8];
    const float* out_proj_w = (const float*)d_in[9];
    const float* out_proj_b = (const float*)d_in[10];
    float* out = (float*)d_out;

    float *zx, *gB, *gC, *gG;
    __half *uh, *ul, *w1h, *ynh, *ynl, *w2h;
    cudaGetSymbolAddress((void**)&zx,  g_zxbcdt);
    cudaGetSymbolAddress((void**)&gB,  g_Bv);
    cudaGetSymbolAddress((void**)&gC,  g_Cv);
    cudaGetSymbolAddress((void**)&gG,  g_G);
    cudaGetSymbolAddress((void**)&uh,  g_uh);
    cudaGetSymbolAddress((void**)&ul,  g_ul);
    cudaGetSymbolAddress((void**)&w1h, g_w1h);
    cudaGetSymbolAddress((void**)&ynh, g_ynh);
    cudaGetSymbolAddress((void**)&ynl, g_ynl);
    cudaGetSymbolAddress((void**)&w2h, g_w2h);

    cudaFuncSetAttribute(mma_gemm_nt, cudaFuncAttributeMaxDynamicSharedMemorySize, 3 * GST);
    cudaFuncSetAttribute(yfused_mma, cudaFuncAttributeMaxDynamicSharedMemorySize, YSMEM);

    // 0) fp32 -> fp16 conversions (vectorized)
    {
        long n1 = (long)NROWS * DMODEL / 4;
        split_f16<<<(unsigned)((n1 + 255) / 256), 256>>>(u, uh, ul, n1);
        long n2 = (long)DINPROJ * DMODEL / 4;
        round_f16<<<(unsigned)((n2 + 255) / 256), 256>>>(in_proj_w, w1h, n2);
        long n3 = (long)DMODEL * DINNER / 4;
        round_f16<<<(unsigned)((n3 + 255) / 256), 256>>>(out_proj_w, w2h, n3);
    }

    // 1) in_proj: M=8192, N=8352, K=2048
    mma_gemm_nt<<<dim3((DINPROJ + 255) / 256, NROWS / 128), 512, 3 * GST>>>(
        uh, ul, w1h, in_proj_b, zx, DINPROJ, DMODEL);

    // 2) fused dt softplus + per-chunk cumsum
    cumsum_kernel<<<dim3(NCHUNK, NHEADS, BATCH), CHUNKT>>>(dt_bias, A_log);

    // 3) causal conv + silu (4 outputs/thread)
    {
        long total = (long)(NROWS / 4) * CONVDIM;
        conv_kernel<<<(unsigned)((total + 255) / 256), 256>>>(conv_w, conv_b);
    }

    // 4) G = C @ B^T per (b,chunk)
    sgemm_nt<<<dim3(2, 2, BATCH * NCHUNK), 256>>>(
        gC, gB, nullptr, gG, CHUNKT, DSTATE,
        (long)CHUNKT * DSTATE, (long)CHUNKT * DSTATE, (long)CHUNKT * CHUNKT);

    // 5) chunk-local states on tensor cores
    states_mma<<<dim3(NHEADS, NCHUNK, BATCH), 256>>>();

    // 6) inter-chunk scan (8-way split)
    scan_kernel<<<BATCH * NHEADS * 8, 256>>>();

    // 7) fused Y on tensor cores
    yfused_mma<<<dim3(NHEADS, NCHUNK, BATCH), 512, YSMEM>>>();

    // 8) gate + layernorm (+ fp16 split of yn)
    ln_kernel<<<NROWS, 256>>>(ln_w, ln_b);

    // 9) out_proj: M=8192, N=2048, K=4096
    mma_gemm_nt<<<dim3(DMODEL / 256, NROWS / 128), 512, 3 * GST>>>(
        ynh, ynl, w2h, out_proj_b, out, DMODEL, DINNER);
}

// round 13
// speedup vs baseline: 1.1769x; 1.0060x over previous
#include <cuda_runtime.h>
#include <cuda_bf16.h>
#include <cuda_fp16.h>
#include <cstdint>
#include <math.h>

#define BATCH   2
#define SEQLEN  4096
#define DMODEL  2048
#define DINNER  4096
#define NHEADS  32
#define HEADDIM 128
#define DSTATE  64
#define NCHUNK  16
#define CHUNKT  256
#define CONVDIM 4224
#define DINPROJ 8352
#define NROWS   (BATCH*SEQLEN)
#define LN_EPS  1e-5f

// ---------------- scratch (device globals; no allocations allowed) ----------------
__device__ float g_zxbcdt[(size_t)NROWS * DINPROJ];
__device__ float g_Bv   [NROWS * DSTATE];
__device__ float g_Cv   [NROWS * DSTATE];
__device__ float g_dt   [NROWS * NHEADS];
__device__ float g_Acum [BATCH * NHEADS * SEQLEN];
__device__ float g_G    [(size_t)BATCH * NCHUNK * CHUNKT * CHUNKT];
__device__ float g_states[(size_t)BATCH * NCHUNK * NHEADS * HEADDIM * DSTATE];
__device__ float g_prefix[(size_t)BATCH * NCHUNK * NHEADS * HEADDIM * DSTATE];
__device__ float g_y    [(size_t)NROWS * DINNER];

// fp16 buffers (activations exact hi/lo, weights rounded)
__device__ __half g_uh [(size_t)NROWS * DMODEL];
__device__ __half g_ul [(size_t)NROWS * DMODEL];
__device__ __half g_w1h[(size_t)DINPROJ * DMODEL];
__device__ __half g_ynh[(size_t)NROWS * DINNER];
__device__ __half g_ynl[(size_t)NROWS * DINNER];
__device__ __half g_w2h[(size_t)DMODEL * DINNER];
__device__ __half g_xf16[(size_t)NROWS * DINNER];   // rounded fp16 of xdt

__device__ __forceinline__ float siluf(float x) { return x / (1.f + __expf(-x)); }

__device__ __forceinline__ uint32_t smem_u32(const void* p) {
    uint32_t a;
    asm("{ .reg .u64 t; cvta.to.shared.u64 t, %1; cvt.u32.u64 %0, t; }" : "=r"(a) : "l"(p));
    return a;
}

// pack two floats into fp16x2 hi; return hi, write lo (exact 2-term split)
__device__ __forceinline__ uint32_t pack2h(float a, float b, uint32_t& lo) {
    __half ha = __float2half_rn(a), hb = __float2half_rn(b);
    __half la = __float2half_rn(a - __half2float(ha));
    __half lb = __float2half_rn(b - __half2float(hb));
    lo = (uint32_t)__half_as_ushort(la) | ((uint32_t)__half_as_ushort(lb) << 16);
    return (uint32_t)__half_as_ushort(ha) | ((uint32_t)__half_as_ushort(hb) << 16);
}
__device__ __forceinline__ uint32_t rnd2h(float a, float b) {
    return (uint32_t)__half_as_ushort(__float2half_rn(a)) |
           ((uint32_t)__half_as_ushort(__float2half_rn(b)) << 16);
}

// ================= split kernels (float4 vectorized; n divisible by 4) =================
__global__ void split_f16(const float* __restrict__ src,
                          __half* __restrict__ hi, __half* __restrict__ lo, long n4)
{
    long i = (long)blockIdx.x * blockDim.x + threadIdx.x;
    if (i >= n4) return;
    float4 x = ((const float4*)src)[i];
    uint32_t l01, l23;
    uint32_t h01 = pack2h(x.x, x.y, l01);
    uint32_t h23 = pack2h(x.z, x.w, l23);
    ((uint2*)hi)[i] = make_uint2(h01, h23);
    ((uint2*)lo)[i] = make_uint2(l01, l23);
}
__global__ void round_f16(const float* __restrict__ src, __half* __restrict__ dst, long n4)
{
    long i = (long)blockIdx.x * blockDim.x + threadIdx.x;
    if (i >= n4) return;
    float4 x = ((const float4*)src)[i];
    ((uint2*)dst)[i] = make_uint2(rnd2h(x.x, x.y), rnd2h(x.z, x.w));
}

// ================= tensor-core primitives =================
__device__ __forceinline__ void mma16816h(float* c, const uint32_t* a, uint32_t b0, uint32_t b1)
{
    asm volatile(
        "mma.sync.aligned.m16n8k16.row.col.f32.f16.f16.f32 "
        "{%0,%1,%2,%3}, {%4,%5,%6,%7}, {%8,%9}, {%0,%1,%2,%3};"
        : "+f"(c[0]), "+f"(c[1]), "+f"(c[2]), "+f"(c[3])
        : "r"(a[0]), "r"(a[1]), "r"(a[2]), "r"(a[3]), "r"(b0), "r"(b1));
}
#define LDSM_X4(r0, r1, r2, r3, addr) \
    asm volatile("ldmatrix.sync.aligned.m8n8.x4.shared.b16 {%0,%1,%2,%3}, [%4];" \
                 : "=r"(r0), "=r"(r1), "=r"(r2), "=r"(r3) : "r"(addr))
#define LDSM_X4_T(r0, r1, r2, r3, addr) \
    asm volatile("ldmatrix.sync.aligned.m8n8.x4.trans.shared.b16 {%0,%1,%2,%3}, [%4];" \
                 : "=r"(r0), "=r"(r1), "=r"(r2), "=r"(r3) : "r"(addr))
#define CP16(dst, src, sz) \
    asm volatile("cp.async.cg.shared.global [%0], [%1], 16, %2;" \
                 :: "r"(dst), "l"(src), "r"(sz))
#define CP_COMMIT() asm volatile("cp.async.commit_group;" ::: "memory")
#define CP_WAIT1()  asm volatile("cp.async.wait_group 1;" ::: "memory")
#define CP_WAIT0()  asm volatile("cp.async.wait_group 0;" ::: "memory")

// ================= fp16 2-MMA GEMM: C = (Ah+Al)*Bh^T + bias =================
// BM=128, BN=256, BK=64, 512 threads (16 warps, 32x64 warp tiles).
// 3-stage cp.async pipeline. A exact fp16 hi/lo (M mult of 128); B rounded fp16.
#define GST 65536
__global__ void __launch_bounds__(512, 1)
mma_gemm_nt(const __half* __restrict__ Ah, const __half* __restrict__ Al,
            const __half* __restrict__ Bh,
            const float* __restrict__ bias, float* __restrict__ C, int N, int K)
{
    extern __shared__ char smem[];
    const uint32_t sb = smem_u32(smem);
    const int tid = threadIdx.x, lane = tid & 31, wid = tid >> 5;
    const int wr = wid >> 2, wc = wid & 3;        // 4x4 warps, each 32(m) x 64(n)
    const int mbase = blockIdx.y * 128;
    const int nbase = blockIdx.x * 256;

    // A loader: 4 thr/row, 2 units; B loader: 2 thr/row, 4 units
    const int ra = tid >> 2, ua0 = (tid & 3) * 2;
    const int rb = tid >> 1, ub0 = (tid & 1) * 4;
    const bool bval = (nbase + rb) < N;
    const uint32_t bsz = bval ? 16u : 0u;
    const __half* gAh = Ah + (size_t)(mbase + ra) * K + ua0 * 8;
    const __half* gAl = Al + (size_t)(mbase + ra) * K + ua0 * 8;
    const __half* gBh = Bh + (size_t)(bval ? nbase + rb : 0) * K + ub0 * 8;
    const uint32_t dA0 = ra * 128 + (( ua0      ^ (ra & 7)) * 16);
    const uint32_t dA1 = ra * 128 + (((ua0 + 1) ^ (ra & 7)) * 16);
    uint32_t dB[4];
#pragma unroll
    for (int j = 0; j < 4; j++) dB[j] = rb * 128 + (((ub0 + j) ^ (rb & 7)) * 16);

    auto issue = [&](int st, int kt) {
        uint32_t s0 = sb + st * GST;
        CP16(s0 + dA0,         gAh + kt,     16);
        CP16(s0 + dA1,         gAh + kt + 8, 16);
        CP16(s0 + 16384 + dA0, gAl + kt,     16);
        CP16(s0 + 16384 + dA1, gAl + kt + 8, 16);
#pragma unroll
        for (int j = 0; j < 4; j++)
            CP16(s0 + 32768 + dB[j], gBh + kt + j * 8, bsz);
        CP_COMMIT();
    };

    float acc[2][8][4];
#pragma unroll
    for (int mt = 0; mt < 2; mt++)
#pragma unroll
        for (int nt = 0; nt < 8; nt++)
#pragma unroll
            for (int i = 0; i < 4; i++) acc[mt][nt][i] = 0.f;

    const int nk = K >> 6;
    issue(0, 0);
    issue(1, 64);

    const int g = lane >> 3, li = lane & 7;
    const int arow_lo = (g & 1) * 8 + li;
    const int ahalf   = g >> 1;
    const int brow_lo = (g >> 1) * 8 + li;
    const int bhalf   = g & 1;

    int stage = 0;
    for (int c = 0; c < nk; c++) {
        if (c + 1 < nk) CP_WAIT1(); else CP_WAIT0();
        __syncthreads();
        if (c + 2 < nk) {
            int st = stage + 2; if (st >= 3) st -= 3;
            issue(st, (c + 2) * 64);
        }
        const uint32_t s0 = sb + stage * GST;
#pragma unroll
        for (int s = 0; s < 4; s++) {
            uint32_t afh[2][4], afl[2][4];
#pragma unroll
            for (int mt = 0; mt < 2; mt++) {
                int row = wr * 32 + mt * 16 + arow_lo;
                uint32_t off = row * 128 + (((2 * s + ahalf) ^ (row & 7)) * 16);
                LDSM_X4(afh[mt][0], afh[mt][1], afh[mt][2], afh[mt][3], s0 + off);
                LDSM_X4(afl[mt][0], afl[mt][1], afl[mt][2], afl[mt][3], s0 + 16384 + off);
            }
#pragma unroll
            for (int ntp = 0; ntp < 4; ntp++) {
                int row = wc * 64 + ntp * 16 + brow_lo;
                uint32_t off = row * 128 + (((2 * s + bhalf) ^ (row & 7)) * 16);
                uint32_t b0, b1, b2, b3;
                LDSM_X4(b0, b1, b2, b3, s0 + 32768 + off);
#pragma unroll
                for (int mt = 0; mt < 2; mt++) {
                    mma16816h(acc[mt][2*ntp+0], afh[mt], b0, b1);
                    mma16816h(acc[mt][2*ntp+0], afl[mt], b0, b1);
                    mma16816h(acc[mt][2*ntp+1], afh[mt], b2, b3);
                    mma16816h(acc[mt][2*ntp+1], afl[mt], b2, b3);
                }
            }
        }
        stage++; if (stage >= 3) stage -= 3;
    }

#pragma unroll
    for (int mt = 0; mt < 2; mt++) {
        int r0 = mbase + wr * 32 + mt * 16 + (lane >> 2);
#pragma unroll
        for (int nt = 0; nt < 8; nt++) {
            int col = nbase + wc * 64 + nt * 8 + (lane & 3) * 2;
            if (col < N) {
                float b0 = bias ? bias[col] : 0.f;
                float b1 = bias ? bias[col + 1] : 0.f;
                float2 v0 = make_float2(acc[mt][nt][0] + b0, acc[mt][nt][1] + b1);
                float2 v1 = make_float2(acc[mt][nt][2] + b0, acc[mt][nt][3] + b1);
                *(float2*)(C + (size_t)r0 * N + col)       = v0;
                *(float2*)(C + (size_t)(r0 + 8) * N + col) = v1;
            }
        }
    }
}

// ---------------- small fp32 NT GEMM (G = C @ B^T) ----------------
__global__ void __launch_bounds__(256)
sgemm_nt(const float* __restrict__ A, const float* __restrict__ B,
         const float* __restrict__ bias, float* __restrict__ C,
         int N, int K, long sA, long sB, long sC)
{
    __shared__ float As[16][128];
    __shared__ float Bs[16][128];
    const int tid  = threadIdx.x;
    const int tcol = tid & 15;
    const int trow = tid >> 4;
    const float* Ab = A + (size_t)blockIdx.z * sA + (size_t)blockIdx.y * 128 * K;
    const float* Bb = B + (size_t)blockIdx.z * sB + (size_t)blockIdx.x * 128 * K;
    const int nbase = blockIdx.x * 128;

    float acc[8][8];
#pragma unroll
    for (int m = 0; m < 8; m++)
#pragma unroll
        for (int n = 0; n < 8; n++) acc[m][n] = 0.f;

    const int lrow = tid >> 2;
    const int lcol = (tid & 3) * 4;

    for (int kt = 0; kt < K; kt += 16) {
#pragma unroll
        for (int it = 0; it < 2; it++) {
            int r = lrow + it * 64;
            float4 va = *(const float4*)(Ab + (size_t)r * K + kt + lcol);
            As[lcol+0][r] = va.x; As[lcol+1][r] = va.y;
            As[lcol+2][r] = va.z; As[lcol+3][r] = va.w;
            float4 vb;
            if (nbase + r < N) vb = *(const float4*)(Bb + (size_t)r * K + kt + lcol);
            else               vb = make_float4(0.f, 0.f, 0.f, 0.f);
            Bs[lcol+0][r] = vb.x; Bs[lcol+1][r] = vb.y;
            Bs[lcol+2][r] = vb.z; Bs[lcol+3][r] = vb.w;
        }
        __syncthreads();
#pragma unroll
        for (int k = 0; k < 16; k++) {
            float ra[8], rb[8];
#pragma unroll
            for (int m = 0; m < 8; m++) ra[m] = As[k][trow * 8 + m];
#pragma unroll
            for (int n = 0; n < 8; n++) rb[n] = Bs[k][tcol * 8 + n];
#pragma unroll
            for (int m = 0; m < 8; m++)
#pragma unroll
                for (int n = 0; n < 8; n++) acc[m][n] = fmaf(ra[m], rb[n], acc[m][n]);
        }
        __syncthreads();
    }
#pragma unroll
    for (int m = 0; m < 8; m++) {
        int row = blockIdx.y * 128 + trow * 8 + m;
#pragma unroll
        for (int n = 0; n < 8; n++) {
            int col = nbase + tcol * 8 + n;
            if (col < N) {
                float bv = bias ? bias[col] : 0.f;
                C[(size_t)blockIdx.z * sC + (size_t)row * N + col] = acc[m][n] + bv;
            }
        }
    }
}

// ---------------- fused dt softplus + per-chunk inclusive cumsum ----------------
__global__ void cumsum_kernel(const float* __restrict__ dt_bias, const float* __restrict__ A_log)
{
    int c = blockIdx.x, h = blockIdx.y, b = blockIdx.z;
    int t = threadIdx.x;
    __shared__ float s[CHUNKT];
    int row = b * SEQLEN + c * CHUNKT + t;
    float v = g_zxbcdt[(size_t)row * DINPROJ + DINNER + CONVDIM + h] + dt_bias[h];
    float dtv = (v > 20.f) ? v : log1pf(__expf(v));
    g_dt[row * NHEADS + h] = dtv;
    s[t] = -__expf(A_log[h]) * dtv;
    __syncthreads();
#pragma unroll
    for (int off = 1; off < CHUNKT; off <<= 1) {
        float x = (t >= off) ? s[t - off] : 0.f;
        __syncthreads();
        s[t] += x;
        __syncthreads();
    }
    g_Acum[(b * NHEADS + h) * SEQLEN + c * CHUNKT + t] = s[t];
}

// ---------------- causal depthwise conv + SiLU (8 outputs/thread) ----------------
__global__ void conv_kernel(const float* __restrict__ w, const float* __restrict__ cb)
{
    long idx = (long)blockIdx.x * blockDim.x + threadIdx.x;
    if (idx >= (long)(NROWS / 8) * CONVDIM) return;
    int c = (int)(idx % CONVDIM);
    int r0 = (int)(idx / CONVDIM) * 8;
    int l0 = r0 & (SEQLEN - 1);
    float v[11];
#pragma unroll
    for (int k = 0; k < 11; k++) {
        int l = l0 - 3 + k;
        v[k] = (l >= 0) ? g_zxbcdt[(size_t)(r0 - 3 + k) * DINPROJ + DINNER + c] : 0.f;
    }
    const float w0 = w[c * 4], w1 = w[c * 4 + 1], w2 = w[c * 4 + 2], w3 = w[c * 4 + 3];
    const float bias = cb[c];
#pragma unroll
    for (int j = 0; j < 8; j++) {
        float acc = bias;
        acc = fmaf(w0, v[j + 0], acc);
        acc = fmaf(w1, v[j + 1], acc);
        acc = fmaf(w2, v[j + 2], acc);
        acc = fmaf(w3, v[j + 3], acc);
        float out = siluf(acc);
        int r = r0 + j;
        if (c < DINNER) {
            float xv = out * g_dt[r * NHEADS + (c >> 7)];
            g_xf16[(size_t)r * DINNER + c] = __float2half_rn(xv);
        } else if (c < DINNER + DSTATE) {
            g_Bv[r * DSTATE + (c - DINNER)] = out;
        } else {
            g_Cv[r * DSTATE + (c - DINNER - DSTATE)] = out;
        }
    }
}

// ---------------- chunk-local states on tensor cores ----------------
__global__ void __launch_bounds__(256) states_mma()
{
    __shared__ __align__(16) char sX[64 * 256];
    __shared__ __align__(16) char sB[64 * 128];
    __shared__ float Ac[CHUNKT];
    const int h = blockIdx.x, c = blockIdx.y, b = blockIdx.z;
    const int tid = threadIdx.x, lane = tid & 31, wid = tid >> 5;
    const int wr = wid >> 1, wc = wid & 1;
    const int brow = b * SEQLEN + c * CHUNKT;
    const uint32_t sbX = smem_u32(sX), sbB = smem_u32(sB);

    Ac[tid] = g_Acum[(b * NHEADS + h) * SEQLEN + c * CHUNKT + tid];
    __syncthreads();
    const float Atot = Ac[CHUNKT - 1];

    float acc[2][4][4];
#pragma unroll
    for (int mt = 0; mt < 2; mt++)
#pragma unroll
        for (int nt = 0; nt < 4; nt++)
#pragma unroll
            for (int i = 0; i < 4; i++) acc[mt][nt][i] = 0.f;

    const int g = lane >> 3, li = lane & 7;
    const int akr = (g >> 1) * 8 + li;
    const int amc = (g & 1) * 8;
    const int bkr = (g & 1) * 8 + li;
    const int bnc = (g >> 1) * 8;

    for (int lt = 0; lt < CHUNKT; lt += 64) {
        if (lt) __syncthreads();
        for (int idx = tid; idx < 64 * 16; idx += 256) {
            int l = idx >> 4, u = idx & 15;
            size_t src = (size_t)(brow + lt + l) * DINNER + h * HEADDIM + u * 8;
            uint32_t dst = l * 256 + ((u ^ (l & 7)) * 16);
            *(uint4*)(sX + dst) = *(const uint4*)(g_xf16 + src);
        }
        for (int idx = tid; idx < 64 * 16; idx += 256) {
            int l = idx >> 4, u4 = idx & 15;
            float4 bv = *(const float4*)&g_Bv[(size_t)(brow + lt + l) * DSTATE + u4 * 4];
            float e = __expf(Atot - Ac[lt + l]);
            uint32_t h01 = rnd2h(bv.x * e, bv.y * e);
            uint32_t h23 = rnd2h(bv.z * e, bv.w * e);
            uint32_t dst = l * 128 + (((u4 >> 1) ^ (l & 7)) * 16) + (u4 & 1) * 8;
            *(uint2*)(sB + dst) = make_uint2(h01, h23);
        }
        __syncthreads();
#pragma unroll
        for (int s = 0; s < 4; s++) {
            uint32_t af[2][4];
#pragma unroll
            for (int mt = 0; mt < 2; mt++) {
                int kr = s * 16 + akr;
                int mc = wr * 32 + mt * 16 + amc;
                uint32_t off = kr * 256 + (((mc >> 3) ^ (kr & 7)) * 16);
                LDSM_X4_T(af[mt][0], af[mt][1], af[mt][2], af[mt][3], sbX + off);
            }
#pragma unroll
            for (int ntp = 0; ntp < 2; ntp++) {
                int kr = s * 16 + bkr;
                int nc = wc * 32 + ntp * 16 + bnc;
                uint32_t off = kr * 128 + (((nc >> 3) ^ (kr & 7)) * 16);
                uint32_t b0, b1, b2, b3;
                LDSM_X4_T(b0, b1, b2, b3, sbB + off);
#pragma unroll
                for (int mt = 0; mt < 2; mt++) {
                    mma16816h(acc[mt][2*ntp+0], af[mt], b0, b1);
                    mma16816h(acc[mt][2*ntp+1], af[mt], b2, b3);
                }
            }
        }
    }

    size_t base = ((size_t)((b * NCHUNK + c) * NHEADS + h)) * HEADDIM * DSTATE;
#pragma unroll
    for (int mt = 0; mt < 2; mt++) {
        int p0 = wr * 32 + mt * 16 + (lane >> 2);
#pragma unroll
        for (int nt = 0; nt < 4; nt++) {
            int n = wc * 32 + nt * 8 + (lane & 3) * 2;
            *(float2*)(g_states + base + (size_t)p0 * DSTATE + n) =
                make_float2(acc[mt][nt][0], acc[mt][nt][1]);
            *(float2*)(g_states + base + (size_t)(p0 + 8) * DSTATE + n) =
                make_float2(acc[mt][nt][2], acc[mt][nt][3]);
        }
    }
}

// ---------------- inter-chunk state scan (8-way split per (b,h)) ----------------
__global__ void scan_kernel()
{
    int bh = blockIdx.x >> 3, seg = blockIdx.x & 7;
    int b = bh >> 5, h = bh & 31;
    int t = threadIdx.x;
    size_t off = (size_t)seg * 1024 + (size_t)t * 4;
    float4 S = make_float4(0.f, 0.f, 0.f, 0.f);
    for (int c = 0; c < NCHUNK; c++) {
        size_t base = ((size_t)((b * NCHUNK + c) * NHEADS + h)) * (HEADDIM * DSTATE) + off;
        *(float4*)(g_prefix + base) = S;
        float f = __expf(g_Acum[(b * NHEADS + h) * SEQLEN + c * CHUNKT + CHUNKT - 1]);
        float4 st = *(const float4*)(g_states + base);
        S.x = S.x * f + st.x;
        S.y = S.y * f + st.y;
        S.z = S.z * f + st.z;
        S.w = S.w * f + st.w;
    }
}

// ================= fused Y on tensor cores (fp16 2-term) =================
// smem: WH 0 (32K) | WL 32768 (32K) | X/S 65536 (16K) | Ac 81920 | eAc 82944
#define YSMEM 84992
__global__ void __launch_bounds__(512, 1) yfused_mma()
{
    extern __shared__ char ysm[];
    const uint32_t sb = smem_u32(ysm);
    float* Ac  = (float*)(ysm + 81920);
    float* eAc = (float*)(ysm + 82944);
    const int h = blockIdx.x, c = blockIdx.y, b = blockIdx.z;
    const int tid = threadIdx.x, lane = tid & 31, wid = tid >> 5;
    const int wr = wid >> 2, wc = wid & 3;
    const int brow = b * SEQLEN + c * CHUNKT;
    const size_t gbase = (size_t)(b * NCHUNK + c) * CHUNKT * CHUNKT;
    const size_t sbase = ((size_t)((b * NCHUNK + c) * NHEADS + h)) * (HEADDIM * DSTATE);

    if (tid < CHUNKT) {
        float a = g_Acum[(b * NHEADS + h) * SEQLEN + c * CHUNKT + tid];
        Ac[tid] = a;
        eAc[tid] = __expf(a);
    }

    float acc[4][4][4];
#pragma unroll
    for (int mt = 0; mt < 4; mt++)
#pragma unroll
        for (int nt = 0; nt < 4; nt++)
#pragma unroll
            for (int i = 0; i < 4; i++) acc[mt][nt][i] = 0.f;

    const int g = lane >> 3, li = lane & 7;
    const int arow  = (g & 1) * 8 + li;
    const int ahalf = g >> 1;
    const int bkt   = (g & 1) * 8 + li;
    const int bnt   = (g >> 1) * 8;
    const int brw2  = (g >> 1) * 8 + li;
    const int bhf2  = g & 1;

    // ---- part 1: W @ X over 4 j-tiles of 64 ----
    // Rows i < jt are fully masked and never read by an active warp (jt is
    // 64-aligned; warp wr computes rows wr*64..wr*64+63 only when
    // wr*64+63 >= jt), so stage W rows [jt, 256) only.
    for (int jt = 0; jt < CHUNKT; jt += 64) {
        __syncthreads();
        const int nrows = CHUNKT - jt;
        for (int idx = tid; idx < nrows * 16; idx += 512) {
            int i = jt + (idx >> 4), u4 = idx & 15;
            float4 gv = *(const float4*)&g_G[gbase + (size_t)i * 256 + jt + u4 * 4];
            float ai = Ac[i];
            int j0 = jt + u4 * 4;
            float v0 = (j0 + 0 <= i) ? __expf(ai - Ac[j0 + 0]) * gv.x : 0.f;
            float v1 = (j0 + 1 <= i) ? __expf(ai - Ac[j0 + 1]) * gv.y : 0.f;
            float v2 = (j0 + 2 <= i) ? __expf(ai - Ac[j0 + 2]) * gv.z : 0.f;
            float v3 = (j0 + 3 <= i) ? __expf(ai - Ac[j0 + 3]) * gv.w : 0.f;
            uint32_t lo01, lo23;
            uint32_t hi01 = pack2h(v0, v1, lo01);
            uint32_t hi23 = pack2h(v2, v3, lo23);
            uint32_t base = i * 128 + (((u4 >> 1) ^ (i & 7)) * 16) + (u4 & 1) * 8;
            *(uint2*)(ysm + base)         = make_uint2(hi01, hi23);
            *(uint2*)(ysm + 32768 + base) = make_uint2(lo01, lo23);
        }
        for (int idx = tid; idx < 64 * 16; idx += 512) {
            int l = idx >> 4, u = idx & 15;
            size_t src = (size_t)(brow + jt + l) * DINNER + h * HEADDIM + u * 8;
            uint32_t dst = l * 256 + ((u ^ (l & 7)) * 16);
            *(uint4*)(ysm + 65536 + dst) = *(const uint4*)(g_xf16 + src);
        }
        __syncthreads();
        if (wr * 64 + 63 >= jt) {
#pragma unroll
            for (int s = 0; s < 4; s++) {
                uint32_t afh[4][4], afl[4][4];
#pragma unroll
                for (int mt = 0; mt < 4; mt++) {
                    int row = wr * 64 + mt * 16 + arow;
                    uint32_t off = row * 128 + (((2 * s + ahalf) ^ (row & 7)) * 16);
                    LDSM_X4(afh[mt][0], afh[mt][1], afh[mt][2], afh[mt][3], sb + off);
                    LDSM_X4(afl[mt][0], afl[mt][1], afl[mt][2], afl[mt][3], sb + 32768 + off);
                }
#pragma unroll
                for (int ntp = 0; ntp < 2; ntp++) {
                    int krow = s * 16 + bkt;
                    int p = wc * 32 + ntp * 16 + bnt;
                    uint32_t off = krow * 256 + (((p >> 3) ^ (krow & 7)) * 16);
                    uint32_t b0, b1, b2, b3;
                    LDSM_X4_T(b0, b1, b2, b3, sb + 65536 + off);
#pragma unroll
                    for (int mt = 0; mt < 4; mt++) {
                        mma16816h(acc[mt][2*ntp+0], afh[mt], b0, b1);
                        mma16816h(acc[mt][2*ntp+0], afl[mt], b0, b1);
                        mma16816h(acc[mt][2*ntp+1], afh[mt], b2, b3);
                        mma16816h(acc[mt][2*ntp+1], afl[mt], b2, b3);
                    }
                }
            }
        }
    }

    // ---- part 2: Ce @ S^T (K = 64) ----
    __syncthreads();
    for (int idx = tid; idx < 256 * 16; idx += 512) {
        int i = idx >> 4, u4 = idx & 15;
        float4 cv = *(const float4*)&g_Cv[(size_t)(brow + i) * 64 + u4 * 4];
        float e = eAc[i];
        uint32_t lo01, lo23;
        uint32_t hi01 = pack2h(cv.x * e, cv.y * e, lo01);
        uint32_t hi23 = pack2h(cv.z * e, cv.w * e, lo23);
        uint32_t base = i * 128 + (((u4 >> 1) ^ (i & 7)) * 16) + (u4 & 1) * 8;
        *(uint2*)(ysm + base)         = make_uint2(hi01, hi23);
        *(uint2*)(ysm + 32768 + base) = make_uint2(lo01, lo23);
    }
    for (int idx = tid; idx < 128 * 16; idx += 512) {
        int p = idx >> 4, u4 = idx & 15;
        float4 sv = *(const float4*)&g_prefix[sbase + (size_t)p * 64 + u4 * 4];
        uint32_t h01 = rnd2h(sv.x, sv.y);
        uint32_t h23 = rnd2h(sv.z, sv.w);
        uint32_t base = p * 128 + (((u4 >> 1) ^ (p & 7)) * 16) + (u4 & 1) * 8;
        *(uint2*)(ysm + 65536 + base) = make_uint2(h01, h23);
    }
    __syncthreads();
#pragma unroll
    for (int s = 0; s < 4; s++) {
        uint32_t afh[4][4], afl[4][4];
#pragma unroll
        for (int mt = 0; mt < 4; mt++) {
            int row = wr * 64 + mt * 16 + arow;
            uint32_t off = row * 128 + (((2 * s + ahalf) ^ (row & 7)) * 16);
            LDSM_X4(afh[mt][0], afh[mt][1], afh[mt][2], afh[mt][3], sb + off);
            LDSM_X4(afl[mt][0], afl[mt][1], afl[mt][2], afl[mt][3], sb + 32768 + off);
        }
#pragma unroll
        for (int ntp = 0; ntp < 2; ntp++) {
            int row = wc * 32 + ntp * 16 + brw2;
            uint32_t off = row * 128 + (((2 * s + bhf2) ^ (row & 7)) * 16);
            uint32_t b0, b1, b2, b3;
            LDSM_X4(b0, b1, b2, b3, sb + 65536 + off);
#pragma unroll
            for (int mt = 0; mt < 4; mt++) {
                mma16816h(acc[mt][2*ntp+0], afh[mt], b0, b1);
                mma16816h(acc[mt][2*ntp+0], afl[mt], b0, b1);
                mma16816h(acc[mt][2*ntp+1], afh[mt], b2, b3);
                mma16816h(acc[mt][2*ntp+1], afl[mt], b2, b3);
            }
        }
    }

    // ---- epilogue ----
#pragma unroll
    for (int mt = 0; mt < 4; mt++) {
        int i0 = wr * 64 + mt * 16 + (lane >> 2);
#pragma unroll
        for (int nt = 0; nt < 4; nt++) {
            int col = h * HEADDIM + wc * 32 + nt * 8 + (lane & 3) * 2;
            *(float2*)(g_y + (size_t)(brow + i0) * DINNER + col) =
                make_float2(acc[mt][nt][0], acc[mt][nt][1]);
            *(float2*)(g_y + (size_t)(brow + i0 + 8) * DINNER + col) =
                make_float2(acc[mt][nt][2], acc[mt][nt][3]);
        }
    }
}

// ---------------- gating (y * silu(z)) + LayerNorm; emits fp16 hi/lo ----------------
__global__ void __launch_bounds__(256) ln_kernel(const float* __restrict__ lnw, const float* __restrict__ lnb)
{
    int row = blockIdx.x;
    int tid = threadIdx.x;
    float gv[4][4];
    float s = 0.f, s2 = 0.f;
#pragma unroll
    for (int q = 0; q < 4; q++) {
        int i = (tid + q * 256) * 4;
        float4 yv = *(const float4*)&g_y[(size_t)row * DINNER + i];
        float4 zv = *(const float4*)&g_zxbcdt[(size_t)row * DINPROJ + i];
        float v0 = yv.x * siluf(zv.x);
        float v1 = yv.y * siluf(zv.y);
        float v2 = yv.z * siluf(zv.z);
        float v3 = yv.w * siluf(zv.w);
        gv[q][0] = v0; gv[q][1] = v1; gv[q][2] = v2; gv[q][3] = v3;
        s += v0 + v1 + v2 + v3;
        s2 = fmaf(v0, v0, s2); s2 = fmaf(v1, v1, s2);
        s2 = fmaf(v2, v2, s2); s2 = fmaf(v3, v3, s2);
    }
    __shared__ float red[2][8];
#pragma unroll
    for (int off = 16; off > 0; off >>= 1) {
        s  += __shfl_xor_sync(0xffffffffu, s, off);
        s2 += __shfl_xor_sync(0xffffffffu, s2, off);
    }
    if ((tid & 31) == 0) { red[0][tid >> 5] = s; red[1][tid >> 5] = s2; }
    __syncthreads();
    if (tid == 0) {
        float a = 0.f, a2 = 0.f;
#pragma unroll
        for (int w = 0; w < 8; w++) { a += red[0][w]; a2 += red[1][w]; }
        red[0][0] = a; red[1][0] = a2;
    }
    __syncthreads();
    float mu  = red[0][0] * (1.f / DINNER);
    float var = red[1][0] * (1.f / DINNER) - mu * mu;
    float rstd = rsqrtf(var + LN_EPS);
#pragma unroll
    for (int q = 0; q < 4; q++) {
        int i = (tid + q * 256) * 4;
        float4 wv = *(const float4*)&lnw[i];
        float4 bv = *(const float4*)&lnb[i];
        float o0 = (gv[q][0] - mu) * rstd * wv.x + bv.x;
        float o1 = (gv[q][1] - mu) * rstd * wv.y + bv.y;
        float o2 = (gv[q][2] - mu) * rstd * wv.z + bv.z;
        float o3 = (gv[q][3] - mu) * rstd * wv.w + bv.w;
        uint32_t l01, l23;
        uint32_t h01 = pack2h(o0, o1, l01);
        uint32_t h23 = pack2h(o2, o3, l23);
        *(uint2*)&g_ynh[(size_t)row * DINNER + i] = make_uint2(h01, h23);
        *(uint2*)&g_ynl[(size_t)row * DINNER + i] = make_uint2(l01, l23);
    }
}

// ---------------- launch ----------------
extern "C" void kernel_launch(void* const* d_in, const int* in_sizes, int n_in,
                              void* d_out, int out_size)
{
    const float* u          = (const float*)d_in[0];
    const float* in_proj_w  = (const float*)d_in[1];
    const float* in_proj_b  = (const float*)d_in[2];
    const float* conv_w     = (const float*)d_in[3];
    const float* conv_b     = (const float*)d_in[4];
    const float* dt_bias    = (const float*)d_in[5];
    const float* A_log      = (const float*)d_in[6];
    const float* ln_w       = (const float*)d_in[7];
    const float* ln_b       = (const float*)d_in[8];
    const float* out_proj_w = (const float*)d_in[9];
    const float* out_proj_b = (const float*)d_in[10];
    float* out = (float*)d_out;

    float *zx, *gB, *gC, *gG;
    __half *uh, *ul, *w1h, *ynh, *ynl, *w2h;
    cudaGetSymbolAddress((void**)&zx,  g_zxbcdt);
    cudaGetSymbolAddress((void**)&gB,  g_Bv);
    cudaGetSymbolAddress((void**)&gC,  g_Cv);
    cudaGetSymbolAddress((void**)&gG,  g_G);
    cudaGetSymbolAddress((void**)&uh,  g_uh);
    cudaGetSymbolAddress((void**)&ul,  g_ul);
    cudaGetSymbolAddress((void**)&w1h, g_w1h);
    cudaGetSymbolAddress((void**)&ynh, g_ynh);
    cudaGetSymbolAddress((void**)&ynl, g_ynl);
    cudaGetSymbolAddress((void**)&w2h, g_w2h);

    cudaFuncSetAttribute(mma_gemm_nt, cudaFuncAttributeMaxDynamicSharedMemorySize, 3 * GST);
    cudaFuncSetAttribute(yfused_mma, cudaFuncAttributeMaxDynamicSharedMemorySize, YSMEM);

    // 0) fp32 -> fp16 conversions (vectorized)
    {
        long n1 = (long)NROWS * DMODEL / 4;
        split_f16<<<(unsigned)((n1 + 255) / 256), 256>>>(u, uh, ul, n1);
        long n2 = (long)DINPROJ * DMODEL / 4;
        round_f16<<<(unsigned)((n2 + 255) / 256), 256>>>(in_proj_w, w1h, n2);
        long n3 = (long)DMODEL * DINNER / 4;
        round_f16<<<(unsigned)((n3 + 255) / 256), 256>>>(out_proj_w, w2h, n3);
    }

    // 1) in_proj: M=8192, N=8352, K=2048
    mma_gemm_nt<<<dim3((DINPROJ + 255) / 256, NROWS / 128), 512, 3 * GST>>>(
        uh, ul, w1h, in_proj_b, zx, DINPROJ, DMODEL);

    // 2) fused dt softplus + per-chunk cumsum
    cumsum_kernel<<<dim3(NCHUNK, NHEADS, BATCH), CHUNKT>>>(dt_bias, A_log);

    // 3) causal conv + silu (8 outputs/thread)
    {
        long total = (long)(NROWS / 8) * CONVDIM;
        conv_kernel<<<(unsigned)((total + 255) / 256), 256>>>(conv_w, conv_b);
    }

    // 4) G = C @ B^T per (b,chunk)
    sgemm_nt<<<dim3(2, 2, BATCH * NCHUNK), 256>>>(
        gC, gB, nullptr, gG, CHUNKT, DSTATE,
        (long)CHUNKT * DSTATE, (long)CHUNKT * DSTATE, (long)CHUNKT * CHUNKT);

    // 5) chunk-local states on tensor cores
    states_mma<<<dim3(NHEADS, NCHUNK, BATCH), 256>>>();

    // 6) inter-chunk scan (8-way split)
    scan_kernel<<<BATCH * NHEADS * 8, 256>>>();

    // 7) fused Y on tensor cores
    yfused_mma<<<dim3(NHEADS, NCHUNK, BATCH), 512, YSMEM>>>();

    // 8) gate + layernorm (+ fp16 split of yn)
    ln_kernel<<<NROWS, 256>>>(ln_w, ln_b);

    // 9) out_proj: M=8192, N=2048, K=4096
    mma_gemm_nt<<<dim3(DMODEL / 256, NROWS / 128), 512, 3 * GST>>>(
        ynh, ynl, w2h, out_proj_b, out, DMODEL, DINNER);
}

// round 14
// speedup vs baseline: 1.1905x; 1.0115x over previous
#include <cuda_runtime.h>
#include <cuda_bf16.h>
#include <cuda_fp16.h>
#include <cstdint>
#include <math.h>

#define BATCH   2
#define SEQLEN  4096
#define DMODEL  2048
#define DINNER  4096
#define NHEADS  32
#define HEADDIM 128
#define DSTATE  64
#define NCHUNK  16
#define CHUNKT  256
#define CONVDIM 4224
#define DINPROJ 8352
#define NROWS   (BATCH*SEQLEN)
#define LN_EPS  1e-5f
#define LOG2E   1.4426950408889634f

// ---------------- scratch (device globals; no allocations allowed) ----------------
__device__ float g_zxbcdt[(size_t)NROWS * DINPROJ];
__device__ float g_Bv   [NROWS * DSTATE];
__device__ float g_Cv   [NROWS * DSTATE];
__device__ float g_dt   [NROWS * NHEADS];
__device__ float g_Acum [BATCH * NHEADS * SEQLEN];
__device__ float g_G    [(size_t)BATCH * NCHUNK * CHUNKT * CHUNKT];
__device__ float g_states[(size_t)BATCH * NCHUNK * NHEADS * HEADDIM * DSTATE];
__device__ float g_prefix[(size_t)BATCH * NCHUNK * NHEADS * HEADDIM * DSTATE];
__device__ float g_y    [(size_t)NROWS * DINNER];

// fp16 buffers (activations exact hi/lo, weights rounded)
__device__ __half g_uh [(size_t)NROWS * DMODEL];
__device__ __half g_ul [(size_t)NROWS * DMODEL];
__device__ __half g_w1h[(size_t)DINPROJ * DMODEL];
__device__ __half g_ynh[(size_t)NROWS * DINNER];
__device__ __half g_ynl[(size_t)NROWS * DINNER];
__device__ __half g_w2h[(size_t)DMODEL * DINNER];
__device__ __half g_xf16[(size_t)NROWS * DINNER];   // rounded fp16 of xdt

__device__ __forceinline__ float siluf(float x) { return x / (1.f + __expf(-x)); }

__device__ __forceinline__ uint32_t smem_u32(const void* p) {
    uint32_t a;
    asm("{ .reg .u64 t; cvta.to.shared.u64 t, %1; cvt.u32.u64 %0, t; }" : "=r"(a) : "l"(p));
    return a;
}

// pack two floats into fp16x2 hi; return hi, write lo (exact 2-term split, packed cvt)
__device__ __forceinline__ uint32_t pack2h(float a, float b, uint32_t& lo) {
    __half2 h = __floats2half2_rn(a, b);
    float2 hf = __half22float2(h);
    __half2 l = __floats2half2_rn(a - hf.x, b - hf.y);
    lo = *reinterpret_cast<uint32_t*>(&l);
    return *reinterpret_cast<uint32_t*>(&h);
}
__device__ __forceinline__ uint32_t rnd2h(float a, float b) {
    __half2 h = __floats2half2_rn(a, b);
    return *reinterpret_cast<uint32_t*>(&h);
}

// ================= split kernels (float4 vectorized; n divisible by 4) =================
__global__ void split_f16(const float* __restrict__ src,
                          __half* __restrict__ hi, __half* __restrict__ lo, long n4)
{
    long i = (long)blockIdx.x * blockDim.x + threadIdx.x;
    if (i >= n4) return;
    float4 x = ((const float4*)src)[i];
    uint32_t l01, l23;
    uint32_t h01 = pack2h(x.x, x.y, l01);
    uint32_t h23 = pack2h(x.z, x.w, l23);
    ((uint2*)hi)[i] = make_uint2(h01, h23);
    ((uint2*)lo)[i] = make_uint2(l01, l23);
}
// round two tensors in one launch
__global__ void round2_f16(const float* __restrict__ a, __half* __restrict__ da, long na4,
                           const float* __restrict__ b, __half* __restrict__ db, long nb4)
{
    long i = (long)blockIdx.x * blockDim.x + threadIdx.x;
    if (i < na4) {
        float4 x = ((const float4*)a)[i];
        ((uint2*)da)[i] = make_uint2(rnd2h(x.x, x.y), rnd2h(x.z, x.w));
    } else if (i < na4 + nb4) {
        long j = i - na4;
        float4 x = ((const float4*)b)[j];
        ((uint2*)db)[j] = make_uint2(rnd2h(x.x, x.y), rnd2h(x.z, x.w));
    }
}

// ================= tensor-core primitives =================
__device__ __forceinline__ void mma16816h(float* c, const uint32_t* a, uint32_t b0, uint32_t b1)
{
    asm volatile(
        "mma.sync.aligned.m16n8k16.row.col.f32.f16.f16.f32 "
        "{%0,%1,%2,%3}, {%4,%5,%6,%7}, {%8,%9}, {%0,%1,%2,%3};"
        : "+f"(c[0]), "+f"(c[1]), "+f"(c[2]), "+f"(c[3])
        : "r"(a[0]), "r"(a[1]), "r"(a[2]), "r"(a[3]), "r"(b0), "r"(b1));
}
#define LDSM_X4(r0, r1, r2, r3, addr) \
    asm volatile("ldmatrix.sync.aligned.m8n8.x4.shared.b16 {%0,%1,%2,%3}, [%4];" \
                 : "=r"(r0), "=r"(r1), "=r"(r2), "=r"(r3) : "r"(addr))
#define LDSM_X4_T(r0, r1, r2, r3, addr) \
    asm volatile("ldmatrix.sync.aligned.m8n8.x4.trans.shared.b16 {%0,%1,%2,%3}, [%4];" \
                 : "=r"(r0), "=r"(r1), "=r"(r2), "=r"(r3) : "r"(addr))
#define CP16(dst, src, sz) \
    asm volatile("cp.async.cg.shared.global [%0], [%1], 16, %2;" \
                 :: "r"(dst), "l"(src), "r"(sz))
#define CP_COMMIT() asm volatile("cp.async.commit_group;" ::: "memory")
#define CP_WAIT1()  asm volatile("cp.async.wait_group 1;" ::: "memory")
#define CP_WAIT0()  asm volatile("cp.async.wait_group 0;" ::: "memory")

// ================= fp16 2-MMA GEMM: C = (Ah+Al)*Bh^T + bias =================
// BM=128, BN=256, BK=64, 512 threads (16 warps, 32x64 warp tiles).
// 3-stage cp.async pipeline. A exact fp16 hi/lo (M mult of 128); B rounded fp16.
#define GST 65536
__global__ void __launch_bounds__(512, 1)
mma_gemm_nt(const __half* __restrict__ Ah, const __half* __restrict__ Al,
            const __half* __restrict__ Bh,
            const float* __restrict__ bias, float* __restrict__ C, int N, int K)
{
    extern __shared__ char smem[];
    const uint32_t sb = smem_u32(smem);
    const int tid = threadIdx.x, lane = tid & 31, wid = tid >> 5;
    const int wr = wid >> 2, wc = wid & 3;        // 4x4 warps, each 32(m) x 64(n)
    const int mbase = blockIdx.y * 128;
    const int nbase = blockIdx.x * 256;

    // A loader: 4 thr/row, 2 units; B loader: 2 thr/row, 4 units
    const int ra = tid >> 2, ua0 = (tid & 3) * 2;
    const int rb = tid >> 1, ub0 = (tid & 1) * 4;
    const bool bval = (nbase + rb) < N;
    const uint32_t bsz = bval ? 16u : 0u;
    const __half* gAh = Ah + (size_t)(mbase + ra) * K + ua0 * 8;
    const __half* gAl = Al + (size_t)(mbase + ra) * K + ua0 * 8;
    const __half* gBh = Bh + (size_t)(bval ? nbase + rb : 0) * K + ub0 * 8;
    const uint32_t dA0 = ra * 128 + (( ua0      ^ (ra & 7)) * 16);
    const uint32_t dA1 = ra * 128 + (((ua0 + 1) ^ (ra & 7)) * 16);
    uint32_t dB[4];
#pragma unroll
    for (int j = 0; j < 4; j++) dB[j] = rb * 128 + (((ub0 + j) ^ (rb & 7)) * 16);

    auto issue = [&](int st, int kt) {
        uint32_t s0 = sb + st * GST;
        CP16(s0 + dA0,         gAh + kt,     16);
        CP16(s0 + dA1,         gAh + kt + 8, 16);
        CP16(s0 + 16384 + dA0, gAl + kt,     16);
        CP16(s0 + 16384 + dA1, gAl + kt + 8, 16);
#pragma unroll
        for (int j = 0; j < 4; j++)
            CP16(s0 + 32768 + dB[j], gBh + kt + j * 8, bsz);
        CP_COMMIT();
    };

    float acc[2][8][4];
#pragma unroll
    for (int mt = 0; mt < 2; mt++)
#pragma unroll
        for (int nt = 0; nt < 8; nt++)
#pragma unroll
            for (int i = 0; i < 4; i++) acc[mt][nt][i] = 0.f;

    const int nk = K >> 6;
    issue(0, 0);
    issue(1, 64);

    const int g = lane >> 3, li = lane & 7;
    const int arow_lo = (g & 1) * 8 + li;
    const int ahalf   = g >> 1;
    const int brow_lo = (g >> 1) * 8 + li;
    const int bhalf   = g & 1;

    int stage = 0;
    for (int c = 0; c < nk; c++) {
        if (c + 1 < nk) CP_WAIT1(); else CP_WAIT0();
        __syncthreads();
        if (c + 2 < nk) {
            int st = stage + 2; if (st >= 3) st -= 3;
            issue(st, (c + 2) * 64);
        }
        const uint32_t s0 = sb + stage * GST;
#pragma unroll
        for (int s = 0; s < 4; s++) {
            uint32_t afh[2][4], afl[2][4];
#pragma unroll
            for (int mt = 0; mt < 2; mt++) {
                int row = wr * 32 + mt * 16 + arow_lo;
                uint32_t off = row * 128 + (((2 * s + ahalf) ^ (row & 7)) * 16);
                LDSM_X4(afh[mt][0], afh[mt][1], afh[mt][2], afh[mt][3], s0 + off);
                LDSM_X4(afl[mt][0], afl[mt][1], afl[mt][2], afl[mt][3], s0 + 16384 + off);
            }
#pragma unroll
            for (int ntp = 0; ntp < 4; ntp++) {
                int row = wc * 64 + ntp * 16 + brow_lo;
                uint32_t off = row * 128 + (((2 * s + bhalf) ^ (row & 7)) * 16);
                uint32_t b0, b1, b2, b3;
                LDSM_X4(b0, b1, b2, b3, s0 + 32768 + off);
#pragma unroll
                for (int mt = 0; mt < 2; mt++) {
                    mma16816h(acc[mt][2*ntp+0], afh[mt], b0, b1);
                    mma16816h(acc[mt][2*ntp+0], afl[mt], b0, b1);
                    mma16816h(acc[mt][2*ntp+1], afh[mt], b2, b3);
                    mma16816h(acc[mt][2*ntp+1], afl[mt], b2, b3);
                }
            }
        }
        stage++; if (stage >= 3) stage -= 3;
    }

#pragma unroll
    for (int mt = 0; mt < 2; mt++) {
        int r0 = mbase + wr * 32 + mt * 16 + (lane >> 2);
#pragma unroll
        for (int nt = 0; nt < 8; nt++) {
            int col = nbase + wc * 64 + nt * 8 + (lane & 3) * 2;
            if (col < N) {
                float b0 = bias ? bias[col] : 0.f;
                float b1 = bias ? bias[col + 1] : 0.f;
                float2 v0 = make_float2(acc[mt][nt][0] + b0, acc[mt][nt][1] + b1);
                float2 v1 = make_float2(acc[mt][nt][2] + b0, acc[mt][nt][3] + b1);
                *(float2*)(C + (size_t)r0 * N + col)       = v0;
                *(float2*)(C + (size_t)(r0 + 8) * N + col) = v1;
            }
        }
    }
}

// ---------------- small fp32 NT GEMM (G = C @ B^T); skips strictly-upper block ----------------
__global__ void __launch_bounds__(256)
sgemm_nt(const float* __restrict__ A, const float* __restrict__ B,
         const float* __restrict__ bias, float* __restrict__ C,
         int N, int K, long sA, long sB, long sC)
{
    // G is consumed only where col-tile <= row-tile region can be touched
    // (yfused stages rows i >= jt and reads j < jt+64); block (x=1,y=0) is never read.
    if (blockIdx.x * 128 > blockIdx.y * 128 + 127) return;

    __shared__ float As[16][128];
    __shared__ float Bs[16][128];
    const int tid  = threadIdx.x;
    const int tcol = tid & 15;
    const int trow = tid >> 4;
    const float* Ab = A + (size_t)blockIdx.z * sA + (size_t)blockIdx.y * 128 * K;
    const float* Bb = B + (size_t)blockIdx.z * sB + (size_t)blockIdx.x * 128 * K;
    const int nbase = blockIdx.x * 128;

    float acc[8][8];
#pragma unroll
    for (int m = 0; m < 8; m++)
#pragma unroll
        for (int n = 0; n < 8; n++) acc[m][n] = 0.f;

    const int lrow = tid >> 2;
    const int lcol = (tid & 3) * 4;

    for (int kt = 0; kt < K; kt += 16) {
#pragma unroll
        for (int it = 0; it < 2; it++) {
            int r = lrow + it * 64;
            float4 va = *(const float4*)(Ab + (size_t)r * K + kt + lcol);
            As[lcol+0][r] = va.x; As[lcol+1][r] = va.y;
            As[lcol+2][r] = va.z; As[lcol+3][r] = va.w;
            float4 vb;
            if (nbase + r < N) vb = *(const float4*)(Bb + (size_t)r * K + kt + lcol);
            else               vb = make_float4(0.f, 0.f, 0.f, 0.f);
            Bs[lcol+0][r] = vb.x; Bs[lcol+1][r] = vb.y;
            Bs[lcol+2][r] = vb.z; Bs[lcol+3][r] = vb.w;
        }
        __syncthreads();
#pragma unroll
        for (int k = 0; k < 16; k++) {
            float ra[8], rb[8];
#pragma unroll
            for (int m = 0; m < 8; m++) ra[m] = As[k][trow * 8 + m];
#pragma unroll
            for (int n = 0; n < 8; n++) rb[n] = Bs[k][tcol * 8 + n];
#pragma unroll
            for (int m = 0; m < 8; m++)
#pragma unroll
                for (int n = 0; n < 8; n++) acc[m][n] = fmaf(ra[m], rb[n], acc[m][n]);
        }
        __syncthreads();
    }
#pragma unroll
    for (int m = 0; m < 8; m++) {
        int row = blockIdx.y * 128 + trow * 8 + m;
#pragma unroll
        for (int n = 0; n < 8; n++) {
            int col = nbase + tcol * 8 + n;
            if (col < N) {
                float bv = bias ? bias[col] : 0.f;
                C[(size_t)blockIdx.z * sC + (size_t)row * N + col] = acc[m][n] + bv;
            }
        }
    }
}

// ---------------- fused dt softplus + per-chunk inclusive cumsum ----------------
__global__ void cumsum_kernel(const float* __restrict__ dt_bias, const float* __restrict__ A_log)
{
    int c = blockIdx.x, h = blockIdx.y, b = blockIdx.z;
    int t = threadIdx.x;
    __shared__ float s[CHUNKT];
    int row = b * SEQLEN + c * CHUNKT + t;
    float v = g_zxbcdt[(size_t)row * DINPROJ + DINNER + CONVDIM + h] + dt_bias[h];
    float dtv = (v > 20.f) ? v : log1pf(__expf(v));
    g_dt[row * NHEADS + h] = dtv;
    s[t] = -__expf(A_log[h]) * dtv;
    __syncthreads();
#pragma unroll
    for (int off = 1; off < CHUNKT; off <<= 1) {
        float x = (t >= off) ? s[t - off] : 0.f;
        __syncthreads();
        s[t] += x;
        __syncthreads();
    }
    g_Acum[(b * NHEADS + h) * SEQLEN + c * CHUNKT + t] = s[t];
}

// ---------------- causal depthwise conv + SiLU (8 outputs/thread) ----------------
__global__ void conv_kernel(const float* __restrict__ w, const float* __restrict__ cb)
{
    long idx = (long)blockIdx.x * blockDim.x + threadIdx.x;
    if (idx >= (long)(NROWS / 8) * CONVDIM) return;
    int c = (int)(idx % CONVDIM);
    int r0 = (int)(idx / CONVDIM) * 8;
    int l0 = r0 & (SEQLEN - 1);
    float v[11];
#pragma unroll
    for (int k = 0; k < 11; k++) {
        int l = l0 - 3 + k;
        v[k] = (l >= 0) ? g_zxbcdt[(size_t)(r0 - 3 + k) * DINPROJ + DINNER + c] : 0.f;
    }
    const float w0 = w[c * 4], w1 = w[c * 4 + 1], w2 = w[c * 4 + 2], w3 = w[c * 4 + 3];
    const float bias = cb[c];
#pragma unroll
    for (int j = 0; j < 8; j++) {
        float acc = bias;
        acc = fmaf(w0, v[j + 0], acc);
        acc = fmaf(w1, v[j + 1], acc);
        acc = fmaf(w2, v[j + 2], acc);
        acc = fmaf(w3, v[j + 3], acc);
        float out = siluf(acc);
        int r = r0 + j;
        if (c < DINNER) {
            float xv = out * g_dt[r * NHEADS + (c >> 7)];
            g_xf16[(size_t)r * DINNER + c] = __float2half_rn(xv);
        } else if (c < DINNER + DSTATE) {
            g_Bv[r * DSTATE + (c - DINNER)] = out;
        } else {
            g_Cv[r * DSTATE + (c - DINNER - DSTATE)] = out;
        }
    }
}

// ---------------- chunk-local states on tensor cores ----------------
__global__ void __launch_bounds__(256) states_mma()
{
    __shared__ __align__(16) char sX[64 * 256];
    __shared__ __align__(16) char sB[64 * 128];
    __shared__ float Ac[CHUNKT];
    const int h = blockIdx.x, c = blockIdx.y, b = blockIdx.z;
    const int tid = threadIdx.x, lane = tid & 31, wid = tid >> 5;
    const int wr = wid >> 1, wc = wid & 1;
    const int brow = b * SEQLEN + c * CHUNKT;
    const uint32_t sbX = smem_u32(sX), sbB = smem_u32(sB);

    Ac[tid] = g_Acum[(b * NHEADS + h) * SEQLEN + c * CHUNKT + tid];
    __syncthreads();
    const float Atot = Ac[CHUNKT - 1];

    float acc[2][4][4];
#pragma unroll
    for (int mt = 0; mt < 2; mt++)
#pragma unroll
        for (int nt = 0; nt < 4; nt++)
#pragma unroll
            for (int i = 0; i < 4; i++) acc[mt][nt][i] = 0.f;

    const int g = lane >> 3, li = lane & 7;
    const int akr = (g >> 1) * 8 + li;
    const int amc = (g & 1) * 8;
    const int bkr = (g & 1) * 8 + li;
    const int bnc = (g >> 1) * 8;

    for (int lt = 0; lt < CHUNKT; lt += 64) {
        if (lt) __syncthreads();
        for (int idx = tid; idx < 64 * 16; idx += 256) {
            int l = idx >> 4, u = idx & 15;
            size_t src = (size_t)(brow + lt + l) * DINNER + h * HEADDIM + u * 8;
            uint32_t dst = l * 256 + ((u ^ (l & 7)) * 16);
            *(uint4*)(sX + dst) = *(const uint4*)(g_xf16 + src);
        }
        for (int idx = tid; idx < 64 * 16; idx += 256) {
            int l = idx >> 4, u4 = idx & 15;
            float4 bv = *(const float4*)&g_Bv[(size_t)(brow + lt + l) * DSTATE + u4 * 4];
            float e = __expf(Atot - Ac[lt + l]);
            uint32_t h01 = rnd2h(bv.x * e, bv.y * e);
            uint32_t h23 = rnd2h(bv.z * e, bv.w * e);
            uint32_t dst = l * 128 + (((u4 >> 1) ^ (l & 7)) * 16) + (u4 & 1) * 8;
            *(uint2*)(sB + dst) = make_uint2(h01, h23);
        }
        __syncthreads();
#pragma unroll
        for (int s = 0; s < 4; s++) {
            uint32_t af[2][4];
#pragma unroll
            for (int mt = 0; mt < 2; mt++) {
                int kr = s * 16 + akr;
                int mc = wr * 32 + mt * 16 + amc;
                uint32_t off = kr * 256 + (((mc >> 3) ^ (kr & 7)) * 16);
                LDSM_X4_T(af[mt][0], af[mt][1], af[mt][2], af[mt][3], sbX + off);
            }
#pragma unroll
            for (int ntp = 0; ntp < 2; ntp++) {
                int kr = s * 16 + bkr;
                int nc = wc * 32 + ntp * 16 + bnc;
                uint32_t off = kr * 128 + (((nc >> 3) ^ (kr & 7)) * 16);
                uint32_t b0, b1, b2, b3;
                LDSM_X4_T(b0, b1, b2, b3, sbB + off);
#pragma unroll
                for (int mt = 0; mt < 2; mt++) {
                    mma16816h(acc[mt][2*ntp+0], af[mt], b0, b1);
                    mma16816h(acc[mt][2*ntp+1], af[mt], b2, b3);
                }
            }
        }
    }

    size_t base = ((size_t)((b * NCHUNK + c) * NHEADS + h)) * HEADDIM * DSTATE;
#pragma unroll
    for (int mt = 0; mt < 2; mt++) {
        int p0 = wr * 32 + mt * 16 + (lane >> 2);
#pragma unroll
        for (int nt = 0; nt < 4; nt++) {
            int n = wc * 32 + nt * 8 + (lane & 3) * 2;
            *(float2*)(g_states + base + (size_t)p0 * DSTATE + n) =
                make_float2(acc[mt][nt][0], acc[mt][nt][1]);
            *(float2*)(g_states + base + (size_t)(p0 + 8) * DSTATE + n) =
                make_float2(acc[mt][nt][2], acc[mt][nt][3]);
        }
    }
}

// ---------------- inter-chunk state scan (16-way split per (b,h)) ----------------
__global__ void scan_kernel()
{
    int bh = blockIdx.x >> 4, seg = blockIdx.x & 15;
    int b = bh >> 5, h = bh & 31;
    int t = threadIdx.x;    // 128 threads
    size_t off = (size_t)seg * 512 + (size_t)t * 4;
    float4 S = make_float4(0.f, 0.f, 0.f, 0.f);
    for (int c = 0; c < NCHUNK; c++) {
        size_t base = ((size_t)((b * NCHUNK + c) * NHEADS + h)) * (HEADDIM * DSTATE) + off;
        *(float4*)(g_prefix + base) = S;
        float f = __expf(g_Acum[(b * NHEADS + h) * SEQLEN + c * CHUNKT + CHUNKT - 1]);
        float4 st = *(const float4*)(g_states + base);
        S.x = S.x * f + st.x;
        S.y = S.y * f + st.y;
        S.z = S.z * f + st.z;
        S.w = S.w * f + st.w;
    }
}

// ================= fused Y on tensor cores (fp16 2-term) =================
// smem: WH 0 (32K) | WL 32768 (32K) | X/S 65536 (16K) | Ac2 81920 | eAc 82944
#define YSMEM 84992
__global__ void __launch_bounds__(512, 1) yfused_mma()
{
    extern __shared__ char ysm[];
    const uint32_t sb = smem_u32(ysm);
    float* Ac2 = (float*)(ysm + 81920);   // Acum * log2(e)
    float* eAc = (float*)(ysm + 82944);
    const int h = blockIdx.x, c = blockIdx.y, b = blockIdx.z;
    const int tid = threadIdx.x, lane = tid & 31, wid = tid >> 5;
    const int wr = wid >> 2, wc = wid & 3;
    const int brow = b * SEQLEN + c * CHUNKT;
    const size_t gbase = (size_t)(b * NCHUNK + c) * CHUNKT * CHUNKT;
    const size_t sbase = ((size_t)((b * NCHUNK + c) * NHEADS + h)) * (HEADDIM * DSTATE);

    if (tid < CHUNKT) {
        float a = g_Acum[(b * NHEADS + h) * SEQLEN + c * CHUNKT + tid];
        Ac2[tid] = a * LOG2E;
        eAc[tid] = __expf(a);
    }

    float acc[4][4][4];
#pragma unroll
    for (int mt = 0; mt < 4; mt++)
#pragma unroll
        for (int nt = 0; nt < 4; nt++)
#pragma unroll
            for (int i = 0; i < 4; i++) acc[mt][nt][i] = 0.f;

    const int g = lane >> 3, li = lane & 7;
    const int arow  = (g & 1) * 8 + li;
    const int ahalf = g >> 1;
    const int bkt   = (g & 1) * 8 + li;
    const int bnt   = (g >> 1) * 8;
    const int brw2  = (g >> 1) * 8 + li;
    const int bhf2  = g & 1;

    // ---- part 1: W @ X over 4 j-tiles of 64; stage W rows [jt,256) only ----
    for (int jt = 0; jt < CHUNKT; jt += 64) {
        __syncthreads();
        const int nrows = CHUNKT - jt;
        for (int idx = tid; idx < nrows * 16; idx += 512) {
            int i = jt + (idx >> 4), u4 = idx & 15;
            float4 gv = *(const float4*)&g_G[gbase + (size_t)i * 256 + jt + u4 * 4];
            float ai = Ac2[i];
            int j0 = jt + u4 * 4;
            float v0 = (j0 + 0 <= i) ? exp2f(ai - Ac2[j0 + 0]) * gv.x : 0.f;
            float v1 = (j0 + 1 <= i) ? exp2f(ai - Ac2[j0 + 1]) * gv.y : 0.f;
            float v2 = (j0 + 2 <= i) ? exp2f(ai - Ac2[j0 + 2]) * gv.z : 0.f;
            float v3 = (j0 + 3 <= i) ? exp2f(ai - Ac2[j0 + 3]) * gv.w : 0.f;
            uint32_t lo01, lo23;
            uint32_t hi01 = pack2h(v0, v1, lo01);
            uint32_t hi23 = pack2h(v2, v3, lo23);
            uint32_t base = i * 128 + (((u4 >> 1) ^ (i & 7)) * 16) + (u4 & 1) * 8;
            *(uint2*)(ysm + base)         = make_uint2(hi01, hi23);
            *(uint2*)(ysm + 32768 + base) = make_uint2(lo01, lo23);
        }
        for (int idx = tid; idx < 64 * 16; idx += 512) {
            int l = idx >> 4, u = idx & 15;
            size_t src = (size_t)(brow + jt + l) * DINNER + h * HEADDIM + u * 8;
            uint32_t dst = l * 256 + ((u ^ (l & 7)) * 16);
            *(uint4*)(ysm + 65536 + dst) = *(const uint4*)(g_xf16 + src);
        }
        __syncthreads();
        if (wr * 64 + 63 >= jt) {
#pragma unroll
            for (int s = 0; s < 4; s++) {
                uint32_t afh[4][4], afl[4][4];
#pragma unroll
                for (int mt = 0; mt < 4; mt++) {
                    int row = wr * 64 + mt * 16 + arow;
                    uint32_t off = row * 128 + (((2 * s + ahalf) ^ (row & 7)) * 16);
                    LDSM_X4(afh[mt][0], afh[mt][1], afh[mt][2], afh[mt][3], sb + off);
                    LDSM_X4(afl[mt][0], afl[mt][1], afl[mt][2], afl[mt][3], sb + 32768 + off);
                }
#pragma unroll
                for (int ntp = 0; ntp < 2; ntp++) {
                    int krow = s * 16 + bkt;
                    int p = wc * 32 + ntp * 16 + bnt;
                    uint32_t off = krow * 256 + (((p >> 3) ^ (krow & 7)) * 16);
                    uint32_t b0, b1, b2, b3;
                    LDSM_X4_T(b0, b1, b2, b3, sb + 65536 + off);
#pragma unroll
                    for (int mt = 0; mt < 4; mt++) {
                        mma16816h(acc[mt][2*ntp+0], afh[mt], b0, b1);
                        mma16816h(acc[mt][2*ntp+0], afl[mt], b0, b1);
                        mma16816h(acc[mt][2*ntp+1], afh[mt], b2, b3);
                        mma16816h(acc[mt][2*ntp+1], afl[mt], b2, b3);
                    }
                }
            }
        }
    }

    // ---- part 2: Ce @ S^T (K = 64) ----
    __syncthreads();
    for (int idx = tid; idx < 256 * 16; idx += 512) {
        int i = idx >> 4, u4 = idx & 15;
        float4 cv = *(const float4*)&g_Cv[(size_t)(brow + i) * 64 + u4 * 4];
        float e = eAc[i];
        uint32_t lo01, lo23;
        uint32_t hi01 = pack2h(cv.x * e, cv.y * e, lo01);
        uint32_t hi23 = pack2h(cv.z * e, cv.w * e, lo23);
        uint32_t base = i * 128 + (((u4 >> 1) ^ (i & 7)) * 16) + (u4 & 1) * 8;
        *(uint2*)(ysm + base)         = make_uint2(hi01, hi23);
        *(uint2*)(ysm + 32768 + base) = make_uint2(lo01, lo23);
    }
    for (int idx = tid; idx < 128 * 16; idx += 512) {
        int p = idx >> 4, u4 = idx & 15;
        float4 sv = *(const float4*)&g_prefix[sbase + (size_t)p * 64 + u4 * 4];
        uint32_t h01 = rnd2h(sv.x, sv.y);
        uint32_t h23 = rnd2h(sv.z, sv.w);
        uint32_t base = p * 128 + (((u4 >> 1) ^ (p & 7)) * 16) + (u4 & 1) * 8;
        *(uint2*)(ysm + 65536 + base) = make_uint2(h01, h23);
    }
    __syncthreads();
#pragma unroll
    for (int s = 0; s < 4; s++) {
        uint32_t afh[4][4], afl[4][4];
#pragma unroll
        for (int mt = 0; mt < 4; mt++) {
            int row = wr * 64 + mt * 16 + arow;
            uint32_t off = row * 128 + (((2 * s + ahalf) ^ (row & 7)) * 16);
            LDSM_X4(afh[mt][0], afh[mt][1], afh[mt][2], afh[mt][3], sb + off);
            LDSM_X4(afl[mt][0], afl[mt][1], afl[mt][2], afl[mt][3], sb + 32768 + off);
        }
#pragma unroll
        for (int ntp = 0; ntp < 2; ntp++) {
            int row = wc * 32 + ntp * 16 + brw2;
            uint32_t off = row * 128 + (((2 * s + bhf2) ^ (row & 7)) * 16);
            uint32_t b0, b1, b2, b3;
            LDSM_X4(b0, b1, b2, b3, sb + 65536 + off);
#pragma unroll
            for (int mt = 0; mt < 4; mt++) {
                mma16816h(acc[mt][2*ntp+0], afh[mt], b0, b1);
                mma16816h(acc[mt][2*ntp+0], afl[mt], b0, b1);
                mma16816h(acc[mt][2*ntp+1], afh[mt], b2, b3);
                mma16816h(acc[mt][2*ntp+1], afl[mt], b2, b3);
            }
        }
    }

    // ---- epilogue ----
#pragma unroll
    for (int mt = 0; mt < 4; mt++) {
        int i0 = wr * 64 + mt * 16 + (lane >> 2);
#pragma unroll
        for (int nt = 0; nt < 4; nt++) {
            int col = h * HEADDIM + wc * 32 + nt * 8 + (lane & 3) * 2;
            *(float2*)(g_y + (size_t)(brow + i0) * DINNER + col) =
                make_float2(acc[mt][nt][0], acc[mt][nt][1]);
            *(float2*)(g_y + (size_t)(brow + i0 + 8) * DINNER + col) =
                make_float2(acc[mt][nt][2], acc[mt][nt][3]);
        }
    }
}

// ---------------- gating (y * silu(z)) + LayerNorm; emits fp16 hi/lo ----------------
__global__ void __launch_bounds__(256) ln_kernel(const float* __restrict__ lnw, const float* __restrict__ lnb)
{
    int row = blockIdx.x;
    int tid = threadIdx.x;
    float gv[4][4];
    float s = 0.f, s2 = 0.f;
#pragma unroll
    for (int q = 0; q < 4; q++) {
        int i = (tid + q * 256) * 4;
        float4 yv = *(const float4*)&g_y[(size_t)row * DINNER + i];
        float4 zv = *(const float4*)&g_zxbcdt[(size_t)row * DINPROJ + i];
        float v0 = yv.x * siluf(zv.x);
        float v1 = yv.y * siluf(zv.y);
        float v2 = yv.z * siluf(zv.z);
        float v3 = yv.w * siluf(zv.w);
        gv[q][0] = v0; gv[q][1] = v1; gv[q][2] = v2; gv[q][3] = v3;
        s += v0 + v1 + v2 + v3;
        s2 = fmaf(v0, v0, s2); s2 = fmaf(v1, v1, s2);
        s2 = fmaf(v2, v2, s2); s2 = fmaf(v3, v3, s2);
    }
    __shared__ float red[2][8];
#pragma unroll
    for (int off = 16; off > 0; off >>= 1) {
        s  += __shfl_xor_sync(0xffffffffu, s, off);
        s2 += __shfl_xor_sync(0xffffffffu, s2, off);
    }
    if ((tid & 31) == 0) { red[0][tid >> 5] = s; red[1][tid >> 5] = s2; }
    __syncthreads();
    if (tid == 0) {
        float a = 0.f, a2 = 0.f;
#pragma unroll
        for (int w = 0; w < 8; w++) { a += red[0][w]; a2 += red[1][w]; }
        red[0][0] = a; red[1][0] = a2;
    }
    __syncthreads();
    float mu  = red[0][0] * (1.f / DINNER);
    float var = red[1][0] * (1.f / DINNER) - mu * mu;
    float rstd = rsqrtf(var + LN_EPS);
#pragma unroll
    for (int q = 0; q < 4; q++) {
        int i = (tid + q * 256) * 4;
        float4 wv = *(const float4*)&lnw[i];
        float4 bv = *(const float4*)&lnb[i];
        float o0 = (gv[q][0] - mu) * rstd * wv.x + bv.x;
        float o1 = (gv[q][1] - mu) * rstd * wv.y + bv.y;
        float o2 = (gv[q][2] - mu) * rstd * wv.z + bv.z;
        float o3 = (gv[q][3] - mu) * rstd * wv.w + bv.w;
        uint32_t l01, l23;
        uint32_t h01 = pack2h(o0, o1, l01);
        uint32_t h23 = pack2h(o2, o3, l23);
        *(uint2*)&g_ynh[(size_t)row * DINNER + i] = make_uint2(h01, h23);
        *(uint2*)&g_ynl[(size_t)row * DINNER + i] = make_uint2(l01, l23);
    }
}

// ---------------- launch ----------------
extern "C" void kernel_launch(void* const* d_in, const int* in_sizes, int n_in,
                              void* d_out, int out_size)
{
    const float* u          = (const float*)d_in[0];
    const float* in_proj_w  = (const float*)d_in[1];
    const float* in_proj_b  = (const float*)d_in[2];
    const float* conv_w     = (const float*)d_in[3];
    const float* conv_b     = (const float*)d_in[4];
    const float* dt_bias    = (const float*)d_in[5];
    const float* A_log      = (const float*)d_in[6];
    const float* ln_w       = (const float*)d_in[7];
    const float* ln_b       = (const float*)d_in[8];
    const float* out_proj_w = (const float*)d_in[9];
    const float* out_proj_b = (const float*)d_in[10];
    float* out = (float*)d_out;

    float *zx, *gB, *gC, *gG;
    __half *uh, *ul, *w1h, *ynh, *ynl, *w2h;
    cudaGetSymbolAddress((void**)&zx,  g_zxbcdt);
    cudaGetSymbolAddress((void**)&gB,  g_Bv);
    cudaGetSymbolAddress((void**)&gC,  g_Cv);
    cudaGetSymbolAddress((void**)&gG,  g_G);
    cudaGetSymbolAddress((void**)&uh,  g_uh);
    cudaGetSymbolAddress((void**)&ul,  g_ul);
    cudaGetSymbolAddress((void**)&w1h, g_w1h);
    cudaGetSymbolAddress((void**)&ynh, g_ynh);
    cudaGetSymbolAddress((void**)&ynl, g_ynl);
    cudaGetSymbolAddress((void**)&w2h, g_w2h);

    cudaFuncSetAttribute(mma_gemm_nt, cudaFuncAttributeMaxDynamicSharedMemorySize, 3 * GST);
    cudaFuncSetAttribute(yfused_mma, cudaFuncAttributeMaxDynamicSharedMemorySize, YSMEM);

    // 0) fp32 -> fp16 conversions (vectorized; both weights in one launch)
    {
        long n1 = (long)NROWS * DMODEL / 4;
        split_f16<<<(unsigned)((n1 + 255) / 256), 256>>>(u, uh, ul, n1);
        long n2 = (long)DINPROJ * DMODEL / 4;
        long n3 = (long)DMODEL * DINNER / 4;
        round2_f16<<<(unsigned)((n2 + n3 + 255) / 256), 256>>>(
            in_proj_w, w1h, n2, out_proj_w, w2h, n3);
    }

    // 1) in_proj: M=8192, N=8352, K=2048
    mma_gemm_nt<<<dim3((DINPROJ + 255) / 256, NROWS / 128), 512, 3 * GST>>>(
        uh, ul, w1h, in_proj_b, zx, DINPROJ, DMODEL);

    // 2) fused dt softplus + per-chunk cumsum
    cumsum_kernel<<<dim3(NCHUNK, NHEADS, BATCH), CHUNKT>>>(dt_bias, A_log);

    // 3) causal conv + silu (8 outputs/thread)
    {
        long total = (long)(NROWS / 8) * CONVDIM;
        conv_kernel<<<(unsigned)((total + 255) / 256), 256>>>(conv_w, conv_b);
    }

    // 4) G = C @ B^T per (b,chunk)  (upper-right block skipped inside)
    sgemm_nt<<<dim3(2, 2, BATCH * NCHUNK), 256>>>(
        gC, gB, nullptr, gG, CHUNKT, DSTATE,
        (long)CHUNKT * DSTATE, (long)CHUNKT * DSTATE, (long)CHUNKT * CHUNKT);

    // 5) chunk-local states on tensor cores
    states_mma<<<dim3(NHEADS, NCHUNK, BATCH), 256>>>();

    // 6) inter-chunk scan (16-way split)
    scan_kernel<<<BATCH * NHEADS * 16, 128>>>();

    // 7) fused Y on tensor cores
    yfused_mma<<<dim3(NHEADS, NCHUNK, BATCH), 512, YSMEM>>>();

    // 8) gate + layernorm (+ fp16 split of yn)
    ln_kernel<<<NROWS, 256>>>(ln_w, ln_b);

    // 9) out_proj: M=8192, N=2048, K=4096
    mma_gemm_nt<<<dim3(DMODEL / 256, NROWS / 128), 512, 3 * GST>>>(
        ynh, ynl, w2h, out_proj_b, out, DMODEL, DINNER);
}

// round 15
// speedup vs baseline: 1.3527x; 1.1363x over previous
#include <cuda_runtime.h>
#include <cuda_bf16.h>
#include <cuda_fp16.h>
#include <cstdint>
#include <math.h>

#define BATCH   2
#define SEQLEN  4096
#define DMODEL  2048
#define DINNER  4096
#define NHEADS  32
#define HEADDIM 128
#define DSTATE  64
#define NCHUNK  16
#define CHUNKT  256
#define CONVDIM 4224
#define DINPROJ 8352
#define NROWS   (BATCH*SEQLEN)
#define LN_EPS  1e-5f
#define LOG2E   1.4426950408889634f

// ---------------- scratch (device globals; no allocations allowed) ----------------
__device__ float g_zxbcdt[(size_t)NROWS * DINPROJ];
__device__ float g_Bv   [NROWS * DSTATE];
__device__ float g_Cv   [NROWS * DSTATE];
__device__ float g_dt   [NROWS * NHEADS];
__device__ float g_Acum [BATCH * NHEADS * SEQLEN];
__device__ float g_G    [(size_t)BATCH * NCHUNK * CHUNKT * CHUNKT];
__device__ float g_states[(size_t)BATCH * NCHUNK * NHEADS * HEADDIM * DSTATE];
__device__ float g_prefix[(size_t)BATCH * NCHUNK * NHEADS * HEADDIM * DSTATE];
__device__ float g_y    [(size_t)NROWS * DINNER];

// fp16 buffers
__device__ __half g_uh [(size_t)NROWS * DMODEL];
__device__ __half g_ul [(size_t)NROWS * DMODEL];
__device__ __half g_w1h[(size_t)DINPROJ * DMODEL];
__device__ __half g_ynh[(size_t)NROWS * DINNER];
__device__ __half g_w2h[(size_t)DMODEL * DINNER];
__device__ __half g_xf16[(size_t)NROWS * DINNER];   // rounded fp16 of xdt

__device__ __forceinline__ float siluf(float x) { return x / (1.f + __expf(-x)); }

__device__ __forceinline__ uint32_t smem_u32(const void* p) {
    uint32_t a;
    asm("{ .reg .u64 t; cvta.to.shared.u64 t, %1; cvt.u32.u64 %0, t; }" : "=r"(a) : "l"(p));
    return a;
}

// pack two floats into fp16x2 hi; return hi, write lo (exact 2-term split, packed cvt)
__device__ __forceinline__ uint32_t pack2h(float a, float b, uint32_t& lo) {
    __half2 h = __floats2half2_rn(a, b);
    float2 hf = __half22float2(h);
    __half2 l = __floats2half2_rn(a - hf.x, b - hf.y);
    lo = *reinterpret_cast<uint32_t*>(&l);
    return *reinterpret_cast<uint32_t*>(&h);
}
__device__ __forceinline__ uint32_t rnd2h(float a, float b) {
    __half2 h = __floats2half2_rn(a, b);
    return *reinterpret_cast<uint32_t*>(&h);
}

// ================= split kernels (float4 vectorized; n divisible by 4) =================
__global__ void split_f16(const float* __restrict__ src,
                          __half* __restrict__ hi, __half* __restrict__ lo, long n4)
{
    long i = (long)blockIdx.x * blockDim.x + threadIdx.x;
    if (i >= n4) return;
    float4 x = ((const float4*)src)[i];
    uint32_t l01, l23;
    uint32_t h01 = pack2h(x.x, x.y, l01);
    uint32_t h23 = pack2h(x.z, x.w, l23);
    ((uint2*)hi)[i] = make_uint2(h01, h23);
    ((uint2*)lo)[i] = make_uint2(l01, l23);
}
// round two tensors in one launch
__global__ void round2_f16(const float* __restrict__ a, __half* __restrict__ da, long na4,
                           const float* __restrict__ b, __half* __restrict__ db, long nb4)
{
    long i = (long)blockIdx.x * blockDim.x + threadIdx.x;
    if (i < na4) {
        float4 x = ((const float4*)a)[i];
        ((uint2*)da)[i] = make_uint2(rnd2h(x.x, x.y), rnd2h(x.z, x.w));
    } else if (i < na4 + nb4) {
        long j = i - na4;
        float4 x = ((const float4*)b)[j];
        ((uint2*)db)[j] = make_uint2(rnd2h(x.x, x.y), rnd2h(x.z, x.w));
    }
}

// ================= tensor-core primitives =================
__device__ __forceinline__ void mma16816h(float* c, const uint32_t* a, uint32_t b0, uint32_t b1)
{
    asm volatile(
        "mma.sync.aligned.m16n8k16.row.col.f32.f16.f16.f32 "
        "{%0,%1,%2,%3}, {%4,%5,%6,%7}, {%8,%9}, {%0,%1,%2,%3};"
        : "+f"(c[0]), "+f"(c[1]), "+f"(c[2]), "+f"(c[3])
        : "r"(a[0]), "r"(a[1]), "r"(a[2]), "r"(a[3]), "r"(b0), "r"(b1));
}
#define LDSM_X4(r0, r1, r2, r3, addr) \
    asm volatile("ldmatrix.sync.aligned.m8n8.x4.shared.b16 {%0,%1,%2,%3}, [%4];" \
                 : "=r"(r0), "=r"(r1), "=r"(r2), "=r"(r3) : "r"(addr))
#define LDSM_X4_T(r0, r1, r2, r3, addr) \
    asm volatile("ldmatrix.sync.aligned.m8n8.x4.trans.shared.b16 {%0,%1,%2,%3}, [%4];" \
                 : "=r"(r0), "=r"(r1), "=r"(r2), "=r"(r3) : "r"(addr))
#define CP16(dst, src, sz) \
    asm volatile("cp.async.cg.shared.global [%0], [%1], 16, %2;" \
                 :: "r"(dst), "l"(src), "r"(sz))
#define CP_COMMIT() asm volatile("cp.async.commit_group;" ::: "memory")
#define CP_WAIT1()  asm volatile("cp.async.wait_group 1;" ::: "memory")
#define CP_WAIT0()  asm volatile("cp.async.wait_group 0;" ::: "memory")

// ================= fp16 2-MMA GEMM: C = (Ah+Al)*Bh^T + bias (in_proj) =================
#define GST 65536
__global__ void __launch_bounds__(512, 1)
mma_gemm_nt(const __half* __restrict__ Ah, const __half* __restrict__ Al,
            const __half* __restrict__ Bh,
            const float* __restrict__ bias, float* __restrict__ C, int N, int K)
{
    extern __shared__ char smem[];
    const uint32_t sb = smem_u32(smem);
    const int tid = threadIdx.x, lane = tid & 31, wid = tid >> 5;
    const int wr = wid >> 2, wc = wid & 3;
    const int mbase = blockIdx.y * 128;
    const int nbase = blockIdx.x * 256;

    const int ra = tid >> 2, ua0 = (tid & 3) * 2;
    const int rb = tid >> 1, ub0 = (tid & 1) * 4;
    const bool bval = (nbase + rb) < N;
    const uint32_t bsz = bval ? 16u : 0u;
    const __half* gAh = Ah + (size_t)(mbase + ra) * K + ua0 * 8;
    const __half* gAl = Al + (size_t)(mbase + ra) * K + ua0 * 8;
    const __half* gBh = Bh + (size_t)(bval ? nbase + rb : 0) * K + ub0 * 8;
    const uint32_t dA0 = ra * 128 + (( ua0      ^ (ra & 7)) * 16);
    const uint32_t dA1 = ra * 128 + (((ua0 + 1) ^ (ra & 7)) * 16);
    uint32_t dB[4];
#pragma unroll
    for (int j = 0; j < 4; j++) dB[j] = rb * 128 + (((ub0 + j) ^ (rb & 7)) * 16);

    auto issue = [&](int st, int kt) {
        uint32_t s0 = sb + st * GST;
        CP16(s0 + dA0,         gAh + kt,     16);
        CP16(s0 + dA1,         gAh + kt + 8, 16);
        CP16(s0 + 16384 + dA0, gAl + kt,     16);
        CP16(s0 + 16384 + dA1, gAl + kt + 8, 16);
#pragma unroll
        for (int j = 0; j < 4; j++)
            CP16(s0 + 32768 + dB[j], gBh + kt + j * 8, bsz);
        CP_COMMIT();
    };

    float acc[2][8][4];
#pragma unroll
    for (int mt = 0; mt < 2; mt++)
#pragma unroll
        for (int nt = 0; nt < 8; nt++)
#pragma unroll
            for (int i = 0; i < 4; i++) acc[mt][nt][i] = 0.f;

    const int nk = K >> 6;
    issue(0, 0);
    issue(1, 64);

    const int g = lane >> 3, li = lane & 7;
    const int arow_lo = (g & 1) * 8 + li;
    const int ahalf   = g >> 1;
    const int brow_lo = (g >> 1) * 8 + li;
    const int bhalf   = g & 1;

    int stage = 0;
    for (int c = 0; c < nk; c++) {
        if (c + 1 < nk) CP_WAIT1(); else CP_WAIT0();
        __syncthreads();
        if (c + 2 < nk) {
            int st = stage + 2; if (st >= 3) st -= 3;
            issue(st, (c + 2) * 64);
        }
        const uint32_t s0 = sb + stage * GST;
#pragma unroll
        for (int s = 0; s < 4; s++) {
            uint32_t afh[2][4], afl[2][4];
#pragma unroll
            for (int mt = 0; mt < 2; mt++) {
                int row = wr * 32 + mt * 16 + arow_lo;
                uint32_t off = row * 128 + (((2 * s + ahalf) ^ (row & 7)) * 16);
                LDSM_X4(afh[mt][0], afh[mt][1], afh[mt][2], afh[mt][3], s0 + off);
                LDSM_X4(afl[mt][0], afl[mt][1], afl[mt][2], afl[mt][3], s0 + 16384 + off);
            }
#pragma unroll
            for (int ntp = 0; ntp < 4; ntp++) {
                int row = wc * 64 + ntp * 16 + brow_lo;
                uint32_t off = row * 128 + (((2 * s + bhalf) ^ (row & 7)) * 16);
                uint32_t b0, b1, b2, b3;
                LDSM_X4(b0, b1, b2, b3, s0 + 32768 + off);
#pragma unroll
                for (int mt = 0; mt < 2; mt++) {
                    mma16816h(acc[mt][2*ntp+0], afh[mt], b0, b1);
                    mma16816h(acc[mt][2*ntp+0], afl[mt], b0, b1);
                    mma16816h(acc[mt][2*ntp+1], afh[mt], b2, b3);
                    mma16816h(acc[mt][2*ntp+1], afl[mt], b2, b3);
                }
            }
        }
        stage++; if (stage >= 3) stage -= 3;
    }

#pragma unroll
    for (int mt = 0; mt < 2; mt++) {
        int r0 = mbase + wr * 32 + mt * 16 + (lane >> 2);
#pragma unroll
        for (int nt = 0; nt < 8; nt++) {
            int col = nbase + wc * 64 + nt * 8 + (lane & 3) * 2;
            if (col < N) {
                float b0 = bias ? bias[col] : 0.f;
                float b1 = bias ? bias[col + 1] : 0.f;
                float2 v0 = make_float2(acc[mt][nt][0] + b0, acc[mt][nt][1] + b1);
                float2 v1 = make_float2(acc[mt][nt][2] + b0, acc[mt][nt][3] + b1);
                *(float2*)(C + (size_t)r0 * N + col)       = v0;
                *(float2*)(C + (size_t)(r0 + 8) * N + col) = v1;
            }
        }
    }
}

// ================= fp16 1-MMA GEMM: C = Ah*Bh^T + bias (out_proj) =================
// Same tiling; A is a single rounded fp16 (no lo term). 48KB/stage x 3 stages.
#define GST1 49152
__global__ void __launch_bounds__(512, 1)
mma_gemm_nt1(const __half* __restrict__ Ah, const __half* __restrict__ Bh,
             const float* __restrict__ bias, float* __restrict__ C, int N, int K)
{
    extern __shared__ char smem[];
    const uint32_t sb = smem_u32(smem);
    const int tid = threadIdx.x, lane = tid & 31, wid = tid >> 5;
    const int wr = wid >> 2, wc = wid & 3;
    const int mbase = blockIdx.y * 128;
    const int nbase = blockIdx.x * 256;

    const int ra = tid >> 2, ua0 = (tid & 3) * 2;
    const int rb = tid >> 1, ub0 = (tid & 1) * 4;
    const bool bval = (nbase + rb) < N;
    const uint32_t bsz = bval ? 16u : 0u;
    const __half* gAh = Ah + (size_t)(mbase + ra) * K + ua0 * 8;
    const __half* gBh = Bh + (size_t)(bval ? nbase + rb : 0) * K + ub0 * 8;
    const uint32_t dA0 = ra * 128 + (( ua0      ^ (ra & 7)) * 16);
    const uint32_t dA1 = ra * 128 + (((ua0 + 1) ^ (ra & 7)) * 16);
    uint32_t dB[4];
#pragma unroll
    for (int j = 0; j < 4; j++) dB[j] = rb * 128 + (((ub0 + j) ^ (rb & 7)) * 16);

    auto issue = [&](int st, int kt) {
        uint32_t s0 = sb + st * GST1;
        CP16(s0 + dA0, gAh + kt,     16);
        CP16(s0 + dA1, gAh + kt + 8, 16);
#pragma unroll
        for (int j = 0; j < 4; j++)
            CP16(s0 + 16384 + dB[j], gBh + kt + j * 8, bsz);
        CP_COMMIT();
    };

    float acc[2][8][4];
#pragma unroll
    for (int mt = 0; mt < 2; mt++)
#pragma unroll
        for (int nt = 0; nt < 8; nt++)
#pragma unroll
            for (int i = 0; i < 4; i++) acc[mt][nt][i] = 0.f;

    const int nk = K >> 6;
    issue(0, 0);
    issue(1, 64);

    const int g = lane >> 3, li = lane & 7;
    const int arow_lo = (g & 1) * 8 + li;
    const int ahalf   = g >> 1;
    const int brow_lo = (g >> 1) * 8 + li;
    const int bhalf   = g & 1;

    int stage = 0;
    for (int c = 0; c < nk; c++) {
        if (c + 1 < nk) CP_WAIT1(); else CP_WAIT0();
        __syncthreads();
        if (c + 2 < nk) {
            int st = stage + 2; if (st >= 3) st -= 3;
            issue(st, (c + 2) * 64);
        }
        const uint32_t s0 = sb + stage * GST1;
#pragma unroll
        for (int s = 0; s < 4; s++) {
            uint32_t af[2][4];
#pragma unroll
            for (int mt = 0; mt < 2; mt++) {
                int row = wr * 32 + mt * 16 + arow_lo;
                uint32_t off = row * 128 + (((2 * s + ahalf) ^ (row & 7)) * 16);
                LDSM_X4(af[mt][0], af[mt][1], af[mt][2], af[mt][3], s0 + off);
            }
#pragma unroll
            for (int ntp = 0; ntp < 4; ntp++) {
                int row = wc * 64 + ntp * 16 + brow_lo;
                uint32_t off = row * 128 + (((2 * s + bhalf) ^ (row & 7)) * 16);
                uint32_t b0, b1, b2, b3;
                LDSM_X4(b0, b1, b2, b3, s0 + 16384 + off);
#pragma unroll
                for (int mt = 0; mt < 2; mt++) {
                    mma16816h(acc[mt][2*ntp+0], af[mt], b0, b1);
                    mma16816h(acc[mt][2*ntp+1], af[mt], b2, b3);
                }
            }
        }
        stage++; if (stage >= 3) stage -= 3;
    }

#pragma unroll
    for (int mt = 0; mt < 2; mt++) {
        int r0 = mbase + wr * 32 + mt * 16 + (lane >> 2);
#pragma unroll
        for (int nt = 0; nt < 8; nt++) {
            int col = nbase + wc * 64 + nt * 8 + (lane & 3) * 2;
            if (col < N) {
                float b0 = bias ? bias[col] : 0.f;
                float b1 = bias ? bias[col + 1] : 0.f;
                float2 v0 = make_float2(acc[mt][nt][0] + b0, acc[mt][nt][1] + b1);
                float2 v1 = make_float2(acc[mt][nt][2] + b0, acc[mt][nt][3] + b1);
                *(float2*)(C + (size_t)r0 * N + col)       = v0;
                *(float2*)(C + (size_t)(r0 + 8) * N + col) = v1;
            }
        }
    }
}

// ---------------- small fp32 NT GEMM (G = C @ B^T); skips strictly-upper block ----------------
__global__ void __launch_bounds__(256)
sgemm_nt(const float* __restrict__ A, const float* __restrict__ B,
         const float* __restrict__ bias, float* __restrict__ C,
         int N, int K, long sA, long sB, long sC)
{
    if (blockIdx.x * 128 > blockIdx.y * 128 + 127) return;

    __shared__ float As[16][128];
    __shared__ float Bs[16][128];
    const int tid  = threadIdx.x;
    const int tcol = tid & 15;
    const int trow = tid >> 4;
    const float* Ab = A + (size_t)blockIdx.z * sA + (size_t)blockIdx.y * 128 * K;
    const float* Bb = B + (size_t)blockIdx.z * sB + (size_t)blockIdx.x * 128 * K;
    const int nbase = blockIdx.x * 128;

    float acc[8][8];
#pragma unroll
    for (int m = 0; m < 8; m++)
#pragma unroll
        for (int n = 0; n < 8; n++) acc[m][n] = 0.f;

    const int lrow = tid >> 2;
    const int lcol = (tid & 3) * 4;

    for (int kt = 0; kt < K; kt += 16) {
#pragma unroll
        for (int it = 0; it < 2; it++) {
            int r = lrow + it * 64;
            float4 va = *(const float4*)(Ab + (size_t)r * K + kt + lcol);
            As[lcol+0][r] = va.x; As[lcol+1][r] = va.y;
            As[lcol+2][r] = va.z; As[lcol+3][r] = va.w;
            float4 vb;
            if (nbase + r < N) vb = *(const float4*)(Bb + (size_t)r * K + kt + lcol);
            else               vb = make_float4(0.f, 0.f, 0.f, 0.f);
            Bs[lcol+0][r] = vb.x; Bs[lcol+1][r] = vb.y;
            Bs[lcol+2][r] = vb.z; Bs[lcol+3][r] = vb.w;
        }
        __syncthreads();
#pragma unroll
        for (int k = 0; k < 16; k++) {
            float ra[8], rb[8];
#pragma unroll
            for (int m = 0; m < 8; m++) ra[m] = As[k][trow * 8 + m];
#pragma unroll
            for (int n = 0; n < 8; n++) rb[n] = Bs[k][tcol * 8 + n];
#pragma unroll
            for (int m = 0; m < 8; m++)
#pragma unroll
                for (int n = 0; n < 8; n++) acc[m][n] = fmaf(ra[m], rb[n], acc[m][n]);
        }
        __syncthreads();
    }
#pragma unroll
    for (int m = 0; m < 8; m++) {
        int row = blockIdx.y * 128 + trow * 8 + m;
#pragma unroll
        for (int n = 0; n < 8; n++) {
            int col = nbase + tcol * 8 + n;
            if (col < N) {
                float bv = bias ? bias[col] : 0.f;
                C[(size_t)blockIdx.z * sC + (size_t)row * N + col] = acc[m][n] + bv;
            }
        }
    }
}

// ---------------- fused dt softplus + per-chunk inclusive cumsum (warp scan) ----------------
__global__ void cumsum_kernel(const float* __restrict__ dt_bias, const float* __restrict__ A_log)
{
    int c = blockIdx.x, h = blockIdx.y, b = blockIdx.z;
    int t = threadIdx.x, lane = t & 31, wid = t >> 5;
    __shared__ float wsum[8];
    int row = b * SEQLEN + c * CHUNKT + t;
    float v = g_zxbcdt[(size_t)row * DINPROJ + DINNER + CONVDIM + h] + dt_bias[h];
    float dtv = (v > 20.f) ? v : log1pf(__expf(v));
    g_dt[row * NHEADS + h] = dtv;
    float x = -__expf(A_log[h]) * dtv;
#pragma unroll
    for (int off = 1; off < 32; off <<= 1) {
        float y = __shfl_up_sync(0xffffffffu, x, off);
        if (lane >= off) x += y;
    }
    if (lane == 31) wsum[wid] = x;
    __syncthreads();
    if (wid == 0 && lane < 8) {
        float w = wsum[lane];
#pragma unroll
        for (int off = 1; off < 8; off <<= 1) {
            float y = __shfl_up_sync(0xffu, w, off);
            if (lane >= off) w += y;
        }
        wsum[lane] = w;
    }
    __syncthreads();
    float base = (wid > 0) ? wsum[wid - 1] : 0.f;
    g_Acum[(b * NHEADS + h) * SEQLEN + c * CHUNKT + t] = base + x;
}

// ---------------- causal depthwise conv + SiLU (8 outputs/thread) ----------------
__global__ void conv_kernel(const float* __restrict__ w, const float* __restrict__ cb)
{
    long idx = (long)blockIdx.x * blockDim.x + threadIdx.x;
    if (idx >= (long)(NROWS / 8) * CONVDIM) return;
    int c = (int)(idx % CONVDIM);
    int r0 = (int)(idx / CONVDIM) * 8;
    int l0 = r0 & (SEQLEN - 1);
    float v[11];
#pragma unroll
    for (int k = 0; k < 11; k++) {
        int l = l0 - 3 + k;
        v[k] = (l >= 0) ? g_zxbcdt[(size_t)(r0 - 3 + k) * DINPROJ + DINNER + c] : 0.f;
    }
    const float w0 = w[c * 4], w1 = w[c * 4 + 1], w2 = w[c * 4 + 2], w3 = w[c * 4 + 3];
    const float bias = cb[c];
#pragma unroll
    for (int j = 0; j < 8; j++) {
        float acc = bias;
        acc = fmaf(w0, v[j + 0], acc);
        acc = fmaf(w1, v[j + 1], acc);
        acc = fmaf(w2, v[j + 2], acc);
        acc = fmaf(w3, v[j + 3], acc);
        float out = siluf(acc);
        int r = r0 + j;
        if (c < DINNER) {
            float xv = out * g_dt[r * NHEADS + (c >> 7)];
            g_xf16[(size_t)r * DINNER + c] = __float2half_rn(xv);
        } else if (c < DINNER + DSTATE) {
            g_Bv[r * DSTATE + (c - DINNER)] = out;
        } else {
            g_Cv[r * DSTATE + (c - DINNER - DSTATE)] = out;
        }
    }
}

// ---------------- chunk-local states on tensor cores ----------------
__global__ void __launch_bounds__(256) states_mma()
{
    __shared__ __align__(16) char sX[64 * 256];
    __shared__ __align__(16) char sB[64 * 128];
    __shared__ float Ac[CHUNKT];
    const int h = blockIdx.x, c = blockIdx.y, b = blockIdx.z;
    const int tid = threadIdx.x, lane = tid & 31, wid = tid >> 5;
    const int wr = wid >> 1, wc = wid & 1;
    const int brow = b * SEQLEN + c * CHUNKT;
    const uint32_t sbX = smem_u32(sX), sbB = smem_u32(sB);

    Ac[tid] = g_Acum[(b * NHEADS + h) * SEQLEN + c * CHUNKT + tid];
    __syncthreads();
    const float Atot = Ac[CHUNKT - 1];

    float acc[2][4][4];
#pragma unroll
    for (int mt = 0; mt < 2; mt++)
#pragma unroll
        for (int nt = 0; nt < 4; nt++)
#pragma unroll
            for (int i = 0; i < 4; i++) acc[mt][nt][i] = 0.f;

    const int g = lane >> 3, li = lane & 7;
    const int akr = (g >> 1) * 8 + li;
    const int amc = (g & 1) * 8;
    const int bkr = (g & 1) * 8 + li;
    const int bnc = (g >> 1) * 8;

    for (int lt = 0; lt < CHUNKT; lt += 64) {
        if (lt) __syncthreads();
        for (int idx = tid; idx < 64 * 16; idx += 256) {
            int l = idx >> 4, u = idx & 15;
            size_t src = (size_t)(brow + lt + l) * DINNER + h * HEADDIM + u * 8;
            uint32_t dst = l * 256 + ((u ^ (l & 7)) * 16);
            *(uint4*)(sX + dst) = *(const uint4*)(g_xf16 + src);
        }
        for (int idx = tid; idx < 64 * 16; idx += 256) {
            int l = idx >> 4, u4 = idx & 15;
            float4 bv = *(const float4*)&g_Bv[(size_t)(brow + lt + l) * DSTATE + u4 * 4];
            float e = __expf(Atot - Ac[lt + l]);
            uint32_t h01 = rnd2h(bv.x * e, bv.y * e);
            uint32_t h23 = rnd2h(bv.z * e, bv.w * e);
            uint32_t dst = l * 128 + (((u4 >> 1) ^ (l & 7)) * 16) + (u4 & 1) * 8;
            *(uint2*)(sB + dst) = make_uint2(h01, h23);
        }
        __syncthreads();
#pragma unroll
        for (int s = 0; s < 4; s++) {
            uint32_t af[2][4];
#pragma unroll
            for (int mt = 0; mt < 2; mt++) {
                int kr = s * 16 + akr;
                int mc = wr * 32 + mt * 16 + amc;
                uint32_t off = kr * 256 + (((mc >> 3) ^ (kr & 7)) * 16);
                LDSM_X4_T(af[mt][0], af[mt][1], af[mt][2], af[mt][3], sbX + off);
            }
#pragma unroll
            for (int ntp = 0; ntp < 2; ntp++) {
                int kr = s * 16 + bkr;
                int nc = wc * 32 + ntp * 16 + bnc;
                uint32_t off = kr * 128 + (((nc >> 3) ^ (kr & 7)) * 16);
                uint32_t b0, b1, b2, b3;
                LDSM_X4_T(b0, b1, b2, b3, sbB + off);
#pragma unroll
                for (int mt = 0; mt < 2; mt++) {
                    mma16816h(acc[mt][2*ntp+0], af[mt], b0, b1);
                    mma16816h(acc[mt][2*ntp+1], af[mt], b2, b3);
                }
            }
        }
    }

    size_t base = ((size_t)((b * NCHUNK + c) * NHEADS + h)) * HEADDIM * DSTATE;
#pragma unroll
    for (int mt = 0; mt < 2; mt++) {
        int p0 = wr * 32 + mt * 16 + (lane >> 2);
#pragma unroll
        for (int nt = 0; nt < 4; nt++) {
            int n = wc * 32 + nt * 8 + (lane & 3) * 2;
            *(float2*)(g_states + base + (size_t)p0 * DSTATE + n) =
                make_float2(acc[mt][nt][0], acc[mt][nt][1]);
            *(float2*)(g_states + base + (size_t)(p0 + 8) * DSTATE + n) =
                make_float2(acc[mt][nt][2], acc[mt][nt][3]);
        }
    }
}

// ---------------- inter-chunk state scan (16-way split per (b,h)) ----------------
__global__ void scan_kernel()
{
    int bh = blockIdx.x >> 4, seg = blockIdx.x & 15;
    int b = bh >> 5, h = bh & 31;
    int t = threadIdx.x;    // 128 threads
    size_t off = (size_t)seg * 512 + (size_t)t * 4;
    float4 S = make_float4(0.f, 0.f, 0.f, 0.f);
    for (int c = 0; c < NCHUNK; c++) {
        size_t base = ((size_t)((b * NCHUNK + c) * NHEADS + h)) * (HEADDIM * DSTATE) + off;
        *(float4*)(g_prefix + base) = S;
        float f = __expf(g_Acum[(b * NHEADS + h) * SEQLEN + c * CHUNKT + CHUNKT - 1]);
        float4 st = *(const float4*)(g_states + base);
        S.x = S.x * f + st.x;
        S.y = S.y * f + st.y;
        S.z = S.z * f + st.z;
        S.w = S.w * f + st.w;
    }
}

// ================= fused Y on tensor cores (fp16 2-term) =================
// smem: WH 0 (32K) | WL 32768 (32K) | X/S 65536 (16K) | Ac2 81920 | eAc 82944
#define YSMEM 84992
__global__ void __launch_bounds__(512, 1) yfused_mma()
{
    extern __shared__ char ysm[];
    const uint32_t sb = smem_u32(ysm);
    float* Ac2 = (float*)(ysm + 81920);
    float* eAc = (float*)(ysm + 82944);
    const int h = blockIdx.x, c = blockIdx.y, b = blockIdx.z;
    const int tid = threadIdx.x, lane = tid & 31, wid = tid >> 5;
    const int wr = wid >> 2, wc = wid & 3;
    const int brow = b * SEQLEN + c * CHUNKT;
    const size_t gbase = (size_t)(b * NCHUNK + c) * CHUNKT * CHUNKT;
    const size_t sbase = ((size_t)((b * NCHUNK + c) * NHEADS + h)) * (HEADDIM * DSTATE);

    if (tid < CHUNKT) {
        float a = g_Acum[(b * NHEADS + h) * SEQLEN + c * CHUNKT + tid];
        Ac2[tid] = a * LOG2E;
        eAc[tid] = __expf(a);
    }

    float acc[4][4][4];
#pragma unroll
    for (int mt = 0; mt < 4; mt++)
#pragma unroll
        for (int nt = 0; nt < 4; nt++)
#pragma unroll
            for (int i = 0; i < 4; i++) acc[mt][nt][i] = 0.f;

    const int g = lane >> 3, li = lane & 7;
    const int arow  = (g & 1) * 8 + li;
    const int ahalf = g >> 1;
    const int bkt   = (g & 1) * 8 + li;
    const int bnt   = (g >> 1) * 8;
    const int brw2  = (g >> 1) * 8 + li;
    const int bhf2  = g & 1;

    // ---- part 1: W @ X over 4 j-tiles of 64; stage W rows [jt,256) only ----
    for (int jt = 0; jt < CHUNKT; jt += 64) {
        __syncthreads();
        const int nrows = CHUNKT - jt;
        for (int idx = tid; idx < nrows * 16; idx += 512) {
            int i = jt + (idx >> 4), u4 = idx & 15;
            float4 gv = *(const float4*)&g_G[gbase + (size_t)i * 256 + jt + u4 * 4];
            float ai = Ac2[i];
            int j0 = jt + u4 * 4;
            float v0 = (j0 + 0 <= i) ? exp2f(ai - Ac2[j0 + 0]) * gv.x : 0.f;
            float v1 = (j0 + 1 <= i) ? exp2f(ai - Ac2[j0 + 1]) * gv.y : 0.f;
            float v2 = (j0 + 2 <= i) ? exp2f(ai - Ac2[j0 + 2]) * gv.z : 0.f;
            float v3 = (j0 + 3 <= i) ? exp2f(ai - Ac2[j0 + 3]) * gv.w : 0.f;
            uint32_t lo01, lo23;
            uint32_t hi01 = pack2h(v0, v1, lo01);
            uint32_t hi23 = pack2h(v2, v3, lo23);
            uint32_t base = i * 128 + (((u4 >> 1) ^ (i & 7)) * 16) + (u4 & 1) * 8;
            *(uint2*)(ysm + base)         = make_uint2(hi01, hi23);
            *(uint2*)(ysm + 32768 + base) = make_uint2(lo01, lo23);
        }
        for (int idx = tid; idx < 64 * 16; idx += 512) {
            int l = idx >> 4, u = idx & 15;
            size_t src = (size_t)(brow + jt + l) * DINNER + h * HEADDIM + u * 8;
            uint32_t dst = l * 256 + ((u ^ (l & 7)) * 16);
            *(uint4*)(ysm + 65536 + dst) = *(const uint4*)(g_xf16 + src);
        }
        __syncthreads();
        if (wr * 64 + 63 >= jt) {
#pragma unroll
            for (int s = 0; s < 4; s++) {
                uint32_t afh[4][4], afl[4][4];
#pragma unroll
                for (int mt = 0; mt < 4; mt++) {
                    int row = wr * 64 + mt * 16 + arow;
                    uint32_t off = row * 128 + (((2 * s + ahalf) ^ (row & 7)) * 16);
                    LDSM_X4(afh[mt][0], afh[mt][1], afh[mt][2], afh[mt][3], sb + off);
                    LDSM_X4(afl[mt][0], afl[mt][1], afl[mt][2], afl[mt][3], sb + 32768 + off);
                }
#pragma unroll
                for (int ntp = 0; ntp < 2; ntp++) {
                    int krow = s * 16 + bkt;
                    int p = wc * 32 + ntp * 16 + bnt;
                    uint32_t off = krow * 256 + (((p >> 3) ^ (krow & 7)) * 16);
                    uint32_t b0, b1, b2, b3;
                    LDSM_X4_T(b0, b1, b2, b3, sb + 65536 + off);
#pragma unroll
                    for (int mt = 0; mt < 4; mt++) {
                        mma16816h(acc[mt][2*ntp+0], afh[mt], b0, b1);
                        mma16816h(acc[mt][2*ntp+0], afl[mt], b0, b1);
                        mma16816h(acc[mt][2*ntp+1], afh[mt], b2, b3);
                        mma16816h(acc[mt][2*ntp+1], afl[mt], b2, b3);
                    }
                }
            }
        }
    }

    // ---- part 2: Ce @ S^T (K = 64) ----
    __syncthreads();
    for (int idx = tid; idx < 256 * 16; idx += 512) {
        int i = idx >> 4, u4 = idx & 15;
        float4 cv = *(const float4*)&g_Cv[(size_t)(brow + i) * 64 + u4 * 4];
        float e = eAc[i];
        uint32_t lo01, lo23;
        uint32_t hi01 = pack2h(cv.x * e, cv.y * e, lo01);
        uint32_t hi23 = pack2h(cv.z * e, cv.w * e, lo23);
        uint32_t base = i * 128 + (((u4 >> 1) ^ (i & 7)) * 16) + (u4 & 1) * 8;
        *(uint2*)(ysm + base)         = make_uint2(hi01, hi23);
        *(uint2*)(ysm + 32768 + base) = make_uint2(lo01, lo23);
    }
    for (int idx = tid; idx < 128 * 16; idx += 512) {
        int p = idx >> 4, u4 = idx & 15;
        float4 sv = *(const float4*)&g_prefix[sbase + (size_t)p * 64 + u4 * 4];
        uint32_t h01 = rnd2h(sv.x, sv.y);
        uint32_t h23 = rnd2h(sv.z, sv.w);
        uint32_t base = p * 128 + (((u4 >> 1) ^ (p & 7)) * 16) + (u4 & 1) * 8;
        *(uint2*)(ysm + 65536 + base) = make_uint2(h01, h23);
    }
    __syncthreads();
#pragma unroll
    for (int s = 0; s < 4; s++) {
        uint32_t afh[4][4], afl[4][4];
#pragma unroll
        for (int mt = 0; mt < 4; mt++) {
            int row = wr * 64 + mt * 16 + arow;
            uint32_t off = row * 128 + (((2 * s + ahalf) ^ (row & 7)) * 16);
            LDSM_X4(afh[mt][0], afh[mt][1], afh[mt][2], afh[mt][3], sb + off);
            LDSM_X4(afl[mt][0], afl[mt][1], afl[mt][2], afl[mt][3], sb + 32768 + off);
        }
#pragma unroll
        for (int ntp = 0; ntp < 2; ntp++) {
            int row = wc * 32 + ntp * 16 + brw2;
            uint32_t off = row * 128 + (((2 * s + bhf2) ^ (row & 7)) * 16);
            uint32_t b0, b1, b2, b3;
            LDSM_X4(b0, b1, b2, b3, sb + 65536 + off);
#pragma unroll
            for (int mt = 0; mt < 4; mt++) {
                mma16816h(acc[mt][2*ntp+0], afh[mt], b0, b1);
                mma16816h(acc[mt][2*ntp+0], afl[mt], b0, b1);
                mma16816h(acc[mt][2*ntp+1], afh[mt], b2, b3);
                mma16816h(acc[mt][2*ntp+1], afl[mt], b2, b3);
            }
        }
    }

    // ---- epilogue ----
#pragma unroll
    for (int mt = 0; mt < 4; mt++) {
        int i0 = wr * 64 + mt * 16 + (lane >> 2);
#pragma unroll
        for (int nt = 0; nt < 4; nt++) {
            int col = h * HEADDIM + wc * 32 + nt * 8 + (lane & 3) * 2;
            *(float2*)(g_y + (size_t)(brow + i0) * DINNER + col) =
                make_float2(acc[mt][nt][0], acc[mt][nt][1]);
            *(float2*)(g_y + (size_t)(brow + i0 + 8) * DINNER + col) =
                make_float2(acc[mt][nt][2], acc[mt][nt][3]);
        }
    }
}

// ---------------- gating (y * silu(z)) + LayerNorm; emits single fp16 ----------------
__global__ void __launch_bounds__(256) ln_kernel(const float* __restrict__ lnw, const float* __restrict__ lnb)
{
    int row = blockIdx.x;
    int tid = threadIdx.x;
    float gv[4][4];
    float s = 0.f, s2 = 0.f;
#pragma unroll
    for (int q = 0; q < 4; q++) {
        int i = (tid + q * 256) * 4;
        float4 yv = *(const float4*)&g_y[(size_t)row * DINNER + i];
        float4 zv = *(const float4*)&g_zxbcdt[(size_t)row * DINPROJ + i];
        float v0 = yv.x * siluf(zv.x);
        float v1 = yv.y * siluf(zv.y);
        float v2 = yv.z * siluf(zv.z);
        float v3 = yv.w * siluf(zv.w);
        gv[q][0] = v0; gv[q][1] = v1; gv[q][2] = v2; gv[q][3] = v3;
        s += v0 + v1 + v2 + v3;
        s2 = fmaf(v0, v0, s2); s2 = fmaf(v1, v1, s2);
        s2 = fmaf(v2, v2, s2); s2 = fmaf(v3, v3, s2);
    }
    __shared__ float red[2][8];
#pragma unroll
    for (int off = 16; off > 0; off >>= 1) {
        s  += __shfl_xor_sync(0xffffffffu, s, off);
        s2 += __shfl_xor_sync(0xffffffffu, s2, off);
    }
    if ((tid & 31) == 0) { red[0][tid >> 5] = s; red[1][tid >> 5] = s2; }
    __syncthreads();
    if (tid == 0) {
        float a = 0.f, a2 = 0.f;
#pragma unroll
        for (int w = 0; w < 8; w++) { a += red[0][w]; a2 += red[1][w]; }
        red[0][0] = a; red[1][0] = a2;
    }
    __syncthreads();
    float mu  = red[0][0] * (1.f / DINNER);
    float var = red[1][0] * (1.f / DINNER) - mu * mu;
    float rstd = rsqrtf(var + LN_EPS);
#pragma unroll
    for (int q = 0; q < 4; q++) {
        int i = (tid + q * 256) * 4;
        float4 wv = *(const float4*)&lnw[i];
        float4 bv = *(const float4*)&lnb[i];
        float o0 = (gv[q][0] - mu) * rstd * wv.x + bv.x;
        float o1 = (gv[q][1] - mu) * rstd * wv.y + bv.y;
        float o2 = (gv[q][2] - mu) * rstd * wv.z + bv.z;
        float o3 = (gv[q][3] - mu) * rstd * wv.w + bv.w;
        *(uint2*)&g_ynh[(size_t)row * DINNER + i] = make_uint2(rnd2h(o0, o1), rnd2h(o2, o3));
    }
}

// ---------------- launch ----------------
extern "C" void kernel_launch(void* const* d_in, const int* in_sizes, int n_in,
                              void* d_out, int out_size)
{
    const float* u          = (const float*)d_in[0];
    const float* in_proj_w  = (const float*)d_in[1];
    const float* in_proj_b  = (const float*)d_in[2];
    const float* conv_w     = (const float*)d_in[3];
    const float* conv_b     = (const float*)d_in[4];
    const float* dt_bias    = (const float*)d_in[5];
    const float* A_log      = (const float*)d_in[6];
    const float* ln_w       = (const float*)d_in[7];
    const float* ln_b       = (const float*)d_in[8];
    const float* out_proj_w = (const float*)d_in[9];
    const float* out_proj_b = (const float*)d_in[10];
    float* out = (float*)d_out;

    float *zx, *gB, *gC, *gG;
    __half *uh, *ul, *w1h, *ynh, *w2h;
    cudaGetSymbolAddress((void**)&zx,  g_zxbcdt);
    cudaGetSymbolAddress((void**)&gB,  g_Bv);
    cudaGetSymbolAddress((void**)&gC,  g_Cv);
    cudaGetSymbolAddress((void**)&gG,  g_G);
    cudaGetSymbolAddress((void**)&uh,  g_uh);
    cudaGetSymbolAddress((void**)&ul,  g_ul);
    cudaGetSymbolAddress((void**)&w1h, g_w1h);
    cudaGetSymbolAddress((void**)&ynh, g_ynh);
    cudaGetSymbolAddress((void**)&w2h, g_w2h);

    cudaFuncSetAttribute(mma_gemm_nt,  cudaFuncAttributeMaxDynamicSharedMemorySize, 3 * GST);
    cudaFuncSetAttribute(mma_gemm_nt1, cudaFuncAttributeMaxDynamicSharedMemorySize, 3 * GST1);
    cudaFuncSetAttribute(yfused_mma,   cudaFuncAttributeMaxDynamicSharedMemorySize, YSMEM);

    // 0) fp32 -> fp16 conversions (vectorized; both weights in one launch)
    {
        long n1 = (long)NROWS * DMODEL / 4;
        split_f16<<<(unsigned)((n1 + 255) / 256), 256>>>(u, uh, ul, n1);
        long n2 = (long)DINPROJ * DMODEL / 4;
        long n3 = (long)DMODEL * DINNER / 4;
        round2_f16<<<(unsigned)((n2 + n3 + 255) / 256), 256>>>(
            in_proj_w, w1h, n2, out_proj_w, w2h, n3);
    }

    // 1) in_proj: M=8192, N=8352, K=2048 (2-term)
    mma_gemm_nt<<<dim3((DINPROJ + 255) / 256, NROWS / 128), 512, 3 * GST>>>(
        uh, ul, w1h, in_proj_b, zx, DINPROJ, DMODEL);

    // 2) fused dt softplus + per-chunk cumsum (warp scan)
    cumsum_kernel<<<dim3(NCHUNK, NHEADS, BATCH), CHUNKT>>>(dt_bias, A_log);

    // 3) causal conv + silu (8 outputs/thread)
    {
        long total = (long)(NROWS / 8) * CONVDIM;
        conv_kernel<<<(unsigned)((total + 255) / 256), 256>>>(conv_w, conv_b);
    }

    // 4) G = C @ B^T per (b,chunk)  (upper-right block skipped inside)
    sgemm_nt<<<dim3(2, 2, BATCH * NCHUNK), 256>>>(
        gC, gB, nullptr, gG, CHUNKT, DSTATE,
        (long)CHUNKT * DSTATE, (long)CHUNKT * DSTATE, (long)CHUNKT * CHUNKT);

    // 5) chunk-local states on tensor cores
    states_mma<<<dim3(NHEADS, NCHUNK, BATCH), 256>>>();

    // 6) inter-chunk scan (16-way split)
    scan_kernel<<<BATCH * NHEADS * 16, 128>>>();

    // 7) fused Y on tensor cores
    yfused_mma<<<dim3(NHEADS, NCHUNK, BATCH), 512, YSMEM>>>();

    // 8) gate + layernorm (single fp16 yn)
    ln_kernel<<<NROWS, 256>>>(ln_w, ln_b);

    // 9) out_proj: M=8192, N=2048, K=4096 (1-term)
    mma_gemm_nt1<<<dim3(DMODEL / 256, NROWS / 128), 512, 3 * GST1>>>(
        ynh, w2h, out_proj_b, out, DMODEL, DINNER);
}

// round 16
// speedup vs baseline: 1.7630x; 1.3033x over previous
#include <cuda_runtime.h>
#include <cuda_bf16.h>
#include <cuda_fp16.h>
#include <cstdint>
#include <math.h>

#define BATCH   2
#define SEQLEN  4096
#define DMODEL  2048
#define DINNER  4096
#define NHEADS  32
#define HEADDIM 128
#define DSTATE  64
#define NCHUNK  16
#define CHUNKT  256
#define CONVDIM 4224
#define DINPROJ 8352
#define NROWS   (BATCH*SEQLEN)
#define LN_EPS  1e-5f
#define LOG2E   1.4426950408889634f

// ---------------- scratch (device globals; no allocations allowed) ----------------
__device__ float g_zxbcdt[(size_t)NROWS * DINPROJ];
__device__ float g_Bv   [NROWS * DSTATE];
__device__ float g_Cv   [NROWS * DSTATE];
__device__ float g_dt   [NROWS * NHEADS];
__device__ float g_Acum [BATCH * NHEADS * SEQLEN];
__device__ float g_G    [(size_t)BATCH * NCHUNK * CHUNKT * CHUNKT];
__device__ float g_states[(size_t)BATCH * NCHUNK * NHEADS * HEADDIM * DSTATE];
__device__ float g_prefix[(size_t)BATCH * NCHUNK * NHEADS * HEADDIM * DSTATE];
__device__ float g_y    [(size_t)NROWS * DINNER];

// fp16 buffers (all single-rounded)
__device__ __half g_uh [(size_t)NROWS * DMODEL];
__device__ __half g_w1h[(size_t)DINPROJ * DMODEL];
__device__ __half g_ynh[(size_t)NROWS * DINNER];
__device__ __half g_w2h[(size_t)DMODEL * DINNER];
__device__ __half g_xf16[(size_t)NROWS * DINNER];   // rounded fp16 of xdt

__device__ __forceinline__ float siluf(float x) { return x / (1.f + __expf(-x)); }

__device__ __forceinline__ uint32_t smem_u32(const void* p) {
    uint32_t a;
    asm("{ .reg .u64 t; cvta.to.shared.u64 t, %1; cvt.u32.u64 %0, t; }" : "=r"(a) : "l"(p));
    return a;
}

// pack two floats into fp16x2 hi; return hi, write lo (exact 2-term split, packed cvt)
__device__ __forceinline__ uint32_t pack2h(float a, float b, uint32_t& lo) {
    __half2 h = __floats2half2_rn(a, b);
    float2 hf = __half22float2(h);
    __half2 l = __floats2half2_rn(a - hf.x, b - hf.y);
    lo = *reinterpret_cast<uint32_t*>(&l);
    return *reinterpret_cast<uint32_t*>(&h);
}
__device__ __forceinline__ uint32_t rnd2h(float a, float b) {
    __half2 h = __floats2half2_rn(a, b);
    return *reinterpret_cast<uint32_t*>(&h);
}

// ================= conversion kernel: three tensors rounded in one launch =================
__global__ void round3_f16(const float* __restrict__ a, __half* __restrict__ da, long na4,
                           const float* __restrict__ b, __half* __restrict__ db, long nb4,
                           const float* __restrict__ c, __half* __restrict__ dc, long nc4)
{
    long i = (long)blockIdx.x * blockDim.x + threadIdx.x;
    if (i < na4) {
        float4 x = ((const float4*)a)[i];
        ((uint2*)da)[i] = make_uint2(rnd2h(x.x, x.y), rnd2h(x.z, x.w));
    } else if (i < na4 + nb4) {
        long j = i - na4;
        float4 x = ((const float4*)b)[j];
        ((uint2*)db)[j] = make_uint2(rnd2h(x.x, x.y), rnd2h(x.z, x.w));
    } else if (i < na4 + nb4 + nc4) {
        long j = i - na4 - nb4;
        float4 x = ((const float4*)c)[j];
        ((uint2*)dc)[j] = make_uint2(rnd2h(x.x, x.y), rnd2h(x.z, x.w));
    }
}

// ================= tensor-core primitives =================
__device__ __forceinline__ void mma16816h(float* c, const uint32_t* a, uint32_t b0, uint32_t b1)
{
    asm volatile(
        "mma.sync.aligned.m16n8k16.row.col.f32.f16.f16.f32 "
        "{%0,%1,%2,%3}, {%4,%5,%6,%7}, {%8,%9}, {%0,%1,%2,%3};"
        : "+f"(c[0]), "+f"(c[1]), "+f"(c[2]), "+f"(c[3])
        : "r"(a[0]), "r"(a[1]), "r"(a[2]), "r"(a[3]), "r"(b0), "r"(b1));
}
#define LDSM_X4(r0, r1, r2, r3, addr) \
    asm volatile("ldmatrix.sync.aligned.m8n8.x4.shared.b16 {%0,%1,%2,%3}, [%4];" \
                 : "=r"(r0), "=r"(r1), "=r"(r2), "=r"(r3) : "r"(addr))
#define LDSM_X4_T(r0, r1, r2, r3, addr) \
    asm volatile("ldmatrix.sync.aligned.m8n8.x4.trans.shared.b16 {%0,%1,%2,%3}, [%4];" \
                 : "=r"(r0), "=r"(r1), "=r"(r2), "=r"(r3) : "r"(addr))
#define CP16(dst, src, sz) \
    asm volatile("cp.async.cg.shared.global [%0], [%1], 16, %2;" \
                 :: "r"(dst), "l"(src), "r"(sz))
#define CP_COMMIT() asm volatile("cp.async.commit_group;" ::: "memory")
#define CP_WAIT1()  asm volatile("cp.async.wait_group 1;" ::: "memory")
#define CP_WAIT0()  asm volatile("cp.async.wait_group 0;" ::: "memory")

// ================= fp16 1-MMA GEMM: C = Ah*Bh^T + bias =================
// BM=128, BN=256, BK=64, 512 threads (16 warps, 32x64 warp tiles).
// 3-stage cp.async pipeline, 48KB/stage.
#define GST1 49152
__global__ void __launch_bounds__(512, 1)
mma_gemm_nt1(const __half* __restrict__ Ah, const __half* __restrict__ Bh,
             const float* __restrict__ bias, float* __restrict__ C, int N, int K)
{
    extern __shared__ char smem[];
    const uint32_t sb = smem_u32(smem);
    const int tid = threadIdx.x, lane = tid & 31, wid = tid >> 5;
    const int wr = wid >> 2, wc = wid & 3;
    const int mbase = blockIdx.y * 128;
    const int nbase = blockIdx.x * 256;

    const int ra = tid >> 2, ua0 = (tid & 3) * 2;
    const int rb = tid >> 1, ub0 = (tid & 1) * 4;
    const bool bval = (nbase + rb) < N;
    const uint32_t bsz = bval ? 16u : 0u;
    const __half* gAh = Ah + (size_t)(mbase + ra) * K + ua0 * 8;
    const __half* gBh = Bh + (size_t)(bval ? nbase + rb : 0) * K + ub0 * 8;
    const uint32_t dA0 = ra * 128 + (( ua0      ^ (ra & 7)) * 16);
    const uint32_t dA1 = ra * 128 + (((ua0 + 1) ^ (ra & 7)) * 16);
    uint32_t dB[4];
#pragma unroll
    for (int j = 0; j < 4; j++) dB[j] = rb * 128 + (((ub0 + j) ^ (rb & 7)) * 16);

    auto issue = [&](int st, int kt) {
        uint32_t s0 = sb + st * GST1;
        CP16(s0 + dA0, gAh + kt,     16);
        CP16(s0 + dA1, gAh + kt + 8, 16);
#pragma unroll
        for (int j = 0; j < 4; j++)
            CP16(s0 + 16384 + dB[j], gBh + kt + j * 8, bsz);
        CP_COMMIT();
    };

    float acc[2][8][4];
#pragma unroll
    for (int mt = 0; mt < 2; mt++)
#pragma unroll
        for (int nt = 0; nt < 8; nt++)
#pragma unroll
            for (int i = 0; i < 4; i++) acc[mt][nt][i] = 0.f;

    const int nk = K >> 6;
    issue(0, 0);
    issue(1, 64);

    const int g = lane >> 3, li = lane & 7;
    const int arow_lo = (g & 1) * 8 + li;
    const int ahalf   = g >> 1;
    const int brow_lo = (g >> 1) * 8 + li;
    const int bhalf   = g & 1;

    int stage = 0;
    for (int c = 0; c < nk; c++) {
        if (c + 1 < nk) CP_WAIT1(); else CP_WAIT0();
        __syncthreads();
        if (c + 2 < nk) {
            int st = stage + 2; if (st >= 3) st -= 3;
            issue(st, (c + 2) * 64);
        }
        const uint32_t s0 = sb + stage * GST1;
#pragma unroll
        for (int s = 0; s < 4; s++) {
            uint32_t af[2][4];
#pragma unroll
            for (int mt = 0; mt < 2; mt++) {
                int row = wr * 32 + mt * 16 + arow_lo;
                uint32_t off = row * 128 + (((2 * s + ahalf) ^ (row & 7)) * 16);
                LDSM_X4(af[mt][0], af[mt][1], af[mt][2], af[mt][3], s0 + off);
            }
#pragma unroll
            for (int ntp = 0; ntp < 4; ntp++) {
                int row = wc * 64 + ntp * 16 + brow_lo;
                uint32_t off = row * 128 + (((2 * s + bhalf) ^ (row & 7)) * 16);
                uint32_t b0, b1, b2, b3;
                LDSM_X4(b0, b1, b2, b3, s0 + 16384 + off);
#pragma unroll
                for (int mt = 0; mt < 2; mt++) {
                    mma16816h(acc[mt][2*ntp+0], af[mt], b0, b1);
                    mma16816h(acc[mt][2*ntp+1], af[mt], b2, b3);
                }
            }
        }
        stage++; if (stage >= 3) stage -= 3;
    }

#pragma unroll
    for (int mt = 0; mt < 2; mt++) {
        int r0 = mbase + wr * 32 + mt * 16 + (lane >> 2);
#pragma unroll
        for (int nt = 0; nt < 8; nt++) {
            int col = nbase + wc * 64 + nt * 8 + (lane & 3) * 2;
            if (col < N) {
                float b0 = bias ? bias[col] : 0.f;
                float b1 = bias ? bias[col + 1] : 0.f;
                float2 v0 = make_float2(acc[mt][nt][0] + b0, acc[mt][nt][1] + b1);
                float2 v1 = make_float2(acc[mt][nt][2] + b0, acc[mt][nt][3] + b1);
                *(float2*)(C + (size_t)r0 * N + col)       = v0;
                *(float2*)(C + (size_t)(r0 + 8) * N + col) = v1;
            }
        }
    }
}

// ---------------- small fp32 NT GEMM (G = C @ B^T); skips strictly-upper block ----------------
__global__ void __launch_bounds__(256)
sgemm_nt(const float* __restrict__ A, const float* __restrict__ B,
         const float* __restrict__ bias, float* __restrict__ C,
         int N, int K, long sA, long sB, long sC)
{
    if (blockIdx.x * 128 > blockIdx.y * 128 + 127) return;

    __shared__ float As[16][128];
    __shared__ float Bs[16][128];
    const int tid  = threadIdx.x;
    const int tcol = tid & 15;
    const int trow = tid >> 4;
    const float* Ab = A + (size_t)blockIdx.z * sA + (size_t)blockIdx.y * 128 * K;
    const float* Bb = B + (size_t)blockIdx.z * sB + (size_t)blockIdx.x * 128 * K;
    const int nbase = blockIdx.x * 128;

    float acc[8][8];
#pragma unroll
    for (int m = 0; m < 8; m++)
#pragma unroll
        for (int n = 0; n < 8; n++) acc[m][n] = 0.f;

    const int lrow = tid >> 2;
    const int lcol = (tid & 3) * 4;

    for (int kt = 0; kt < K; kt += 16) {
#pragma unroll
        for (int it = 0; it < 2; it++) {
            int r = lrow + it * 64;
            float4 va = *(const float4*)(Ab + (size_t)r * K + kt + lcol);
            As[lcol+0][r] = va.x; As[lcol+1][r] = va.y;
            As[lcol+2][r] = va.z; As[lcol+3][r] = va.w;
            float4 vb;
            if (nbase + r < N) vb = *(const float4*)(Bb + (size_t)r * K + kt + lcol);
            else               vb = make_float4(0.f, 0.f, 0.f, 0.f);
            Bs[lcol+0][r] = vb.x; Bs[lcol+1][r] = vb.y;
            Bs[lcol+2][r] = vb.z; Bs[lcol+3][r] = vb.w;
        }
        __syncthreads();
#pragma unroll
        for (int k = 0; k < 16; k++) {
            float ra[8], rb[8];
#pragma unroll
            for (int m = 0; m < 8; m++) ra[m] = As[k][trow * 8 + m];
#pragma unroll
            for (int n = 0; n < 8; n++) rb[n] = Bs[k][tcol * 8 + n];
#pragma unroll
            for (int m = 0; m < 8; m++)
#pragma unroll
                for (int n = 0; n < 8; n++) acc[m][n] = fmaf(ra[m], rb[n], acc[m][n]);
        }
        __syncthreads();
    }
#pragma unroll
    for (int m = 0; m < 8; m++) {
        int row = blockIdx.y * 128 + trow * 8 + m;
#pragma unroll
        for (int n = 0; n < 8; n++) {
            int col = nbase + tcol * 8 + n;
            if (col < N) {
                float bv = bias ? bias[col] : 0.f;
                C[(size_t)blockIdx.z * sC + (size_t)row * N + col] = acc[m][n] + bv;
            }
        }
    }
}

// ---------------- fused dt softplus + per-chunk inclusive cumsum (warp scan) ----------------
__global__ void cumsum_kernel(const float* __restrict__ dt_bias, const float* __restrict__ A_log)
{
    int c = blockIdx.x, h = blockIdx.y, b = blockIdx.z;
    int t = threadIdx.x, lane = t & 31, wid = t >> 5;
    __shared__ float wsum[8];
    int row = b * SEQLEN + c * CHUNKT + t;
    float v = g_zxbcdt[(size_t)row * DINPROJ + DINNER + CONVDIM + h] + dt_bias[h];
    float dtv = (v > 20.f) ? v : log1pf(__expf(v));
    g_dt[row * NHEADS + h] = dtv;
    float x = -__expf(A_log[h]) * dtv;
#pragma unroll
    for (int off = 1; off < 32; off <<= 1) {
        float y = __shfl_up_sync(0xffffffffu, x, off);
        if (lane >= off) x += y;
    }
    if (lane == 31) wsum[wid] = x;
    __syncthreads();
    if (wid == 0 && lane < 8) {
        float w = wsum[lane];
#pragma unroll
        for (int off = 1; off < 8; off <<= 1) {
            float y = __shfl_up_sync(0xffu, w, off);
            if (lane >= off) w += y;
        }
        wsum[lane] = w;
    }
    __syncthreads();
    float base = (wid > 0) ? wsum[wid - 1] : 0.f;
    g_Acum[(b * NHEADS + h) * SEQLEN + c * CHUNKT + t] = base + x;
}

// ---------------- causal depthwise conv + SiLU (8 outputs/thread) ----------------
__global__ void conv_kernel(const float* __restrict__ w, const float* __restrict__ cb)
{
    long idx = (long)blockIdx.x * blockDim.x + threadIdx.x;
    if (idx >= (long)(NROWS / 8) * CONVDIM) return;
    int c = (int)(idx % CONVDIM);
    int r0 = (int)(idx / CONVDIM) * 8;
    int l0 = r0 & (SEQLEN - 1);
    float v[11];
#pragma unroll
    for (int k = 0; k < 11; k++) {
        int l = l0 - 3 + k;
        v[k] = (l >= 0) ? g_zxbcdt[(size_t)(r0 - 3 + k) * DINPROJ + DINNER + c] : 0.f;
    }
    const float w0 = w[c * 4], w1 = w[c * 4 + 1], w2 = w[c * 4 + 2], w3 = w[c * 4 + 3];
    const float bias = cb[c];
#pragma unroll
    for (int j = 0; j < 8; j++) {
        float acc = bias;
        acc = fmaf(w0, v[j + 0], acc);
        acc = fmaf(w1, v[j + 1], acc);
        acc = fmaf(w2, v[j + 2], acc);
        acc = fmaf(w3, v[j + 3], acc);
        float out = siluf(acc);
        int r = r0 + j;
        if (c < DINNER) {
            float xv = out * g_dt[r * NHEADS + (c >> 7)];
            g_xf16[(size_t)r * DINNER + c] = __float2half_rn(xv);
        } else if (c < DINNER + DSTATE) {
            g_Bv[r * DSTATE + (c - DINNER)] = out;
        } else {
            g_Cv[r * DSTATE + (c - DINNER - DSTATE)] = out;
        }
    }
}

// ---------------- chunk-local states on tensor cores ----------------
__global__ void __launch_bounds__(256) states_mma()
{
    __shared__ __align__(16) char sX[64 * 256];
    __shared__ __align__(16) char sB[64 * 128];
    __shared__ float Ac[CHUNKT];
    const int h = blockIdx.x, c = blockIdx.y, b = blockIdx.z;
    const int tid = threadIdx.x, lane = tid & 31, wid = tid >> 5;
    const int wr = wid >> 1, wc = wid & 1;
    const int brow = b * SEQLEN + c * CHUNKT;
    const uint32_t sbX = smem_u32(sX), sbB = smem_u32(sB);

    Ac[tid] = g_Acum[(b * NHEADS + h) * SEQLEN + c * CHUNKT + tid];
    __syncthreads();
    const float Atot = Ac[CHUNKT - 1];

    float acc[2][4][4];
#pragma unroll
    for (int mt = 0; mt < 2; mt++)
#pragma unroll
        for (int nt = 0; nt < 4; nt++)
#pragma unroll
            for (int i = 0; i < 4; i++) acc[mt][nt][i] = 0.f;

    const int g = lane >> 3, li = lane & 7;
    const int akr = (g >> 1) * 8 + li;
    const int amc = (g & 1) * 8;
    const int bkr = (g & 1) * 8 + li;
    const int bnc = (g >> 1) * 8;

    for (int lt = 0; lt < CHUNKT; lt += 64) {
        if (lt) __syncthreads();
        for (int idx = tid; idx < 64 * 16; idx += 256) {
            int l = idx >> 4, u = idx & 15;
            size_t src = (size_t)(brow + lt + l) * DINNER + h * HEADDIM + u * 8;
            uint32_t dst = l * 256 + ((u ^ (l & 7)) * 16);
            *(uint4*)(sX + dst) = *(const uint4*)(g_xf16 + src);
        }
        for (int idx = tid; idx < 64 * 16; idx += 256) {
            int l = idx >> 4, u4 = idx & 15;
            float4 bv = *(const float4*)&g_Bv[(size_t)(brow + lt + l) * DSTATE + u4 * 4];
            float e = __expf(Atot - Ac[lt + l]);
            uint32_t h01 = rnd2h(bv.x * e, bv.y * e);
            uint32_t h23 = rnd2h(bv.z * e, bv.w * e);
            uint32_t dst = l * 128 + (((u4 >> 1) ^ (l & 7)) * 16) + (u4 & 1) * 8;
            *(uint2*)(sB + dst) = make_uint2(h01, h23);
        }
        __syncthreads();
#pragma unroll
        for (int s = 0; s < 4; s++) {
            uint32_t af[2][4];
#pragma unroll
            for (int mt = 0; mt < 2; mt++) {
                int kr = s * 16 + akr;
                int mc = wr * 32 + mt * 16 + amc;
                uint32_t off = kr * 256 + (((mc >> 3) ^ (kr & 7)) * 16);
                LDSM_X4_T(af[mt][0], af[mt][1], af[mt][2], af[mt][3], sbX + off);
            }
#pragma unroll
            for (int ntp = 0; ntp < 2; ntp++) {
                int kr = s * 16 + bkr;
                int nc = wc * 32 + ntp * 16 + bnc;
                uint32_t off = kr * 128 + (((nc >> 3) ^ (kr & 7)) * 16);
                uint32_t b0, b1, b2, b3;
                LDSM_X4_T(b0, b1, b2, b3, sbB + off);
#pragma unroll
                for (int mt = 0; mt < 2; mt++) {
                    mma16816h(acc[mt][2*ntp+0], af[mt], b0, b1);
                    mma16816h(acc[mt][2*ntp+1], af[mt], b2, b3);
                }
            }
        }
    }

    size_t base = ((size_t)((b * NCHUNK + c) * NHEADS + h)) * HEADDIM * DSTATE;
#pragma unroll
    for (int mt = 0; mt < 2; mt++) {
        int p0 = wr * 32 + mt * 16 + (lane >> 2);
#pragma unroll
        for (int nt = 0; nt < 4; nt++) {
            int n = wc * 32 + nt * 8 + (lane & 3) * 2;
            *(float2*)(g_states + base + (size_t)p0 * DSTATE + n) =
                make_float2(acc[mt][nt][0], acc[mt][nt][1]);
            *(float2*)(g_states + base + (size_t)(p0 + 8) * DSTATE + n) =
                make_float2(acc[mt][nt][2], acc[mt][nt][3]);
        }
    }
}

// ---------------- inter-chunk state scan (16-way split per (b,h)) ----------------
__global__ void scan_kernel()
{
    int bh = blockIdx.x >> 4, seg = blockIdx.x & 15;
    int b = bh >> 5, h = bh & 31;
    int t = threadIdx.x;    // 128 threads
    size_t off = (size_t)seg * 512 + (size_t)t * 4;
    float4 S = make_float4(0.f, 0.f, 0.f, 0.f);
    for (int c = 0; c < NCHUNK; c++) {
        size_t base = ((size_t)((b * NCHUNK + c) * NHEADS + h)) * (HEADDIM * DSTATE) + off;
        *(float4*)(g_prefix + base) = S;
        float f = __expf(g_Acum[(b * NHEADS + h) * SEQLEN + c * CHUNKT + CHUNKT - 1]);
        float4 st = *(const float4*)(g_states + base);
        S.x = S.x * f + st.x;
        S.y = S.y * f + st.y;
        S.z = S.z * f + st.z;
        S.w = S.w * f + st.w;
    }
}

// ================= fused Y on tensor cores (fp16 2-term) =================
// smem: WH 0 (32K) | WL 32768 (32K) | X/S 65536 (16K) | Ac2 81920 | eAc 82944
#define YSMEM 84992
__global__ void __launch_bounds__(512, 1) yfused_mma()
{
    extern __shared__ char ysm[];
    const uint32_t sb = smem_u32(ysm);
    float* Ac2 = (float*)(ysm + 81920);
    float* eAc = (float*)(ysm + 82944);
    const int h = blockIdx.x, c = blockIdx.y, b = blockIdx.z;
    const int tid = threadIdx.x, lane = tid & 31, wid = tid >> 5;
    const int wr = wid >> 2, wc = wid & 3;
    const int brow = b * SEQLEN + c * CHUNKT;
    const size_t gbase = (size_t)(b * NCHUNK + c) * CHUNKT * CHUNKT;
    const size_t sbase = ((size_t)((b * NCHUNK + c) * NHEADS + h)) * (HEADDIM * DSTATE);

    if (tid < CHUNKT) {
        float a = g_Acum[(b * NHEADS + h) * SEQLEN + c * CHUNKT + tid];
        Ac2[tid] = a * LOG2E;
        eAc[tid] = __expf(a);
    }

    float acc[4][4][4];
#pragma unroll
    for (int mt = 0; mt < 4; mt++)
#pragma unroll
        for (int nt = 0; nt < 4; nt++)
#pragma unroll
            for (int i = 0; i < 4; i++) acc[mt][nt][i] = 0.f;

    const int g = lane >> 3, li = lane & 7;
    const int arow  = (g & 1) * 8 + li;
    const int ahalf = g >> 1;
    const int bkt   = (g & 1) * 8 + li;
    const int bnt   = (g >> 1) * 8;
    const int brw2  = (g >> 1) * 8 + li;
    const int bhf2  = g & 1;

    // ---- part 1: W @ X over 4 j-tiles of 64; stage W rows [jt,256) only ----
    for (int jt = 0; jt < CHUNKT; jt += 64) {
        __syncthreads();
        const int nrows = CHUNKT - jt;
        for (int idx = tid; idx < nrows * 16; idx += 512) {
            int i = jt + (idx >> 4), u4 = idx & 15;
            float4 gv = *(const float4*)&g_G[gbase + (size_t)i * 256 + jt + u4 * 4];
            float ai = Ac2[i];
            int j0 = jt + u4 * 4;
            float v0 = (j0 + 0 <= i) ? exp2f(ai - Ac2[j0 + 0]) * gv.x : 0.f;
            float v1 = (j0 + 1 <= i) ? exp2f(ai - Ac2[j0 + 1]) * gv.y : 0.f;
            float v2 = (j0 + 2 <= i) ? exp2f(ai - Ac2[j0 + 2]) * gv.z : 0.f;
            float v3 = (j0 + 3 <= i) ? exp2f(ai - Ac2[j0 + 3]) * gv.w : 0.f;
            uint32_t lo01, lo23;
            uint32_t hi01 = pack2h(v0, v1, lo01);
            uint32_t hi23 = pack2h(v2, v3, lo23);
            uint32_t base = i * 128 + (((u4 >> 1) ^ (i & 7)) * 16) + (u4 & 1) * 8;
            *(uint2*)(ysm + base)         = make_uint2(hi01, hi23);
            *(uint2*)(ysm + 32768 + base) = make_uint2(lo01, lo23);
        }
        for (int idx = tid; idx < 64 * 16; idx += 512) {
            int l = idx >> 4, u = idx & 15;
            size_t src = (size_t)(brow + jt + l) * DINNER + h * HEADDIM + u * 8;
            uint32_t dst = l * 256 + ((u ^ (l & 7)) * 16);
            *(uint4*)(ysm + 65536 + dst) = *(const uint4*)(g_xf16 + src);
        }
        __syncthreads();
        if (wr * 64 + 63 >= jt) {
#pragma unroll
            for (int s = 0; s < 4; s++) {
                uint32_t afh[4][4], afl[4][4];
#pragma unroll
                for (int mt = 0; mt < 4; mt++) {
                    int row = wr * 64 + mt * 16 + arow;
                    uint32_t off = row * 128 + (((2 * s + ahalf) ^ (row & 7)) * 16);
                    LDSM_X4(afh[mt][0], afh[mt][1], afh[mt][2], afh[mt][3], sb + off);
                    LDSM_X4(afl[mt][0], afl[mt][1], afl[mt][2], afl[mt][3], sb + 32768 + off);
                }
#pragma unroll
                for (int ntp = 0; ntp < 2; ntp++) {
                    int krow = s * 16 + bkt;
                    int p = wc * 32 + ntp * 16 + bnt;
                    uint32_t off = krow * 256 + (((p >> 3) ^ (krow & 7)) * 16);
                    uint32_t b0, b1, b2, b3;
                    LDSM_X4_T(b0, b1, b2, b3, sb + 65536 + off);
#pragma unroll
                    for (int mt = 0; mt < 4; mt++) {
                        mma16816h(acc[mt][2*ntp+0], afh[mt], b0, b1);
                        mma16816h(acc[mt][2*ntp+0], afl[mt], b0, b1);
                        mma16816h(acc[mt][2*ntp+1], afh[mt], b2, b3);
                        mma16816h(acc[mt][2*ntp+1], afl[mt], b2, b3);
                    }
                }
            }
        }
    }

    // ---- part 2: Ce @ S^T (K = 64) ----
    __syncthreads();
    for (int idx = tid; idx < 256 * 16; idx += 512) {
        int i = idx >> 4, u4 = idx & 15;
        float4 cv = *(const float4*)&g_Cv[(size_t)(brow + i) * 64 + u4 * 4];
        float e = eAc[i];
        uint32_t lo01, lo23;
        uint32_t hi01 = pack2h(cv.x * e, cv.y * e, lo01);
        uint32_t hi23 = pack2h(cv.z * e, cv.w * e, lo23);
        uint32_t base = i * 128 + (((u4 >> 1) ^ (i & 7)) * 16) + (u4 & 1) * 8;
        *(uint2*)(ysm + base)         = make_uint2(hi01, hi23);
        *(uint2*)(ysm + 32768 + base) = make_uint2(lo01, lo23);
    }
    for (int idx = tid; idx < 128 * 16; idx += 512) {
        int p = idx >> 4, u4 = idx & 15;
        float4 sv = *(const float4*)&g_prefix[sbase + (size_t)p * 64 + u4 * 4];
        uint32_t h01 = rnd2h(sv.x, sv.y);
        uint32_t h23 = rnd2h(sv.z, sv.w);
        uint32_t base = p * 128 + (((u4 >> 1) ^ (p & 7)) * 16) + (u4 & 1) * 8;
        *(uint2*)(ysm + 65536 + base) = make_uint2(h01, h23);
    }
    __syncthreads();
#pragma unroll
    for (int s = 0; s < 4; s++) {
        uint32_t afh[4][4], afl[4][4];
#pragma unroll
        for (int mt = 0; mt < 4; mt++) {
            int row = wr * 64 + mt * 16 + arow;
            uint32_t off = row * 128 + (((2 * s + ahalf) ^ (row & 7)) * 16);
            LDSM_X4(afh[mt][0], afh[mt][1], afh[mt][2], afh[mt][3], sb + off);
            LDSM_X4(afl[mt][0], afl[mt][1], afl[mt][2], afl[mt][3], sb + 32768 + off);
        }
#pragma unroll
        for (int ntp = 0; ntp < 2; ntp++) {
            int row = wc * 32 + ntp * 16 + brw2;
            uint32_t off = row * 128 + (((2 * s + bhf2) ^ (row & 7)) * 16);
            uint32_t b0, b1, b2, b3;
            LDSM_X4(b0, b1, b2, b3, sb + 65536 + off);
#pragma unroll
            for (int mt = 0; mt < 4; mt++) {
                mma16816h(acc[mt][2*ntp+0], afh[mt], b0, b1);
                mma16816h(acc[mt][2*ntp+0], afl[mt], b0, b1);
                mma16816h(acc[mt][2*ntp+1], afh[mt], b2, b3);
                mma16816h(acc[mt][2*ntp+1], afl[mt], b2, b3);
            }
        }
    }

    // ---- epilogue ----
#pragma unroll
    for (int mt = 0; mt < 4; mt++) {
        int i0 = wr * 64 + mt * 16 + (lane >> 2);
#pragma unroll
        for (int nt = 0; nt < 4; nt++) {
            int col = h * HEADDIM + wc * 32 + nt * 8 + (lane & 3) * 2;
            *(float2*)(g_y + (size_t)(brow + i0) * DINNER + col) =
                make_float2(acc[mt][nt][0], acc[mt][nt][1]);
            *(float2*)(g_y + (size_t)(brow + i0 + 8) * DINNER + col) =
                make_float2(acc[mt][nt][2], acc[mt][nt][3]);
        }
    }
}

// ---------------- gating (y * silu(z)) + LayerNorm; emits single fp16 ----------------
__global__ void __launch_bounds__(256) ln_kernel(const float* __restrict__ lnw, const float* __restrict__ lnb)
{
    int row = blockIdx.x;
    int tid = threadIdx.x;
    float gv[4][4];
    float s = 0.f, s2 = 0.f;
#pragma unroll
    for (int q = 0; q < 4; q++) {
        int i = (tid + q * 256) * 4;
        float4 yv = *(const float4*)&g_y[(size_t)row * DINNER + i];
        float4 zv = *(const float4*)&g_zxbcdt[(size_t)row * DINPROJ + i];
        float v0 = yv.x * siluf(zv.x);
        float v1 = yv.y * siluf(zv.y);
        float v2 = yv.z * siluf(zv.z);
        float v3 = yv.w * siluf(zv.w);
        gv[q][0] = v0; gv[q][1] = v1; gv[q][2] = v2; gv[q][3] = v3;
        s += v0 + v1 + v2 + v3;
        s2 = fmaf(v0, v0, s2); s2 = fmaf(v1, v1, s2);
        s2 = fmaf(v2, v2, s2); s2 = fmaf(v3, v3, s2);
    }
    __shared__ float red[2][8];
#pragma unroll
    for (int off = 16; off > 0; off >>= 1) {
        s  += __shfl_xor_sync(0xffffffffu, s, off);
        s2 += __shfl_xor_sync(0xffffffffu, s2, off);
    }
    if ((tid & 31) == 0) { red[0][tid >> 5] = s; red[1][tid >> 5] = s2; }
    __syncthreads();
    if (tid == 0) {
        float a = 0.f, a2 = 0.f;
#pragma unroll
        for (int w = 0; w < 8; w++) { a += red[0][w]; a2 += red[1][w]; }
        red[0][0] = a; red[1][0] = a2;
    }
    __syncthreads();
    float mu  = red[0][0] * (1.f / DINNER);
    float var = red[1][0] * (1.f / DINNER) - mu * mu;
    float rstd = rsqrtf(var + LN_EPS);
#pragma unroll
    for (int q = 0; q < 4; q++) {
        int i = (tid + q * 256) * 4;
        float4 wv = *(const float4*)&lnw[i];
        float4 bv = *(const float4*)&lnb[i];
        float o0 = (gv[q][0] - mu) * rstd * wv.x + bv.x;
        float o1 = (gv[q][1] - mu) * rstd * wv.y + bv.y;
        float o2 = (gv[q][2] - mu) * rstd * wv.z + bv.z;
        float o3 = (gv[q][3] - mu) * rstd * wv.w + bv.w;
        *(uint2*)&g_ynh[(size_t)row * DINNER + i] = make_uint2(rnd2h(o0, o1), rnd2h(o2, o3));
    }
}

// ---------------- launch ----------------
extern "C" void kernel_launch(void* const* d_in, const int* in_sizes, int n_in,
                              void* d_out, int out_size)
{
    const float* u          = (const float*)d_in[0];
    const float* in_proj_w  = (const float*)d_in[1];
    const float* in_proj_b  = (const float*)d_in[2];
    const float* conv_w     = (const float*)d_in[3];
    const float* conv_b     = (const float*)d_in[4];
    const float* dt_bias    = (const float*)d_in[5];
    const float* A_log      = (const float*)d_in[6];
    const float* ln_w       = (const float*)d_in[7];
    const float* ln_b       = (const float*)d_in[8];
    const float* out_proj_w = (const float*)d_in[9];
    const float* out_proj_b = (const float*)d_in[10];
    float* out = (float*)d_out;

    float *zx, *gB, *gC, *gG;
    __half *uh, *w1h, *ynh, *w2h;
    cudaGetSymbolAddress((void**)&zx,  g_zxbcdt);
    cudaGetSymbolAddress((void**)&gB,  g_Bv);
    cudaGetSymbolAddress((void**)&gC,  g_Cv);
    cudaGetSymbolAddress((void**)&gG,  g_G);
    cudaGetSymbolAddress((void**)&uh,  g_uh);
    cudaGetSymbolAddress((void**)&w1h, g_w1h);
    cudaGetSymbolAddress((void**)&ynh, g_ynh);
    cudaGetSymbolAddress((void**)&w2h, g_w2h);

    cudaFuncSetAttribute(mma_gemm_nt1, cudaFuncAttributeMaxDynamicSharedMemorySize, 3 * GST1);
    cudaFuncSetAttribute(yfused_mma,   cudaFuncAttributeMaxDynamicSharedMemorySize, YSMEM);

    // 0) fp32 -> fp16 rounding: u, in_proj_w, out_proj_w in one launch
    {
        long n1 = (long)NROWS * DMODEL / 4;
        long n2 = (long)DINPROJ * DMODEL / 4;
        long n3 = (long)DMODEL * DINNER / 4;
        round3_f16<<<(unsigned)((n1 + n2 + n3 + 255) / 256), 256>>>(
            u, uh, n1, in_proj_w, w1h, n2, out_proj_w, w2h, n3);
    }

    // 1) in_proj: M=8192, N=8352, K=2048 (1-term)
    mma_gemm_nt1<<<dim3((DINPROJ + 255) / 256, NROWS / 128), 512, 3 * GST1>>>(
        uh, w1h, in_proj_b, zx, DINPROJ, DMODEL);

    // 2) fused dt softplus + per-chunk cumsum (warp scan)
    cumsum_kernel<<<dim3(NCHUNK, NHEADS, BATCH), CHUNKT>>>(dt_bias, A_log);

    // 3) causal conv + silu (8 outputs/thread)
    {
        long total = (long)(NROWS / 8) * CONVDIM;
        conv_kernel<<<(unsigned)((total + 255) / 256), 256>>>(conv_w, conv_b);
    }

    // 4) G = C @ B^T per (b,chunk)  (upper-right block skipped inside)
    sgemm_nt<<<dim3(2, 2, BATCH * NCHUNK), 256>>>(
        gC, gB, nullptr, gG, CHUNKT, DSTATE,
        (long)CHUNKT * DSTATE, (long)CHUNKT * DSTATE, (long)CHUNKT * CHUNKT);

    // 5) chunk-local states on tensor cores
    states_mma<<<dim3(NHEADS, NCHUNK, BATCH), 256>>>();

    // 6) inter-chunk scan (16-way split)
    scan_kernel<<<BATCH * NHEADS * 16, 128>>>();

    // 7) fused Y on tensor cores
    yfused_mma<<<dim3(NHEADS, NCHUNK, BATCH), 512, YSMEM>>>();

    // 8) gate + layernorm (single fp16 yn)
    ln_kernel<<<NROWS, 256>>>(ln_w, ln_b);

    // 9) out_proj: M=8192, N=2048, K=4096 (1-term)
    mma_gemm_nt1<<<dim3(DMODEL / 256, NROWS / 128), 512, 3 * GST1>>>(
        ynh, w2h, out_proj_b, out, DMODEL, DINNER);
}

// round 17
// speedup vs baseline: 1.7753x; 1.0069x over previous
#include <cuda_runtime.h>
#include <cuda_bf16.h>
#include <cuda_fp16.h>
#include <cstdint>
#include <math.h>

#define BATCH   2
#define SEQLEN  4096
#define DMODEL  2048
#define DINNER  4096
#define NHEADS  32
#define HEADDIM 128
#define DSTATE  64
#define NCHUNK  16
#define CHUNKT  256
#define CONVDIM 4224
#define DINPROJ 8352
#define NROWS   (BATCH*SEQLEN)
#define LN_EPS  1e-5f
#define LOG2E   1.4426950408889634f

// ---------------- scratch (device globals; no allocations allowed) ----------------
__device__ float g_zxbcdt[(size_t)NROWS * DINPROJ];   // xBC | dt region fp32 (z routed to g_zh)
__device__ float g_Bv   [NROWS * DSTATE];
__device__ float g_Cv   [NROWS * DSTATE];
__device__ float g_dt   [NROWS * NHEADS];
__device__ float g_Acum [BATCH * NHEADS * SEQLEN];
__device__ float g_G    [(size_t)BATCH * NCHUNK * CHUNKT * CHUNKT];
__device__ float g_states[(size_t)BATCH * NCHUNK * NHEADS * HEADDIM * DSTATE];
__device__ float g_prefix[(size_t)BATCH * NCHUNK * NHEADS * HEADDIM * DSTATE];

// fp16 buffers (single-rounded)
__device__ __half g_uh [(size_t)NROWS * DMODEL];
__device__ __half g_w1h[(size_t)DINPROJ * DMODEL];
__device__ __half g_ynh[(size_t)NROWS * DINNER];
__device__ __half g_w2h[(size_t)DMODEL * DINNER];
__device__ __half g_xf16[(size_t)NROWS * DINNER];   // rounded fp16 of xdt
__device__ __half g_zh [(size_t)NROWS * DINNER];    // fp16 z (from in_proj epilogue)
__device__ __half g_yh [(size_t)NROWS * DINNER];    // fp16 Y (from yfused epilogue)

__device__ __forceinline__ float siluf(float x) { return x / (1.f + __expf(-x)); }

__device__ __forceinline__ uint32_t smem_u32(const void* p) {
    uint32_t a;
    asm("{ .reg .u64 t; cvta.to.shared.u64 t, %1; cvt.u32.u64 %0, t; }" : "=r"(a) : "l"(p));
    return a;
}

// pack two floats into fp16x2 hi; return hi, write lo (exact 2-term split, packed cvt)
__device__ __forceinline__ uint32_t pack2h(float a, float b, uint32_t& lo) {
    __half2 h = __floats2half2_rn(a, b);
    float2 hf = __half22float2(h);
    __half2 l = __floats2half2_rn(a - hf.x, b - hf.y);
    lo = *reinterpret_cast<uint32_t*>(&l);
    return *reinterpret_cast<uint32_t*>(&h);
}
__device__ __forceinline__ uint32_t rnd2h(float a, float b) {
    __half2 h = __floats2half2_rn(a, b);
    return *reinterpret_cast<uint32_t*>(&h);
}

// ================= conversion kernel: three tensors rounded in one launch =================
__global__ void round3_f16(const float* __restrict__ a, __half* __restrict__ da, long na4,
                           const float* __restrict__ b, __half* __restrict__ db, long nb4,
                           const float* __restrict__ c, __half* __restrict__ dc, long nc4)
{
    long i = (long)blockIdx.x * blockDim.x + threadIdx.x;
    if (i < na4) {
        float4 x = ((const float4*)a)[i];
        ((uint2*)da)[i] = make_uint2(rnd2h(x.x, x.y), rnd2h(x.z, x.w));
    } else if (i < na4 + nb4) {
        long j = i - na4;
        float4 x = ((const float4*)b)[j];
        ((uint2*)db)[j] = make_uint2(rnd2h(x.x, x.y), rnd2h(x.z, x.w));
    } else if (i < na4 + nb4 + nc4) {
        long j = i - na4 - nb4;
        float4 x = ((const float4*)c)[j];
        ((uint2*)dc)[j] = make_uint2(rnd2h(x.x, x.y), rnd2h(x.z, x.w));
    }
}

// ================= tensor-core primitives =================
__device__ __forceinline__ void mma16816h(float* c, const uint32_t* a, uint32_t b0, uint32_t b1)
{
    asm volatile(
        "mma.sync.aligned.m16n8k16.row.col.f32.f16.f16.f32 "
        "{%0,%1,%2,%3}, {%4,%5,%6,%7}, {%8,%9}, {%0,%1,%2,%3};"
        : "+f"(c[0]), "+f"(c[1]), "+f"(c[2]), "+f"(c[3])
        : "r"(a[0]), "r"(a[1]), "r"(a[2]), "r"(a[3]), "r"(b0), "r"(b1));
}
#define LDSM_X4(r0, r1, r2, r3, addr) \
    asm volatile("ldmatrix.sync.aligned.m8n8.x4.shared.b16 {%0,%1,%2,%3}, [%4];" \
                 : "=r"(r0), "=r"(r1), "=r"(r2), "=r"(r3) : "r"(addr))
#define LDSM_X4_T(r0, r1, r2, r3, addr) \
    asm volatile("ldmatrix.sync.aligned.m8n8.x4.trans.shared.b16 {%0,%1,%2,%3}, [%4];" \
                 : "=r"(r0), "=r"(r1), "=r"(r2), "=r"(r3) : "r"(addr))
#define CP16(dst, src, sz) \
    asm volatile("cp.async.cg.shared.global [%0], [%1], 16, %2;" \
                 :: "r"(dst), "l"(src), "r"(sz))
#define CP_COMMIT() asm volatile("cp.async.commit_group;" ::: "memory")
#define CP_WAIT1()  asm volatile("cp.async.wait_group 1;" ::: "memory")
#define CP_WAIT0()  asm volatile("cp.async.wait_group 0;" ::: "memory")

// ================= fp16 1-MMA GEMM: C = Ah*Bh^T + bias =================
// BM=128, BN=256, BK=64, 512 threads (16 warps, 32x64 warp tiles), 3-stage cp.async.
// If Zh != null, columns < DINNER are written as fp16 to Zh (row stride DINNER)
// instead of fp32 to C (used by in_proj to emit the z gate directly in fp16).
#define GST1 49152
__global__ void __launch_bounds__(512, 1)
mma_gemm_nt1(const __half* __restrict__ Ah, const __half* __restrict__ Bh,
             const float* __restrict__ bias, float* __restrict__ C,
             __half* __restrict__ Zh, int N, int K)
{
    extern __shared__ char smem[];
    const uint32_t sb = smem_u32(smem);
    const int tid = threadIdx.x, lane = tid & 31, wid = tid >> 5;
    const int wr = wid >> 2, wc = wid & 3;
    const int mbase = blockIdx.y * 128;
    const int nbase = blockIdx.x * 256;

    const int ra = tid >> 2, ua0 = (tid & 3) * 2;
    const int rb = tid >> 1, ub0 = (tid & 1) * 4;
    const bool bval = (nbase + rb) < N;
    const uint32_t bsz = bval ? 16u : 0u;
    const __half* gAh = Ah + (size_t)(mbase + ra) * K + ua0 * 8;
    const __half* gBh = Bh + (size_t)(bval ? nbase + rb : 0) * K + ub0 * 8;
    const uint32_t dA0 = ra * 128 + (( ua0      ^ (ra & 7)) * 16);
    const uint32_t dA1 = ra * 128 + (((ua0 + 1) ^ (ra & 7)) * 16);
    uint32_t dB[4];
#pragma unroll
    for (int j = 0; j < 4; j++) dB[j] = rb * 128 + (((ub0 + j) ^ (rb & 7)) * 16);

    auto issue = [&](int st, int kt) {
        uint32_t s0 = sb + st * GST1;
        CP16(s0 + dA0, gAh + kt,     16);
        CP16(s0 + dA1, gAh + kt + 8, 16);
#pragma unroll
        for (int j = 0; j < 4; j++)
            CP16(s0 + 16384 + dB[j], gBh + kt + j * 8, bsz);
        CP_COMMIT();
    };

    float acc[2][8][4];
#pragma unroll
    for (int mt = 0; mt < 2; mt++)
#pragma unroll
        for (int nt = 0; nt < 8; nt++)
#pragma unroll
            for (int i = 0; i < 4; i++) acc[mt][nt][i] = 0.f;

    const int nk = K >> 6;
    issue(0, 0);
    issue(1, 64);

    const int g = lane >> 3, li = lane & 7;
    const int arow_lo = (g & 1) * 8 + li;
    const int ahalf   = g >> 1;
    const int brow_lo = (g >> 1) * 8 + li;
    const int bhalf   = g & 1;

    int stage = 0;
    for (int c = 0; c < nk; c++) {
        if (c + 1 < nk) CP_WAIT1(); else CP_WAIT0();
        __syncthreads();
        if (c + 2 < nk) {
            int st = stage + 2; if (st >= 3) st -= 3;
            issue(st, (c + 2) * 64);
        }
        const uint32_t s0 = sb + stage * GST1;
#pragma unroll
        for (int s = 0; s < 4; s++) {
            uint32_t af[2][4];
#pragma unroll
            for (int mt = 0; mt < 2; mt++) {
                int row = wr * 32 + mt * 16 + arow_lo;
                uint32_t off = row * 128 + (((2 * s + ahalf) ^ (row & 7)) * 16);
                LDSM_X4(af[mt][0], af[mt][1], af[mt][2], af[mt][3], s0 + off);
            }
#pragma unroll
            for (int ntp = 0; ntp < 4; ntp++) {
                int row = wc * 64 + ntp * 16 + brow_lo;
                uint32_t off = row * 128 + (((2 * s + bhalf) ^ (row & 7)) * 16);
                uint32_t b0, b1, b2, b3;
                LDSM_X4(b0, b1, b2, b3, s0 + 16384 + off);
#pragma unroll
                for (int mt = 0; mt < 2; mt++) {
                    mma16816h(acc[mt][2*ntp+0], af[mt], b0, b1);
                    mma16816h(acc[mt][2*ntp+1], af[mt], b2, b3);
                }
            }
        }
        stage++; if (stage >= 3) stage -= 3;
    }

#pragma unroll
    for (int mt = 0; mt < 2; mt++) {
        int r0 = mbase + wr * 32 + mt * 16 + (lane >> 2);
#pragma unroll
        for (int nt = 0; nt < 8; nt++) {
            int col = nbase + wc * 64 + nt * 8 + (lane & 3) * 2;
            if (col < N) {
                float b0 = bias ? bias[col] : 0.f;
                float b1 = bias ? bias[col + 1] : 0.f;
                float a00 = acc[mt][nt][0] + b0, a01 = acc[mt][nt][1] + b1;
                float a10 = acc[mt][nt][2] + b0, a11 = acc[mt][nt][3] + b1;
                if (Zh && col < DINNER) {
                    *(uint32_t*)&Zh[(size_t)r0 * DINNER + col]       = rnd2h(a00, a01);
                    *(uint32_t*)&Zh[(size_t)(r0 + 8) * DINNER + col] = rnd2h(a10, a11);
                } else {
                    *(float2*)(C + (size_t)r0 * N + col)       = make_float2(a00, a01);
                    *(float2*)(C + (size_t)(r0 + 8) * N + col) = make_float2(a10, a11);
                }
            }
        }
    }
}

// ---------------- small fp32 NT GEMM (G = C @ B^T); skips strictly-upper block ----------------
__global__ void __launch_bounds__(256)
sgemm_nt(const float* __restrict__ A, const float* __restrict__ B,
         const float* __restrict__ bias, float* __restrict__ C,
         int N, int K, long sA, long sB, long sC)
{
    if (blockIdx.x * 128 > blockIdx.y * 128 + 127) return;

    __shared__ float As[16][128];
    __shared__ float Bs[16][128];
    const int tid  = threadIdx.x;
    const int tcol = tid & 15;
    const int trow = tid >> 4;
    const float* Ab = A + (size_t)blockIdx.z * sA + (size_t)blockIdx.y * 128 * K;
    const float* Bb = B + (size_t)blockIdx.z * sB + (size_t)blockIdx.x * 128 * K;
    const int nbase = blockIdx.x * 128;

    float acc[8][8];
#pragma unroll
    for (int m = 0; m < 8; m++)
#pragma unroll
        for (int n = 0; n < 8; n++) acc[m][n] = 0.f;

    const int lrow = tid >> 2;
    const int lcol = (tid & 3) * 4;

    for (int kt = 0; kt < K; kt += 16) {
#pragma unroll
        for (int it = 0; it < 2; it++) {
            int r = lrow + it * 64;
            float4 va = *(const float4*)(Ab + (size_t)r * K + kt + lcol);
            As[lcol+0][r] = va.x; As[lcol+1][r] = va.y;
            As[lcol+2][r] = va.z; As[lcol+3][r] = va.w;
            float4 vb;
            if (nbase + r < N) vb = *(const float4*)(Bb + (size_t)r * K + kt + lcol);
            else               vb = make_float4(0.f, 0.f, 0.f, 0.f);
            Bs[lcol+0][r] = vb.x; Bs[lcol+1][r] = vb.y;
            Bs[lcol+2][r] = vb.z; Bs[lcol+3][r] = vb.w;
        }
        __syncthreads();
#pragma unroll
        for (int k = 0; k < 16; k++) {
            float ra[8], rb[8];
#pragma unroll
            for (int m = 0; m < 8; m++) ra[m] = As[k][trow * 8 + m];
#pragma unroll
            for (int n = 0; n < 8; n++) rb[n] = Bs[k][tcol * 8 + n];
#pragma unroll
            for (int m = 0; m < 8; m++)
#pragma unroll
                for (int n = 0; n < 8; n++) acc[m][n] = fmaf(ra[m], rb[n], acc[m][n]);
        }
        __syncthreads();
    }
#pragma unroll
    for (int m = 0; m < 8; m++) {
        int row = blockIdx.y * 128 + trow * 8 + m;
#pragma unroll
        for (int n = 0; n < 8; n++) {
            int col = nbase + tcol * 8 + n;
            if (col < N) {
                float bv = bias ? bias[col] : 0.f;
                C[(size_t)blockIdx.z * sC + (size_t)row * N + col] = acc[m][n] + bv;
            }
        }
    }
}

// ---------------- fused dt softplus + per-chunk inclusive cumsum (warp scan) ----------------
__global__ void cumsum_kernel(const float* __restrict__ dt_bias, const float* __restrict__ A_log)
{
    int c = blockIdx.x, h = blockIdx.y, b = blockIdx.z;
    int t = threadIdx.x, lane = t & 31, wid = t >> 5;
    __shared__ float wsum[8];
    int row = b * SEQLEN + c * CHUNKT + t;
    float v = g_zxbcdt[(size_t)row * DINPROJ + DINNER + CONVDIM + h] + dt_bias[h];
    float dtv = (v > 20.f) ? v : log1pf(__expf(v));
    g_dt[row * NHEADS + h] = dtv;
    float x = -__expf(A_log[h]) * dtv;
#pragma unroll
    for (int off = 1; off < 32; off <<= 1) {
        float y = __shfl_up_sync(0xffffffffu, x, off);
        if (lane >= off) x += y;
    }
    if (lane == 31) wsum[wid] = x;
    __syncthreads();
    if (wid == 0 && lane < 8) {
        float w = wsum[lane];
#pragma unroll
        for (int off = 1; off < 8; off <<= 1) {
            float y = __shfl_up_sync(0xffu, w, off);
            if (lane >= off) w += y;
        }
        wsum[lane] = w;
    }
    __syncthreads();
    float base = (wid > 0) ? wsum[wid - 1] : 0.f;
    g_Acum[(b * NHEADS + h) * SEQLEN + c * CHUNKT + t] = base + x;
}

// ---------------- causal depthwise conv + SiLU (8 outputs/thread) ----------------
__global__ void conv_kernel(const float* __restrict__ w, const float* __restrict__ cb)
{
    long idx = (long)blockIdx.x * blockDim.x + threadIdx.x;
    if (idx >= (long)(NROWS / 8) * CONVDIM) return;
    int c = (int)(idx % CONVDIM);
    int r0 = (int)(idx / CONVDIM) * 8;
    int l0 = r0 & (SEQLEN - 1);
    float v[11];
#pragma unroll
    for (int k = 0; k < 11; k++) {
        int l = l0 - 3 + k;
        v[k] = (l >= 0) ? g_zxbcdt[(size_t)(r0 - 3 + k) * DINPROJ + DINNER + c] : 0.f;
    }
    const float w0 = w[c * 4], w1 = w[c * 4 + 1], w2 = w[c * 4 + 2], w3 = w[c * 4 + 3];
    const float bias = cb[c];
#pragma unroll
    for (int j = 0; j < 8; j++) {
        float acc = bias;
        acc = fmaf(w0, v[j + 0], acc);
        acc = fmaf(w1, v[j + 1], acc);
        acc = fmaf(w2, v[j + 2], acc);
        acc = fmaf(w3, v[j + 3], acc);
        float out = siluf(acc);
        int r = r0 + j;
        if (c < DINNER) {
            float xv = out * g_dt[r * NHEADS + (c >> 7)];
            g_xf16[(size_t)r * DINNER + c] = __float2half_rn(xv);
        } else if (c < DINNER + DSTATE) {
            g_Bv[r * DSTATE + (c - DINNER)] = out;
        } else {
            g_Cv[r * DSTATE + (c - DINNER - DSTATE)] = out;
        }
    }
}

// ---------------- chunk-local states on tensor cores ----------------
__global__ void __launch_bounds__(256) states_mma()
{
    __shared__ __align__(16) char sX[64 * 256];
    __shared__ __align__(16) char sB[64 * 128];
    __shared__ float Ac[CHUNKT];
    const int h = blockIdx.x, c = blockIdx.y, b = blockIdx.z;
    const int tid = threadIdx.x, lane = tid & 31, wid = tid >> 5;
    const int wr = wid >> 1, wc = wid & 1;
    const int brow = b * SEQLEN + c * CHUNKT;
    const uint32_t sbX = smem_u32(sX), sbB = smem_u32(sB);

    Ac[tid] = g_Acum[(b * NHEADS + h) * SEQLEN + c * CHUNKT + tid];
    __syncthreads();
    const float Atot = Ac[CHUNKT - 1];

    float acc[2][4][4];
#pragma unroll
    for (int mt = 0; mt < 2; mt++)
#pragma unroll
        for (int nt = 0; nt < 4; nt++)
#pragma unroll
            for (int i = 0; i < 4; i++) acc[mt][nt][i] = 0.f;

    const int g = lane >> 3, li = lane & 7;
    const int akr = (g >> 1) * 8 + li;
    const int amc = (g & 1) * 8;
    const int bkr = (g & 1) * 8 + li;
    const int bnc = (g >> 1) * 8;

    for (int lt = 0; lt < CHUNKT; lt += 64) {
        if (lt) __syncthreads();
        for (int idx = tid; idx < 64 * 16; idx += 256) {
            int l = idx >> 4, u = idx & 15;
            size_t src = (size_t)(brow + lt + l) * DINNER + h * HEADDIM + u * 8;
            uint32_t dst = l * 256 + ((u ^ (l & 7)) * 16);
            *(uint4*)(sX + dst) = *(const uint4*)(g_xf16 + src);
        }
        for (int idx = tid; idx < 64 * 16; idx += 256) {
            int l = idx >> 4, u4 = idx & 15;
            float4 bv = *(const float4*)&g_Bv[(size_t)(brow + lt + l) * DSTATE + u4 * 4];
            float e = __expf(Atot - Ac[lt + l]);
            uint32_t h01 = rnd2h(bv.x * e, bv.y * e);
            uint32_t h23 = rnd2h(bv.z * e, bv.w * e);
            uint32_t dst = l * 128 + (((u4 >> 1) ^ (l & 7)) * 16) + (u4 & 1) * 8;
            *(uint2*)(sB + dst) = make_uint2(h01, h23);
        }
        __syncthreads();
#pragma unroll
        for (int s = 0; s < 4; s++) {
            uint32_t af[2][4];
#pragma unroll
            for (int mt = 0; mt < 2; mt++) {
                int kr = s * 16 + akr;
                int mc = wr * 32 + mt * 16 + amc;
                uint32_t off = kr * 256 + (((mc >> 3) ^ (kr & 7)) * 16);
                LDSM_X4_T(af[mt][0], af[mt][1], af[mt][2], af[mt][3], sbX + off);
            }
#pragma unroll
            for (int ntp = 0; ntp < 2; ntp++) {
                int kr = s * 16 + bkr;
                int nc = wc * 32 + ntp * 16 + bnc;
                uint32_t off = kr * 128 + (((nc >> 3) ^ (kr & 7)) * 16);
                uint32_t b0, b1, b2, b3;
                LDSM_X4_T(b0, b1, b2, b3, sbB + off);
#pragma unroll
                for (int mt = 0; mt < 2; mt++) {
                    mma16816h(acc[mt][2*ntp+0], af[mt], b0, b1);
                    mma16816h(acc[mt][2*ntp+1], af[mt], b2, b3);
                }
            }
        }
    }

    size_t base = ((size_t)((b * NCHUNK + c) * NHEADS + h)) * HEADDIM * DSTATE;
#pragma unroll
    for (int mt = 0; mt < 2; mt++) {
        int p0 = wr * 32 + mt * 16 + (lane >> 2);
#pragma unroll
        for (int nt = 0; nt < 4; nt++) {
            int n = wc * 32 + nt * 8 + (lane & 3) * 2;
            *(float2*)(g_states + base + (size_t)p0 * DSTATE + n) =
                make_float2(acc[mt][nt][0], acc[mt][nt][1]);
            *(float2*)(g_states + base + (size_t)(p0 + 8) * DSTATE + n) =
                make_float2(acc[mt][nt][2], acc[mt][nt][3]);
        }
    }
}

// ---------------- inter-chunk state scan (16-way split per (b,h)) ----------------
__global__ void scan_kernel()
{
    int bh = blockIdx.x >> 4, seg = blockIdx.x & 15;
    int b = bh >> 5, h = bh & 31;
    int t = threadIdx.x;    // 128 threads
    size_t off = (size_t)seg * 512 + (size_t)t * 4;
    float4 S = make_float4(0.f, 0.f, 0.f, 0.f);
    for (int c = 0; c < NCHUNK; c++) {
        size_t base = ((size_t)((b * NCHUNK + c) * NHEADS + h)) * (HEADDIM * DSTATE) + off;
        *(float4*)(g_prefix + base) = S;
        float f = __expf(g_Acum[(b * NHEADS + h) * SEQLEN + c * CHUNKT + CHUNKT - 1]);
        float4 st = *(const float4*)(g_states + base);
        S.x = S.x * f + st.x;
        S.y = S.y * f + st.y;
        S.z = S.z * f + st.z;
        S.w = S.w * f + st.w;
    }
}

// ================= fused Y on tensor cores (fp16 2-term); fp16 output =================
// smem: WH 0 (32K) | WL 32768 (32K) | X/S 65536 (16K) | Ac2 81920 | eAc 82944
#define YSMEM 84992
__global__ void __launch_bounds__(512, 1) yfused_mma()
{
    extern __shared__ char ysm[];
    const uint32_t sb = smem_u32(ysm);
    float* Ac2 = (float*)(ysm + 81920);
    float* eAc = (float*)(ysm + 82944);
    const int h = blockIdx.x, c = blockIdx.y, b = blockIdx.z;
    const int tid = threadIdx.x, lane = tid & 31, wid = tid >> 5;
    const int wr = wid >> 2, wc = wid & 3;
    const int brow = b * SEQLEN + c * CHUNKT;
    const size_t gbase = (size_t)(b * NCHUNK + c) * CHUNKT * CHUNKT;
    const size_t sbase = ((size_t)((b * NCHUNK + c) * NHEADS + h)) * (HEADDIM * DSTATE);

    if (tid < CHUNKT) {
        float a = g_Acum[(b * NHEADS + h) * SEQLEN + c * CHUNKT + tid];
        Ac2[tid] = a * LOG2E;
        eAc[tid] = __expf(a);
    }

    float acc[4][4][4];
#pragma unroll
    for (int mt = 0; mt < 4; mt++)
#pragma unroll
        for (int nt = 0; nt < 4; nt++)
#pragma unroll
            for (int i = 0; i < 4; i++) acc[mt][nt][i] = 0.f;

    const int g = lane >> 3, li = lane & 7;
    const int arow  = (g & 1) * 8 + li;
    const int ahalf = g >> 1;
    const int bkt   = (g & 1) * 8 + li;
    const int bnt   = (g >> 1) * 8;
    const int brw2  = (g >> 1) * 8 + li;
    const int bhf2  = g & 1;

    // ---- part 1: W @ X over 4 j-tiles of 64; stage W rows [jt,256) only ----
    for (int jt = 0; jt < CHUNKT; jt += 64) {
        __syncthreads();
        const int nrows = CHUNKT - jt;
        for (int idx = tid; idx < nrows * 16; idx += 512) {
            int i = jt + (idx >> 4), u4 = idx & 15;
            float4 gv = *(const float4*)&g_G[gbase + (size_t)i * 256 + jt + u4 * 4];
            float ai = Ac2[i];
            int j0 = jt + u4 * 4;
            float v0 = (j0 + 0 <= i) ? exp2f(ai - Ac2[j0 + 0]) * gv.x : 0.f;
            float v1 = (j0 + 1 <= i) ? exp2f(ai - Ac2[j0 + 1]) * gv.y : 0.f;
            float v2 = (j0 + 2 <= i) ? exp2f(ai - Ac2[j0 + 2]) * gv.z : 0.f;
            float v3 = (j0 + 3 <= i) ? exp2f(ai - Ac2[j0 + 3]) * gv.w : 0.f;
            uint32_t lo01, lo23;
            uint32_t hi01 = pack2h(v0, v1, lo01);
            uint32_t hi23 = pack2h(v2, v3, lo23);
            uint32_t base = i * 128 + (((u4 >> 1) ^ (i & 7)) * 16) + (u4 & 1) * 8;
            *(uint2*)(ysm + base)         = make_uint2(hi01, hi23);
            *(uint2*)(ysm + 32768 + base) = make_uint2(lo01, lo23);
        }
        for (int idx = tid; idx < 64 * 16; idx += 512) {
            int l = idx >> 4, u = idx & 15;
            size_t src = (size_t)(brow + jt + l) * DINNER + h * HEADDIM + u * 8;
            uint32_t dst = l * 256 + ((u ^ (l & 7)) * 16);
            *(uint4*)(ysm + 65536 + dst) = *(const uint4*)(g_xf16 + src);
        }
        __syncthreads();
        if (wr * 64 + 63 >= jt) {
#pragma unroll
            for (int s = 0; s < 4; s++) {
                uint32_t afh[4][4], afl[4][4];
#pragma unroll
                for (int mt = 0; mt < 4; mt++) {
                    int row = wr * 64 + mt * 16 + arow;
                    uint32_t off = row * 128 + (((2 * s + ahalf) ^ (row & 7)) * 16);
                    LDSM_X4(afh[mt][0], afh[mt][1], afh[mt][2], afh[mt][3], sb + off);
                    LDSM_X4(afl[mt][0], afl[mt][1], afl[mt][2], afl[mt][3], sb + 32768 + off);
                }
#pragma unroll
                for (int ntp = 0; ntp < 2; ntp++) {
                    int krow = s * 16 + bkt;
                    int p = wc * 32 + ntp * 16 + bnt;
                    uint32_t off = krow * 256 + (((p >> 3) ^ (krow & 7)) * 16);
                    uint32_t b0, b1, b2, b3;
                    LDSM_X4_T(b0, b1, b2, b3, sb + 65536 + off);
#pragma unroll
                    for (int mt = 0; mt < 4; mt++) {
                        mma16816h(acc[mt][2*ntp+0], afh[mt], b0, b1);
                        mma16816h(acc[mt][2*ntp+0], afl[mt], b0, b1);
                        mma16816h(acc[mt][2*ntp+1], afh[mt], b2, b3);
                        mma16816h(acc[mt][2*ntp+1], afl[mt], b2, b3);
                    }
                }
            }
        }
    }

    // ---- part 2: Ce @ S^T (K = 64) ----
    __syncthreads();
    for (int idx = tid; idx < 256 * 16; idx += 512) {
        int i = idx >> 4, u4 = idx & 15;
        float4 cv = *(const float4*)&g_Cv[(size_t)(brow + i) * 64 + u4 * 4];
        float e = eAc[i];
        uint32_t lo01, lo23;
        uint32_t hi01 = pack2h(cv.x * e, cv.y * e, lo01);
        uint32_t hi23 = pack2h(cv.z * e, cv.w * e, lo23);
        uint32_t base = i * 128 + (((u4 >> 1) ^ (i & 7)) * 16) + (u4 & 1) * 8;
        *(uint2*)(ysm + base)         = make_uint2(hi01, hi23);
        *(uint2*)(ysm + 32768 + base) = make_uint2(lo01, lo23);
    }
    for (int idx = tid; idx < 128 * 16; idx += 512) {
        int p = idx >> 4, u4 = idx & 15;
        float4 sv = *(const float4*)&g_prefix[sbase + (size_t)p * 64 + u4 * 4];
        uint32_t h01 = rnd2h(sv.x, sv.y);
        uint32_t h23 = rnd2h(sv.z, sv.w);
        uint32_t base = p * 128 + (((u4 >> 1) ^ (p & 7)) * 16) + (u4 & 1) * 8;
        *(uint2*)(ysm + 65536 + base) = make_uint2(h01, h23);
    }
    __syncthreads();
#pragma unroll
    for (int s = 0; s < 4; s++) {
        uint32_t afh[4][4], afl[4][4];
#pragma unroll
        for (int mt = 0; mt < 4; mt++) {
            int row = wr * 64 + mt * 16 + arow;
            uint32_t off = row * 128 + (((2 * s + ahalf) ^ (row & 7)) * 16);
            LDSM_X4(afh[mt][0], afh[mt][1], afh[mt][2], afh[mt][3], sb + off);
            LDSM_X4(afl[mt][0], afl[mt][1], afl[mt][2], afl[mt][3], sb + 32768 + off);
        }
#pragma unroll
        for (int ntp = 0; ntp < 2; ntp++) {
            int row = wc * 32 + ntp * 16 + brw2;
            uint32_t off = row * 128 + (((2 * s + bhf2) ^ (row & 7)) * 16);
            uint32_t b0, b1, b2, b3;
            LDSM_X4(b0, b1, b2, b3, sb + 65536 + off);
#pragma unroll
            for (int mt = 0; mt < 4; mt++) {
                mma16816h(acc[mt][2*ntp+0], afh[mt], b0, b1);
                mma16816h(acc[mt][2*ntp+0], afl[mt], b0, b1);
                mma16816h(acc[mt][2*ntp+1], afh[mt], b2, b3);
                mma16816h(acc[mt][2*ntp+1], afl[mt], b2, b3);
            }
        }
    }

    // ---- epilogue (fp16) ----
#pragma unroll
    for (int mt = 0; mt < 4; mt++) {
        int i0 = wr * 64 + mt * 16 + (lane >> 2);
#pragma unroll
        for (int nt = 0; nt < 4; nt++) {
            int col = h * HEADDIM + wc * 32 + nt * 8 + (lane & 3) * 2;
            *(uint32_t*)&g_yh[(size_t)(brow + i0) * DINNER + col] =
                rnd2h(acc[mt][nt][0], acc[mt][nt][1]);
            *(uint32_t*)&g_yh[(size_t)(brow + i0 + 8) * DINNER + col] =
                rnd2h(acc[mt][nt][2], acc[mt][nt][3]);
        }
    }
}

// ---------------- gating (y * silu(z)) + LayerNorm; fp16 in, fp16 out ----------------
__global__ void __launch_bounds__(256) ln_kernel(const float* __restrict__ lnw, const float* __restrict__ lnb)
{
    int row = blockIdx.x;
    int tid = threadIdx.x;
    float gv[4][4];
    float s = 0.f, s2 = 0.f;
#pragma unroll
    for (int q = 0; q < 4; q++) {
        int i = (tid + q * 256) * 4;
        uint2 yv = *(const uint2*)&g_yh[(size_t)row * DINNER + i];
        uint2 zv = *(const uint2*)&g_zh[(size_t)row * DINNER + i];
        float2 y01 = __half22float2(*reinterpret_cast<__half2*>(&yv.x));
        float2 y23 = __half22float2(*reinterpret_cast<__half2*>(&yv.y));
        float2 z01 = __half22float2(*reinterpret_cast<__half2*>(&zv.x));
        float2 z23 = __half22float2(*reinterpret_cast<__half2*>(&zv.y));
        float v0 = y01.x * siluf(z01.x);
        float v1 = y01.y * siluf(z01.y);
        float v2 = y23.x * siluf(z23.x);
        float v3 = y23.y * siluf(z23.y);
        gv[q][0] = v0; gv[q][1] = v1; gv[q][2] = v2; gv[q][3] = v3;
        s += v0 + v1 + v2 + v3;
        s2 = fmaf(v0, v0, s2); s2 = fmaf(v1, v1, s2);
        s2 = fmaf(v2, v2, s2); s2 = fmaf(v3, v3, s2);
    }
    __shared__ float red[2][8];
#pragma unroll
    for (int off = 16; off > 0; off >>= 1) {
        s  += __shfl_xor_sync(0xffffffffu, s, off);
        s2 += __shfl_xor_sync(0xffffffffu, s2, off);
    }
    if ((tid & 31) == 0) { red[0][tid >> 5] = s; red[1][tid >> 5] = s2; }
    __syncthreads();
    if (tid == 0) {
        float a = 0.f, a2 = 0.f;
#pragma unroll
        for (int w = 0; w < 8; w++) { a += red[0][w]; a2 += red[1][w]; }
        red[0][0] = a; red[1][0] = a2;
    }
    __syncthreads();
    float mu  = red[0][0] * (1.f / DINNER);
    float var = red[1][0] * (1.f / DINNER) - mu * mu;
    float rstd = rsqrtf(var + LN_EPS);
#pragma unroll
    for (int q = 0; q < 4; q++) {
        int i = (tid + q * 256) * 4;
        float4 wv = *(const float4*)&lnw[i];
        float4 bv = *(const float4*)&lnb[i];
        float o0 = (gv[q][0] - mu) * rstd * wv.x + bv.x;
        float o1 = (gv[q][1] - mu) * rstd * wv.y + bv.y;
        float o2 = (gv[q][2] - mu) * rstd * wv.z + bv.z;
        float o3 = (gv[q][3] - mu) * rstd * wv.w + bv.w;
        *(uint2*)&g_ynh[(size_t)row * DINNER + i] = make_uint2(rnd2h(o0, o1), rnd2h(o2, o3));
    }
}

// ---------------- launch ----------------
extern "C" void kernel_launch(void* const* d_in, const int* in_sizes, int n_in,
                              void* d_out, int out_size)
{
    const float* u          = (const float*)d_in[0];
    const float* in_proj_w  = (const float*)d_in[1];
    const float* in_proj_b  = (const float*)d_in[2];
    const float* conv_w     = (const float*)d_in[3];
    const float* conv_b     = (const float*)d_in[4];
    const float* dt_bias    = (const float*)d_in[5];
    const float* A_log      = (const float*)d_in[6];
    const float* ln_w       = (const float*)d_in[7];
    const float* ln_b       = (const float*)d_in[8];
    const float* out_proj_w = (const float*)d_in[9];
    const float* out_proj_b = (const float*)d_in[10];
    float* out = (float*)d_out;

    float *zx, *gB, *gC, *gG;
    __half *uh, *w1h, *ynh, *w2h, *zh;
    cudaGetSymbolAddress((void**)&zx,  g_zxbcdt);
    cudaGetSymbolAddress((void**)&gB,  g_Bv);
    cudaGetSymbolAddress((void**)&gC,  g_Cv);
    cudaGetSymbolAddress((void**)&gG,  g_G);
    cudaGetSymbolAddress((void**)&uh,  g_uh);
    cudaGetSymbolAddress((void**)&w1h, g_w1h);
    cudaGetSymbolAddress((void**)&ynh, g_ynh);
    cudaGetSymbolAddress((void**)&w2h, g_w2h);
    cudaGetSymbolAddress((void**)&zh,  g_zh);

    cudaFuncSetAttribute(mma_gemm_nt1, cudaFuncAttributeMaxDynamicSharedMemorySize, 3 * GST1);
    cudaFuncSetAttribute(yfused_mma,   cudaFuncAttributeMaxDynamicSharedMemorySize, YSMEM);

    // 0) fp32 -> fp16 rounding: u, in_proj_w, out_proj_w in one launch
    {
        long n1 = (long)NROWS * DMODEL / 4;
        long n2 = (long)DINPROJ * DMODEL / 4;
        long n3 = (long)DMODEL * DINNER / 4;
        round3_f16<<<(unsigned)((n1 + n2 + n3 + 255) / 256), 256>>>(
            u, uh, n1, in_proj_w, w1h, n2, out_proj_w, w2h, n3);
    }

    // 1) in_proj: M=8192, N=8352, K=2048 (1-term; z columns emitted fp16)
    mma_gemm_nt1<<<dim3((DINPROJ + 255) / 256, NROWS / 128), 512, 3 * GST1>>>(
        uh, w1h, in_proj_b, zx, zh, DINPROJ, DMODEL);

    // 2) fused dt softplus + per-chunk cumsum (warp scan)
    cumsum_kernel<<<dim3(NCHUNK, NHEADS, BATCH), CHUNKT>>>(dt_bias, A_log);

    // 3) causal conv + silu (8 outputs/thread)
    {
        long total = (long)(NROWS / 8) * CONVDIM;
        conv_kernel<<<(unsigned)((total + 255) / 256), 256>>>(conv_w, conv_b);
    }

    // 4) G = C @ B^T per (b,chunk)  (upper-right block skipped inside)
    sgemm_nt<<<dim3(2, 2, BATCH * NCHUNK), 256>>>(
        gC, gB, nullptr, gG, CHUNKT, DSTATE,
        (long)CHUNKT * DSTATE, (long)CHUNKT * DSTATE, (long)CHUNKT * CHUNKT);

    // 5) chunk-local states on tensor cores
    states_mma<<<dim3(NHEADS, NCHUNK, BATCH), 256>>>();

    // 6) inter-chunk scan (16-way split)
    scan_kernel<<<BATCH * NHEADS * 16, 128>>>();

    // 7) fused Y on tensor cores (fp16 output)
    yfused_mma<<<dim3(NHEADS, NCHUNK, BATCH), 512, YSMEM>>>();

    // 8) gate + layernorm (fp16 y/z in, fp16 yn out)
    ln_kernel<<<NROWS, 256>>>(ln_w, ln_b);

    // 9) out_proj: M=8192, N=2048, K=4096 (1-term)
    mma_gemm_nt1<<<dim3(DMODEL / 256, NROWS / 128), 512, 3 * GST1>>>(
        ynh, w2h, out_proj_b, out, nullptr, DMODEL, DINNER);
}